// round 1
// baseline (speedup 1.0000x reference)
#include <cuda_runtime.h>
#include <math.h>

// Problem constants
#define LYR 6
#define BB  4
#define SS  1024
#define DD  1024
#define HH  16
#define DKK 64
#define FF  4096
#define MM  (BB*SS)          // 4096 rows
#define ATT_SCALE 0.125f     // 1/sqrt(64)
#define LN_EPS 1e-6f

// ---------------- scratch buffers (device globals; no allocation) -------------
__device__ float g_x [MM*DD];
__device__ float g_h [MM*DD];
__device__ float g_x1[MM*DD];
__device__ float g_q [MM*DD];
__device__ float g_k [MM*DD];
__device__ float g_v [MM*DD];
__device__ float g_o [MM*DD];
__device__ float g_ff[MM*FF];

// ---------------- PE add: x = embed + pe (broadcast over batch) --------------
__global__ void add_pe_kernel(const float* __restrict__ embed,
                              const float* __restrict__ pe,
                              float* __restrict__ x)
{
    int i = blockIdx.x * blockDim.x + threadIdx.x;   // float4 index
    const int TOT4 = MM * DD / 4;
    if (i >= TOT4) return;
    int pe4 = i % (SS * DD / 4);
    float4 e = ((const float4*)embed)[i];
    float4 p = ((const float4*)pe)[pe4];
    float4 r; r.x = e.x + p.x; r.y = e.y + p.y; r.z = e.z + p.z; r.w = e.w + p.w;
    ((float4*)x)[i] = r;
}

// ---------------- LayerNorm over last dim (D=1024), one block per row --------
__global__ void ln_kernel(const float* __restrict__ x,
                          const float* __restrict__ g,
                          const float* __restrict__ beta,
                          float* __restrict__ y)
{
    __shared__ float shm[32];
    __shared__ float s_mu, s_rstd;
    int row = blockIdx.x;
    int t   = threadIdx.x;            // 256 threads, 4 floats each
    const float4* xr = (const float4*)(x + (size_t)row * DD);
    float4 v = xr[t];
    float s = v.x + v.y + v.z + v.w;
    #pragma unroll
    for (int o = 16; o; o >>= 1) s += __shfl_xor_sync(0xffffffffu, s, o);
    if ((t & 31) == 0) shm[t >> 5] = s;
    __syncthreads();
    if (t < 32) {
        float tot = (t < 8) ? shm[t] : 0.f;
        #pragma unroll
        for (int o = 4; o; o >>= 1) tot += __shfl_xor_sync(0xffffffffu, tot, o);
        if (t == 0) s_mu = tot * (1.0f / DD);
    }
    __syncthreads();
    float mu = s_mu;
    float d0 = v.x - mu, d1 = v.y - mu, d2 = v.z - mu, d3 = v.w - mu;
    float s2 = d0*d0 + d1*d1 + d2*d2 + d3*d3;
    #pragma unroll
    for (int o = 16; o; o >>= 1) s2 += __shfl_xor_sync(0xffffffffu, s2, o);
    if ((t & 31) == 0) shm[t >> 5] = s2;
    __syncthreads();
    if (t < 32) {
        float tot = (t < 8) ? shm[t] : 0.f;
        #pragma unroll
        for (int o = 4; o; o >>= 1) tot += __shfl_xor_sync(0xffffffffu, tot, o);
        if (t == 0) s_rstd = rsqrtf(tot * (1.0f / DD) + LN_EPS);
    }
    __syncthreads();
    float rstd = s_rstd;
    float4 gg = ((const float4*)g)[t];
    float4 bb = ((const float4*)beta)[t];
    float4 out;
    out.x = d0 * rstd * gg.x + bb.x;
    out.y = d1 * rstd * gg.y + bb.y;
    out.z = d2 * rstd * gg.z + bb.z;
    out.w = d3 * rstd * gg.w + bb.w;
    ((float4*)(y + (size_t)row * DD))[t] = out;
}

// ---------------- SGEMM 128x128x8, 256 threads, 8x8 per thread ---------------
// C[M,N] = A[M,K] @ W[K,N] (+ bias) (+relu) (+ residual, * seq mask)
// epi: 0 = bias; 1 = bias+relu; 2 = bias+residual+mask
#define GBM 128
#define GBN 128
#define GBK 8

__global__ __launch_bounds__(256, 2)
void sgemm_kernel(const float* __restrict__ A, const float* __restrict__ W,
                  const float* __restrict__ bias, const float* __restrict__ res,
                  const int* __restrict__ mask, float* __restrict__ C,
                  int M, int N, int K, int epi)
{
    __shared__ float As[GBK][GBM];
    __shared__ float Bs[GBK][GBN];

    int tid  = threadIdx.x;
    int brow = blockIdx.y * GBM;
    int bcol = blockIdx.x * GBN;

    int arow = tid >> 1;              // 0..127
    int acol = (tid & 1) * 4;         // 0 or 4
    int brl  = tid >> 5;              // 0..7
    int bcl  = (tid & 31) * 4;        // 0..124

    int tr = (tid >> 4) * 8;          // 0..120
    int tc = (tid & 15) * 8;          // 0..120

    float acc[8][8];
    #pragma unroll
    for (int i = 0; i < 8; i++)
        #pragma unroll
        for (int j = 0; j < 8; j++) acc[i][j] = 0.f;

    const float* Aptr = A + (size_t)(brow + arow) * K + acol;
    const float* Wptr = W + (size_t)brl * N + bcol + bcl;

    for (int k0 = 0; k0 < K; k0 += GBK) {
        float4 av = *(const float4*)(Aptr + k0);
        As[acol + 0][arow] = av.x;
        As[acol + 1][arow] = av.y;
        As[acol + 2][arow] = av.z;
        As[acol + 3][arow] = av.w;
        float4 bv = *(const float4*)(Wptr + (size_t)k0 * N);
        *(float4*)&Bs[brl][bcl] = bv;
        __syncthreads();

        #pragma unroll
        for (int kk = 0; kk < GBK; kk++) {
            float4 a0 = *(const float4*)&As[kk][tr];
            float4 a1 = *(const float4*)&As[kk][tr + 4];
            float4 b0 = *(const float4*)&Bs[kk][tc];
            float4 b1 = *(const float4*)&Bs[kk][tc + 4];
            float ar[8] = {a0.x, a0.y, a0.z, a0.w, a1.x, a1.y, a1.z, a1.w};
            float br[8] = {b0.x, b0.y, b0.z, b0.w, b1.x, b1.y, b1.z, b1.w};
            #pragma unroll
            for (int i = 0; i < 8; i++)
                #pragma unroll
                for (int j = 0; j < 8; j++)
                    acc[i][j] += ar[i] * br[j];
        }
        __syncthreads();
    }

    // epilogue
    #pragma unroll
    for (int i = 0; i < 8; i++) {
        int m = brow + tr + i;
        float mk = 1.f;
        if (epi == 2) mk = mask[m] ? 1.f : 0.f;
        const float* resrow = (epi == 2) ? (res + (size_t)m * N) : nullptr;
        #pragma unroll
        for (int j = 0; j < 8; j += 4) {
            int n = bcol + tc + j;
            float4 bv = *(const float4*)(bias + n);
            float4 r;
            r.x = acc[i][j + 0] + bv.x;
            r.y = acc[i][j + 1] + bv.y;
            r.z = acc[i][j + 2] + bv.z;
            r.w = acc[i][j + 3] + bv.w;
            if (epi == 1) {
                r.x = fmaxf(r.x, 0.f); r.y = fmaxf(r.y, 0.f);
                r.z = fmaxf(r.z, 0.f); r.w = fmaxf(r.w, 0.f);
            } else if (epi == 2) {
                float4 rv = *(const float4*)(resrow + n);
                r.x = (r.x + rv.x) * mk; r.y = (r.y + rv.y) * mk;
                r.z = (r.z + rv.z) * mk; r.w = (r.w + rv.w) * mk;
            }
            *(float4*)(C + (size_t)m * N + n) = r;
        }
    }
}

// ---------------- Flash-style attention ----------------
// grid: (S/QT, H, B), block 256. QT=64 queries, KT=32 keys per tile.
// Q/K/V layout: [B*S, D] with head h at cols [h*64, h*64+64).
#define QT 64
#define KT 32
#define DPAD 68

__global__ __launch_bounds__(256, 2)
void attn_kernel(const float* __restrict__ Q, const float* __restrict__ K,
                 const float* __restrict__ V, const int* __restrict__ npm,
                 float* __restrict__ O)
{
    __shared__ float Qs[QT][DPAD];
    __shared__ float Ks[KT][DPAD];
    __shared__ float Vs[KT][DPAD];
    __shared__ float Ps[QT][KT + 1];
    __shared__ float km[KT];

    int b  = blockIdx.z, h = blockIdx.y, qt = blockIdx.x;
    int tid = threadIdx.x;
    int q = tid >> 2;          // 0..63 (query row in tile)
    int c = tid & 3;           // 0..3
    int dcol = c * 16;

    // load Q tile (64 x 64), float4
    for (int i = tid; i < QT * 16; i += 256) {
        int r = i >> 4, col = (i & 15) << 2;
        float4 v4 = *(const float4*)(Q + (size_t)(b * SS + qt * QT + r) * DD + h * 64 + col);
        *(float4*)&Qs[r][col] = v4;
    }

    float mrun = -1e30f, lrun = 0.f;
    float o[16];
    #pragma unroll
    for (int i = 0; i < 16; i++) o[i] = 0.f;

    for (int kt = 0; kt < SS / KT; kt++) {
        __syncthreads();
        for (int i = tid; i < KT * 16; i += 256) {
            int r = i >> 4, col = (i & 15) << 2;
            size_t gidx = (size_t)(b * SS + kt * KT + r) * DD + h * 64 + col;
            *(float4*)&Ks[r][col] = *(const float4*)(K + gidx);
            *(float4*)&Vs[r][col] = *(const float4*)(V + gidx);
        }
        if (tid < KT) km[tid] = npm[b * SS + kt * KT + tid] ? 1.f : 0.f;
        __syncthreads();

        // scores: each thread does keys kk = c + 4*j, j=0..7
        float s[8];
        #pragma unroll
        for (int j = 0; j < 8; j++) {
            int kk = c + 4 * j;
            float acc = 0.f;
            #pragma unroll
            for (int d4 = 0; d4 < 64; d4 += 4) {
                float4 qv = *(const float4*)&Qs[q][d4];
                float4 kv = *(const float4*)&Ks[kk][d4];
                acc += qv.x * kv.x + qv.y * kv.y + qv.z * kv.z + qv.w * kv.w;
            }
            s[j] = (km[kk] != 0.f) ? acc * ATT_SCALE : -1e9f;
        }
        // tile max (reduce across the 4 threads of this query row)
        float tmax = s[0];
        #pragma unroll
        for (int j = 1; j < 8; j++) tmax = fmaxf(tmax, s[j]);
        tmax = fmaxf(tmax, __shfl_xor_sync(0xffffffffu, tmax, 1));
        tmax = fmaxf(tmax, __shfl_xor_sync(0xffffffffu, tmax, 2));
        float newm = fmaxf(mrun, tmax);
        float fac = __expf(mrun - newm);
        float ts = 0.f;
        #pragma unroll
        for (int j = 0; j < 8; j++) {
            float p = __expf(s[j] - newm);
            Ps[q][c + 4 * j] = p;
            ts += p;
        }
        ts += __shfl_xor_sync(0xffffffffu, ts, 1);
        ts += __shfl_xor_sync(0xffffffffu, ts, 2);
        lrun = lrun * fac + ts;
        mrun = newm;
        #pragma unroll
        for (int i = 0; i < 16; i++) o[i] *= fac;
        __syncwarp();
        #pragma unroll
        for (int kk = 0; kk < KT; kk++) {
            float p = Ps[q][kk];
            #pragma unroll
            for (int i4 = 0; i4 < 16; i4 += 4) {
                float4 vv = *(const float4*)&Vs[kk][dcol + i4];
                o[i4 + 0] += p * vv.x;
                o[i4 + 1] += p * vv.y;
                o[i4 + 2] += p * vv.z;
                o[i4 + 3] += p * vv.w;
            }
        }
    }

    float inv = 1.f / lrun;
    size_t base = (size_t)(b * SS + qt * QT + q) * DD + h * 64 + dcol;
    #pragma unroll
    for (int i4 = 0; i4 < 16; i4 += 4) {
        float4 w;
        w.x = o[i4 + 0] * inv; w.y = o[i4 + 1] * inv;
        w.z = o[i4 + 2] * inv; w.w = o[i4 + 3] * inv;
        *(float4*)(O + base + i4) = w;
    }
}

// ---------------- host orchestration ----------------
extern "C" void kernel_launch(void* const* d_in, const int* in_sizes, int n_in,
                              void* d_out, int out_size)
{
    const float* embed = (const float*)d_in[0];
    const int*   npm   = (const int*)  d_in[1];
    const float* pe    = (const float*)d_in[2];
    const float* Wq    = (const float*)d_in[3];
    const float* bq    = (const float*)d_in[4];
    const float* Wk    = (const float*)d_in[5];
    const float* bk    = (const float*)d_in[6];
    const float* Wv    = (const float*)d_in[7];
    const float* bv    = (const float*)d_in[8];
    const float* Wo    = (const float*)d_in[9];
    const float* bo    = (const float*)d_in[10];
    const float* ln1g  = (const float*)d_in[11];
    const float* ln1b  = (const float*)d_in[12];
    const float* W1    = (const float*)d_in[13];
    const float* b1    = (const float*)d_in[14];
    const float* W2    = (const float*)d_in[15];
    const float* b2    = (const float*)d_in[16];
    const float* ln2g  = (const float*)d_in[17];
    const float* ln2b  = (const float*)d_in[18];
    const float* lnfg  = (const float*)d_in[19];
    const float* lnfb  = (const float*)d_in[20];

    float *x, *hh, *x1, *qb, *kb, *vb, *ob, *ffb;
    cudaGetSymbolAddress((void**)&x,   g_x);
    cudaGetSymbolAddress((void**)&hh,  g_h);
    cudaGetSymbolAddress((void**)&x1,  g_x1);
    cudaGetSymbolAddress((void**)&qb,  g_q);
    cudaGetSymbolAddress((void**)&kb,  g_k);
    cudaGetSymbolAddress((void**)&vb,  g_v);
    cudaGetSymbolAddress((void**)&ob,  g_o);
    cudaGetSymbolAddress((void**)&ffb, g_ff);

    // x = embed + pe
    {
        int tot4 = MM * DD / 4;
        add_pe_kernel<<<(tot4 + 255) / 256, 256>>>(embed, pe, x);
    }

    dim3 gD(DD / GBN, MM / GBM);     // N=1024 gemms: (8, 32)
    dim3 gF(FF / GBN, MM / GBM);     // N=4096 gemms: (32, 32)
    dim3 gAttn(SS / QT, HH, BB);     // (16, 16, 4)

    for (int l = 0; l < LYR; l++) {
        const float* wq = Wq + (size_t)l * DD * DD;
        const float* wk = Wk + (size_t)l * DD * DD;
        const float* wv = Wv + (size_t)l * DD * DD;
        const float* wo = Wo + (size_t)l * DD * DD;
        const float* w1 = W1 + (size_t)l * DD * FF;
        const float* w2 = W2 + (size_t)l * FF * DD;
        const float* lbq = bq + (size_t)l * DD;
        const float* lbk = bk + (size_t)l * DD;
        const float* lbv = bv + (size_t)l * DD;
        const float* lbo = bo + (size_t)l * DD;
        const float* lb1 = b1 + (size_t)l * FF;
        const float* lb2 = b2 + (size_t)l * DD;

        // h = LN1(x)
        ln_kernel<<<MM, 256>>>(x, ln1g + (size_t)l * DD, ln1b + (size_t)l * DD, hh);
        // q,k,v = h @ W + b
        sgemm_kernel<<<gD, 256>>>(hh, wq, lbq, nullptr, nullptr, qb, MM, DD, DD, 0);
        sgemm_kernel<<<gD, 256>>>(hh, wk, lbk, nullptr, nullptr, kb, MM, DD, DD, 0);
        sgemm_kernel<<<gD, 256>>>(hh, wv, lbv, nullptr, nullptr, vb, MM, DD, DD, 0);
        // o = attention(q,k,v)
        attn_kernel<<<gAttn, 256>>>(qb, kb, vb, npm, ob);
        // x1 = (h + o@Wo + bo) * mask
        sgemm_kernel<<<gD, 256>>>(ob, wo, lbo, hh, npm, x1, MM, DD, DD, 2);
        // h2 = LN2(x1)   (reuse hh)
        ln_kernel<<<MM, 256>>>(x1, ln2g + (size_t)l * DD, ln2b + (size_t)l * DD, hh);
        // ff = relu(h2 @ W1 + b1)
        sgemm_kernel<<<gF, 256>>>(hh, w1, lb1, nullptr, nullptr, ffb, MM, FF, DD, 1);
        // x = (h2 + ff@W2 + b2) * mask
        sgemm_kernel<<<gD, 256>>>(ffb, w2, lb2, hh, npm, x, MM, DD, FF, 2);
    }

    // final LN -> d_out
    ln_kernel<<<MM, 256>>>(x, lnfg, lnfb, (float*)d_out);
}

// round 3
// speedup vs baseline: 1.5189x; 1.5189x over previous
#include <cuda_runtime.h>
#include <math.h>

// Problem constants
#define LYR 6
#define BB  4
#define SS  1024
#define DD  1024
#define HH  16
#define DKK 64
#define FF  4096
#define MM  (BB*SS)          // 4096 rows
#define ATT_SCALE 0.125f     // 1/sqrt(64)
#define LN_EPS 1e-6f

// ---------------- scratch buffers (device globals; no allocation) -------------
__device__ float g_x [MM*DD];
__device__ float g_h [MM*DD];
__device__ float g_x1[MM*DD];
__device__ float g_q [MM*DD];
__device__ float g_k [MM*DD];
__device__ float g_v [MM*DD];
__device__ float g_o [MM*DD];
__device__ float g_ff[MM*FF];

// ---------------- PE add: x = embed + pe (broadcast over batch) --------------
__global__ void add_pe_kernel(const float* __restrict__ embed,
                              const float* __restrict__ pe,
                              float* __restrict__ x)
{
    int i = blockIdx.x * blockDim.x + threadIdx.x;   // float4 index
    const int TOT4 = MM * DD / 4;
    if (i >= TOT4) return;
    int pe4 = i % (SS * DD / 4);
    float4 e = ((const float4*)embed)[i];
    float4 p = ((const float4*)pe)[pe4];
    float4 r; r.x = e.x + p.x; r.y = e.y + p.y; r.z = e.z + p.z; r.w = e.w + p.w;
    ((float4*)x)[i] = r;
}

// ---------------- LayerNorm over last dim (D=1024), one block per row --------
__global__ void ln_kernel(const float* __restrict__ x,
                          const float* __restrict__ g,
                          const float* __restrict__ beta,
                          float* __restrict__ y)
{
    __shared__ float shm[32];
    __shared__ float s_mu, s_rstd;
    int row = blockIdx.x;
    int t   = threadIdx.x;            // 256 threads, 4 floats each
    const float4* xr = (const float4*)(x + (size_t)row * DD);
    float4 v = xr[t];
    float s = v.x + v.y + v.z + v.w;
    #pragma unroll
    for (int o = 16; o; o >>= 1) s += __shfl_xor_sync(0xffffffffu, s, o);
    if ((t & 31) == 0) shm[t >> 5] = s;
    __syncthreads();
    if (t < 32) {
        float tot = (t < 8) ? shm[t] : 0.f;
        #pragma unroll
        for (int o = 4; o; o >>= 1) tot += __shfl_xor_sync(0xffffffffu, tot, o);
        if (t == 0) s_mu = tot * (1.0f / DD);
    }
    __syncthreads();
    float mu = s_mu;
    float d0 = v.x - mu, d1 = v.y - mu, d2 = v.z - mu, d3 = v.w - mu;
    float s2 = d0*d0 + d1*d1 + d2*d2 + d3*d3;
    #pragma unroll
    for (int o = 16; o; o >>= 1) s2 += __shfl_xor_sync(0xffffffffu, s2, o);
    if ((t & 31) == 0) shm[t >> 5] = s2;
    __syncthreads();
    if (t < 32) {
        float tot = (t < 8) ? shm[t] : 0.f;
        #pragma unroll
        for (int o = 4; o; o >>= 1) tot += __shfl_xor_sync(0xffffffffu, tot, o);
        if (t == 0) s_rstd = rsqrtf(tot * (1.0f / DD) + LN_EPS);
    }
    __syncthreads();
    float rstd = s_rstd;
    float4 gg = ((const float4*)g)[t];
    float4 bb = ((const float4*)beta)[t];
    float4 out;
    out.x = d0 * rstd * gg.x + bb.x;
    out.y = d1 * rstd * gg.y + bb.y;
    out.z = d2 * rstd * gg.z + bb.z;
    out.w = d3 * rstd * gg.w + bb.w;
    ((float4*)(y + (size_t)row * DD))[t] = out;
}

// ---------------- TF32 tensor-core GEMM 128x128x16 ---------------------------
// C[M,N] = A[M,K] @ W[K,N] (+ bias) (+relu) (+ residual, * seq mask)
// epi: 0 = bias; 1 = bias+relu; 2 = bias+residual+mask
// 256 threads = 8 warps (2 x 4). Warp tile 64x32 via m16n8k8 (4x4 mma tiles).
#define BM 128
#define BN 128
#define BK 16
#define ASTR 20     // As row stride (floats): conflict-free for A-frag pattern
#define BSTR 136    // Bs row stride (floats): conflict-free for B-frag pattern

__device__ __forceinline__ unsigned f2tf(float f) {
    unsigned u;
    asm("cvt.rna.tf32.f32 %0, %1;" : "=r"(u) : "f"(f));
    return u;
}

__device__ __forceinline__ void mma_tf32(float c[4], const unsigned a[4], const unsigned b[2]) {
    asm volatile("mma.sync.aligned.m16n8k8.row.col.f32.tf32.tf32.f32 "
        "{%0,%1,%2,%3}, {%4,%5,%6,%7}, {%8,%9}, {%0,%1,%2,%3};"
        : "+f"(c[0]), "+f"(c[1]), "+f"(c[2]), "+f"(c[3])
        : "r"(a[0]), "r"(a[1]), "r"(a[2]), "r"(a[3]), "r"(b[0]), "r"(b[1]));
}

__global__ __launch_bounds__(256, 1)
void mma_gemm_kernel(const float* __restrict__ A, const float* __restrict__ W,
                     const float* __restrict__ bias, const float* __restrict__ res,
                     const int* __restrict__ mask, float* __restrict__ C,
                     int M, int N, int K, int epi)
{
    __shared__ unsigned As[2][BM][ASTR];
    __shared__ __align__(16) unsigned Bs[2][BK][BSTR];

    const int tid  = threadIdx.x;
    const int lane = tid & 31;
    const int wrp  = tid >> 5;       // 0..7
    const int wm   = wrp >> 2;       // 0..1  -> 64 rows
    const int wn   = wrp & 3;        // 0..3  -> 32 cols
    const int g    = lane >> 2;      // 0..7
    const int cc   = lane & 3;       // 0..3

    const int brow = blockIdx.y * BM;
    const int bcol = blockIdx.x * BN;

    // global staging indices: A tile 128x16 = 512 float4; B tile 16x128 = 512 float4
    const int a_row0 = tid >> 2,  a_c4 = tid & 3;         // + second at tid+256
    const int a_row1 = (tid + 256) >> 2;
    const int b_row0 = tid >> 5,  b_c4 = tid & 31;
    const int b_row1 = (tid + 256) >> 5;

    const float* Ab = A + (size_t)brow * K;
    const float* Wb = W + bcol;

    float acc[4][4][4];
    #pragma unroll
    for (int i = 0; i < 4; i++)
        #pragma unroll
        for (int j = 0; j < 4; j++) {
            acc[i][j][0] = 0.f; acc[i][j][1] = 0.f;
            acc[i][j][2] = 0.f; acc[i][j][3] = 0.f;
        }

    // ---- prologue: stage tile 0 into buffer 0 ----
    {
        float4 av0 = *(const float4*)(Ab + (size_t)a_row0 * K + a_c4 * 4);
        float4 av1 = *(const float4*)(Ab + (size_t)a_row1 * K + a_c4 * 4);
        As[0][a_row0][a_c4*4+0] = f2tf(av0.x); As[0][a_row0][a_c4*4+1] = f2tf(av0.y);
        As[0][a_row0][a_c4*4+2] = f2tf(av0.z); As[0][a_row0][a_c4*4+3] = f2tf(av0.w);
        As[0][a_row1][a_c4*4+0] = f2tf(av1.x); As[0][a_row1][a_c4*4+1] = f2tf(av1.y);
        As[0][a_row1][a_c4*4+2] = f2tf(av1.z); As[0][a_row1][a_c4*4+3] = f2tf(av1.w);
        float4 bv0 = *(const float4*)(Wb + (size_t)b_row0 * N + b_c4 * 4);
        float4 bv1 = *(const float4*)(Wb + (size_t)b_row1 * N + b_c4 * 4);
        *(uint4*)&Bs[0][b_row0][b_c4*4] =
            make_uint4(f2tf(bv0.x), f2tf(bv0.y), f2tf(bv0.z), f2tf(bv0.w));
        *(uint4*)&Bs[0][b_row1][b_c4*4] =
            make_uint4(f2tf(bv1.x), f2tf(bv1.y), f2tf(bv1.z), f2tf(bv1.w));
    }
    __syncthreads();

    const int NK = K / BK;
    int cur = 0;

    for (int kt = 0; kt < NK; kt++) {
        float4 av0, av1, bv0, bv1;
        const bool more = (kt + 1 < NK);
        if (more) {
            int k0 = (kt + 1) * BK;
            av0 = *(const float4*)(Ab + (size_t)a_row0 * K + k0 + a_c4 * 4);
            av1 = *(const float4*)(Ab + (size_t)a_row1 * K + k0 + a_c4 * 4);
            bv0 = *(const float4*)(Wb + (size_t)(k0 + b_row0) * N + b_c4 * 4);
            bv1 = *(const float4*)(Wb + (size_t)(k0 + b_row1) * N + b_c4 * 4);
        }

        // ---- compute on buffer cur ----
        #pragma unroll
        for (int ks = 0; ks < 2; ks++) {
            const int kk = ks * 8;
            unsigned a[4][4], b[4][2];
            #pragma unroll
            for (int mt = 0; mt < 4; mt++) {
                int rb = wm * 64 + mt * 16;
                a[mt][0] = As[cur][rb + g    ][kk + cc    ];
                a[mt][1] = As[cur][rb + g + 8][kk + cc    ];
                a[mt][2] = As[cur][rb + g    ][kk + cc + 4];
                a[mt][3] = As[cur][rb + g + 8][kk + cc + 4];
            }
            #pragma unroll
            for (int nt = 0; nt < 4; nt++) {
                int nb = wn * 32 + nt * 8;
                b[nt][0] = Bs[cur][kk + cc    ][nb + g];
                b[nt][1] = Bs[cur][kk + cc + 4][nb + g];
            }
            #pragma unroll
            for (int mt = 0; mt < 4; mt++)
                #pragma unroll
                for (int nt = 0; nt < 4; nt++)
                    mma_tf32(acc[mt][nt], a[mt], b[nt]);
        }

        if (more) {
            int nxt = cur ^ 1;
            As[nxt][a_row0][a_c4*4+0] = f2tf(av0.x); As[nxt][a_row0][a_c4*4+1] = f2tf(av0.y);
            As[nxt][a_row0][a_c4*4+2] = f2tf(av0.z); As[nxt][a_row0][a_c4*4+3] = f2tf(av0.w);
            As[nxt][a_row1][a_c4*4+0] = f2tf(av1.x); As[nxt][a_row1][a_c4*4+1] = f2tf(av1.y);
            As[nxt][a_row1][a_c4*4+2] = f2tf(av1.z); As[nxt][a_row1][a_c4*4+3] = f2tf(av1.w);
            *(uint4*)&Bs[nxt][b_row0][b_c4*4] =
                make_uint4(f2tf(bv0.x), f2tf(bv0.y), f2tf(bv0.z), f2tf(bv0.w));
            *(uint4*)&Bs[nxt][b_row1][b_c4*4] =
                make_uint4(f2tf(bv1.x), f2tf(bv1.y), f2tf(bv1.z), f2tf(bv1.w));
        }
        __syncthreads();
        cur ^= 1;
    }

    // ---- epilogue ----
    #pragma unroll
    for (int mt = 0; mt < 4; mt++) {
        int r0 = brow + wm * 64 + mt * 16 + g;
        int r1 = r0 + 8;
        float mk0 = 1.f, mk1 = 1.f;
        if (epi == 2) {
            mk0 = mask[r0] ? 1.f : 0.f;
            mk1 = mask[r1] ? 1.f : 0.f;
        }
        #pragma unroll
        for (int nt = 0; nt < 4; nt++) {
            int ncol = bcol + wn * 32 + nt * 8 + cc * 2;
            float2 bv = *(const float2*)(bias + ncol);
            float2 o0, o1;
            o0.x = acc[mt][nt][0] + bv.x; o0.y = acc[mt][nt][1] + bv.y;
            o1.x = acc[mt][nt][2] + bv.x; o1.y = acc[mt][nt][3] + bv.y;
            if (epi == 1) {
                o0.x = fmaxf(o0.x, 0.f); o0.y = fmaxf(o0.y, 0.f);
                o1.x = fmaxf(o1.x, 0.f); o1.y = fmaxf(o1.y, 0.f);
            } else if (epi == 2) {
                float2 rv0 = *(const float2*)(res + (size_t)r0 * N + ncol);
                float2 rv1 = *(const float2*)(res + (size_t)r1 * N + ncol);
                o0.x = (o0.x + rv0.x) * mk0; o0.y = (o0.y + rv0.y) * mk0;
                o1.x = (o1.x + rv1.x) * mk1; o1.y = (o1.y + rv1.y) * mk1;
            }
            *(float2*)(C + (size_t)r0 * N + ncol) = o0;
            *(float2*)(C + (size_t)r1 * N + ncol) = o1;
        }
    }
}

// ---------------- Flash-style attention ----------------
// grid: (S/QT, H, B), block 256. QT=64 queries, KT=32 keys per tile.
#define QT 64
#define KT 32
#define DPAD 68

__global__ __launch_bounds__(256, 2)
void attn_kernel(const float* __restrict__ Q, const float* __restrict__ K,
                 const float* __restrict__ V, const int* __restrict__ npm,
                 float* __restrict__ O)
{
    __shared__ float Qs[QT][DPAD];
    __shared__ float Ks[KT][DPAD];
    __shared__ float Vs[KT][DPAD];
    __shared__ float Ps[QT][KT + 1];
    __shared__ float km[KT];

    int b  = blockIdx.z, h = blockIdx.y, qt = blockIdx.x;
    int tid = threadIdx.x;
    int q = tid >> 2;          // 0..63 (query row in tile)
    int c = tid & 3;           // 0..3
    int dcol = c * 16;

    for (int i = tid; i < QT * 16; i += 256) {
        int r = i >> 4, col = (i & 15) << 2;
        float4 v4 = *(const float4*)(Q + (size_t)(b * SS + qt * QT + r) * DD + h * 64 + col);
        *(float4*)&Qs[r][col] = v4;
    }

    float mrun = -1e30f, lrun = 0.f;
    float o[16];
    #pragma unroll
    for (int i = 0; i < 16; i++) o[i] = 0.f;

    for (int kt = 0; kt < SS / KT; kt++) {
        __syncthreads();
        for (int i = tid; i < KT * 16; i += 256) {
            int r = i >> 4, col = (i & 15) << 2;
            size_t gidx = (size_t)(b * SS + kt * KT + r) * DD + h * 64 + col;
            *(float4*)&Ks[r][col] = *(const float4*)(K + gidx);
            *(float4*)&Vs[r][col] = *(const float4*)(V + gidx);
        }
        if (tid < KT) km[tid] = npm[b * SS + kt * KT + tid] ? 1.f : 0.f;
        __syncthreads();

        float s[8];
        #pragma unroll
        for (int j = 0; j < 8; j++) {
            int kk = c + 4 * j;
            float acc = 0.f;
            #pragma unroll
            for (int d4 = 0; d4 < 64; d4 += 4) {
                float4 qv = *(const float4*)&Qs[q][d4];
                float4 kv = *(const float4*)&Ks[kk][d4];
                acc += qv.x * kv.x + qv.y * kv.y + qv.z * kv.z + qv.w * kv.w;
            }
            s[j] = (km[kk] != 0.f) ? acc * ATT_SCALE : -1e9f;
        }
        float tmax = s[0];
        #pragma unroll
        for (int j = 1; j < 8; j++) tmax = fmaxf(tmax, s[j]);
        tmax = fmaxf(tmax, __shfl_xor_sync(0xffffffffu, tmax, 1));
        tmax = fmaxf(tmax, __shfl_xor_sync(0xffffffffu, tmax, 2));
        float newm = fmaxf(mrun, tmax);
        float fac = __expf(mrun - newm);
        float ts = 0.f;
        #pragma unroll
        for (int j = 0; j < 8; j++) {
            float p = __expf(s[j] - newm);
            Ps[q][c + 4 * j] = p;
            ts += p;
        }
        ts += __shfl_xor_sync(0xffffffffu, ts, 1);
        ts += __shfl_xor_sync(0xffffffffu, ts, 2);
        lrun = lrun * fac + ts;
        mrun = newm;
        #pragma unroll
        for (int i = 0; i < 16; i++) o[i] *= fac;
        __syncwarp();
        #pragma unroll
        for (int kk = 0; kk < KT; kk++) {
            float p = Ps[q][kk];
            #pragma unroll
            for (int i4 = 0; i4 < 16; i4 += 4) {
                float4 vv = *(const float4*)&Vs[kk][dcol + i4];
                o[i4 + 0] += p * vv.x;
                o[i4 + 1] += p * vv.y;
                o[i4 + 2] += p * vv.z;
                o[i4 + 3] += p * vv.w;
            }
        }
    }

    float inv = 1.f / lrun;
    size_t base = (size_t)(b * SS + qt * QT + q) * DD + h * 64 + dcol;
    #pragma unroll
    for (int i4 = 0; i4 < 16; i4 += 4) {
        float4 w;
        w.x = o[i4 + 0] * inv; w.y = o[i4 + 1] * inv;
        w.z = o[i4 + 2] * inv; w.w = o[i4 + 3] * inv;
        *(float4*)(O + base + i4) = w;
    }
}

// ---------------- host orchestration ----------------
extern "C" void kernel_launch(void* const* d_in, const int* in_sizes, int n_in,
                              void* d_out, int out_size)
{
    const float* embed = (const float*)d_in[0];
    const int*   npm   = (const int*)  d_in[1];
    const float* pe    = (const float*)d_in[2];
    const float* Wq    = (const float*)d_in[3];
    const float* bq    = (const float*)d_in[4];
    const float* Wk    = (const float*)d_in[5];
    const float* bk    = (const float*)d_in[6];
    const float* Wv    = (const float*)d_in[7];
    const float* bv    = (const float*)d_in[8];
    const float* Wo    = (const float*)d_in[9];
    const float* bo    = (const float*)d_in[10];
    const float* ln1g  = (const float*)d_in[11];
    const float* ln1b  = (const float*)d_in[12];
    const float* W1    = (const float*)d_in[13];
    const float* b1    = (const float*)d_in[14];
    const float* W2    = (const float*)d_in[15];
    const float* b2    = (const float*)d_in[16];
    const float* ln2g  = (const float*)d_in[17];
    const float* ln2b  = (const float*)d_in[18];
    const float* lnfg  = (const float*)d_in[19];
    const float* lnfb  = (const float*)d_in[20];

    float *x, *hh, *x1, *qb, *kb, *vb, *ob, *ffb;
    cudaGetSymbolAddress((void**)&x,   g_x);
    cudaGetSymbolAddress((void**)&hh,  g_h);
    cudaGetSymbolAddress((void**)&x1,  g_x1);
    cudaGetSymbolAddress((void**)&qb,  g_q);
    cudaGetSymbolAddress((void**)&kb,  g_k);
    cudaGetSymbolAddress((void**)&vb,  g_v);
    cudaGetSymbolAddress((void**)&ob,  g_o);
    cudaGetSymbolAddress((void**)&ffb, g_ff);

    {
        int tot4 = MM * DD / 4;
        add_pe_kernel<<<(tot4 + 255) / 256, 256>>>(embed, pe, x);
    }

    dim3 gD(DD / BN, MM / BM);       // (8, 32)
    dim3 gF(FF / BN, MM / BM);       // (32, 32)
    dim3 gAttn(SS / QT, HH, BB);     // (16, 16, 4)

    for (int l = 0; l < LYR; l++) {
        const float* wq = Wq + (size_t)l * DD * DD;
        const float* wk = Wk + (size_t)l * DD * DD;
        const float* wv = Wv + (size_t)l * DD * DD;
        const float* wo = Wo + (size_t)l * DD * DD;
        const float* w1 = W1 + (size_t)l * DD * FF;
        const float* w2 = W2 + (size_t)l * FF * DD;
        const float* lbq = bq + (size_t)l * DD;
        const float* lbk = bk + (size_t)l * DD;
        const float* lbv = bv + (size_t)l * DD;
        const float* lbo = bo + (size_t)l * DD;
        const float* lb1 = b1 + (size_t)l * FF;
        const float* lb2 = b2 + (size_t)l * DD;

        ln_kernel<<<MM, 256>>>(x, ln1g + (size_t)l * DD, ln1b + (size_t)l * DD, hh);
        mma_gemm_kernel<<<gD, 256>>>(hh, wq, lbq, nullptr, nullptr, qb, MM, DD, DD, 0);
        mma_gemm_kernel<<<gD, 256>>>(hh, wk, lbk, nullptr, nullptr, kb, MM, DD, DD, 0);
        mma_gemm_kernel<<<gD, 256>>>(hh, wv, lbv, nullptr, nullptr, vb, MM, DD, DD, 0);
        attn_kernel<<<gAttn, 256>>>(qb, kb, vb, npm, ob);
        mma_gemm_kernel<<<gD, 256>>>(ob, wo, lbo, hh, npm, x1, MM, DD, DD, 2);
        ln_kernel<<<MM, 256>>>(x1, ln2g + (size_t)l * DD, ln2b + (size_t)l * DD, hh);
        mma_gemm_kernel<<<gF, 256>>>(hh, w1, lb1, nullptr, nullptr, ffb, MM, FF, DD, 1);
        mma_gemm_kernel<<<gD, 256>>>(ffb, w2, lb2, hh, npm, x, MM, DD, FF, 2);
    }

    ln_kernel<<<MM, 256>>>(x, lnfg, lnfb, (float*)d_out);
}

// round 4
// speedup vs baseline: 2.8966x; 1.9071x over previous
#include <cuda_runtime.h>
#include <math.h>

// Problem constants
#define LYR 6
#define BB  4
#define SS  1024
#define DD  1024
#define HH  16
#define DKK 64
#define FF  4096
#define MM  (BB*SS)          // 4096 rows
#define ATT_SCALE 0.125f     // 1/sqrt(64)
#define LN_EPS 1e-6f

// ---------------- scratch buffers (device globals; no allocation) -------------
__device__ float g_x [MM*DD];
__device__ float g_h [MM*DD];
__device__ float g_x1[MM*DD];
__device__ float g_q [MM*DD];
__device__ float g_k [MM*DD];
__device__ float g_v [MM*DD];
__device__ float g_o [MM*DD];
__device__ float g_ff[MM*FF];

// ---------------- PE add: x = embed + pe (broadcast over batch) --------------
__global__ void add_pe_kernel(const float* __restrict__ embed,
                              const float* __restrict__ pe,
                              float* __restrict__ x)
{
    int i = blockIdx.x * blockDim.x + threadIdx.x;   // float4 index
    const int TOT4 = MM * DD / 4;
    if (i >= TOT4) return;
    int pe4 = i % (SS * DD / 4);
    float4 e = ((const float4*)embed)[i];
    float4 p = ((const float4*)pe)[pe4];
    float4 r; r.x = e.x + p.x; r.y = e.y + p.y; r.z = e.z + p.z; r.w = e.w + p.w;
    ((float4*)x)[i] = r;
}

// ---------------- LayerNorm over last dim (D=1024), one block per row --------
__global__ void ln_kernel(const float* __restrict__ x,
                          const float* __restrict__ g,
                          const float* __restrict__ beta,
                          float* __restrict__ y)
{
    __shared__ float shm[32];
    __shared__ float s_mu, s_rstd;
    int row = blockIdx.x;
    int t   = threadIdx.x;            // 256 threads, 4 floats each
    const float4* xr = (const float4*)(x + (size_t)row * DD);
    float4 v = xr[t];
    float s = v.x + v.y + v.z + v.w;
    #pragma unroll
    for (int o = 16; o; o >>= 1) s += __shfl_xor_sync(0xffffffffu, s, o);
    if ((t & 31) == 0) shm[t >> 5] = s;
    __syncthreads();
    if (t < 32) {
        float tot = (t < 8) ? shm[t] : 0.f;
        #pragma unroll
        for (int o = 4; o; o >>= 1) tot += __shfl_xor_sync(0xffffffffu, tot, o);
        if (t == 0) s_mu = tot * (1.0f / DD);
    }
    __syncthreads();
    float mu = s_mu;
    float d0 = v.x - mu, d1 = v.y - mu, d2 = v.z - mu, d3 = v.w - mu;
    float s2 = d0*d0 + d1*d1 + d2*d2 + d3*d3;
    #pragma unroll
    for (int o = 16; o; o >>= 1) s2 += __shfl_xor_sync(0xffffffffu, s2, o);
    if ((t & 31) == 0) shm[t >> 5] = s2;
    __syncthreads();
    if (t < 32) {
        float tot = (t < 8) ? shm[t] : 0.f;
        #pragma unroll
        for (int o = 4; o; o >>= 1) tot += __shfl_xor_sync(0xffffffffu, tot, o);
        if (t == 0) s_rstd = rsqrtf(tot * (1.0f / DD) + LN_EPS);
    }
    __syncthreads();
    float rstd = s_rstd;
    float4 gg = ((const float4*)g)[t];
    float4 bb = ((const float4*)beta)[t];
    float4 out;
    out.x = d0 * rstd * gg.x + bb.x;
    out.y = d1 * rstd * gg.y + bb.y;
    out.z = d2 * rstd * gg.z + bb.z;
    out.w = d3 * rstd * gg.w + bb.w;
    ((float4*)(y + (size_t)row * DD))[t] = out;
}

// ---------------- TF32 helpers ----------------
__device__ __forceinline__ unsigned f2tf(float f) {
    unsigned u;
    asm("cvt.rna.tf32.f32 %0, %1;" : "=r"(u) : "f"(f));
    return u;
}

__device__ __forceinline__ void mma_tf32(float c[4], const unsigned a[4], const unsigned b[2]) {
    asm volatile("mma.sync.aligned.m16n8k8.row.col.f32.tf32.tf32.f32 "
        "{%0,%1,%2,%3}, {%4,%5,%6,%7}, {%8,%9}, {%0,%1,%2,%3};"
        : "+f"(c[0]), "+f"(c[1]), "+f"(c[2]), "+f"(c[3])
        : "r"(a[0]), "r"(a[1]), "r"(a[2]), "r"(a[3]), "r"(b[0]), "r"(b[1]));
}

// ---------------- TF32 tensor-core GEMM 128x128x16 ---------------------------
// C[M,N] = A[M,K] @ W[K,N] (+ bias) (+relu) (+ residual, * seq mask)
#define BM 128
#define BN 128
#define BK 16
#define ASTR 20
#define BSTR 136

__global__ __launch_bounds__(256, 1)
void mma_gemm_kernel(const float* __restrict__ A, const float* __restrict__ W,
                     const float* __restrict__ bias, const float* __restrict__ res,
                     const int* __restrict__ mask, float* __restrict__ C,
                     int M, int N, int K, int epi)
{
    __shared__ unsigned As[2][BM][ASTR];
    __shared__ __align__(16) unsigned Bs[2][BK][BSTR];

    const int tid  = threadIdx.x;
    const int lane = tid & 31;
    const int wrp  = tid >> 5;
    const int wm   = wrp >> 2;
    const int wn   = wrp & 3;
    const int g    = lane >> 2;
    const int cc   = lane & 3;

    const int brow = blockIdx.y * BM;
    const int bcol = blockIdx.x * BN;

    const int a_row0 = tid >> 2,  a_c4 = tid & 3;
    const int a_row1 = (tid + 256) >> 2;
    const int b_row0 = tid >> 5,  b_c4 = tid & 31;
    const int b_row1 = (tid + 256) >> 5;

    const float* Ab = A + (size_t)brow * K;
    const float* Wb = W + bcol;

    float acc[4][4][4];
    #pragma unroll
    for (int i = 0; i < 4; i++)
        #pragma unroll
        for (int j = 0; j < 4; j++) {
            acc[i][j][0] = 0.f; acc[i][j][1] = 0.f;
            acc[i][j][2] = 0.f; acc[i][j][3] = 0.f;
        }

    {
        float4 av0 = *(const float4*)(Ab + (size_t)a_row0 * K + a_c4 * 4);
        float4 av1 = *(const float4*)(Ab + (size_t)a_row1 * K + a_c4 * 4);
        As[0][a_row0][a_c4*4+0] = f2tf(av0.x); As[0][a_row0][a_c4*4+1] = f2tf(av0.y);
        As[0][a_row0][a_c4*4+2] = f2tf(av0.z); As[0][a_row0][a_c4*4+3] = f2tf(av0.w);
        As[0][a_row1][a_c4*4+0] = f2tf(av1.x); As[0][a_row1][a_c4*4+1] = f2tf(av1.y);
        As[0][a_row1][a_c4*4+2] = f2tf(av1.z); As[0][a_row1][a_c4*4+3] = f2tf(av1.w);
        float4 bv0 = *(const float4*)(Wb + (size_t)b_row0 * N + b_c4 * 4);
        float4 bv1 = *(const float4*)(Wb + (size_t)b_row1 * N + b_c4 * 4);
        *(uint4*)&Bs[0][b_row0][b_c4*4] =
            make_uint4(f2tf(bv0.x), f2tf(bv0.y), f2tf(bv0.z), f2tf(bv0.w));
        *(uint4*)&Bs[0][b_row1][b_c4*4] =
            make_uint4(f2tf(bv1.x), f2tf(bv1.y), f2tf(bv1.z), f2tf(bv1.w));
    }
    __syncthreads();

    const int NK = K / BK;
    int cur = 0;

    for (int kt = 0; kt < NK; kt++) {
        float4 av0, av1, bv0, bv1;
        const bool more = (kt + 1 < NK);
        if (more) {
            int k0 = (kt + 1) * BK;
            av0 = *(const float4*)(Ab + (size_t)a_row0 * K + k0 + a_c4 * 4);
            av1 = *(const float4*)(Ab + (size_t)a_row1 * K + k0 + a_c4 * 4);
            bv0 = *(const float4*)(Wb + (size_t)(k0 + b_row0) * N + b_c4 * 4);
            bv1 = *(const float4*)(Wb + (size_t)(k0 + b_row1) * N + b_c4 * 4);
        }

        #pragma unroll
        for (int ks = 0; ks < 2; ks++) {
            const int kk = ks * 8;
            unsigned a[4][4], b[4][2];
            #pragma unroll
            for (int mt = 0; mt < 4; mt++) {
                int rb = wm * 64 + mt * 16;
                a[mt][0] = As[cur][rb + g    ][kk + cc    ];
                a[mt][1] = As[cur][rb + g + 8][kk + cc    ];
                a[mt][2] = As[cur][rb + g    ][kk + cc + 4];
                a[mt][3] = As[cur][rb + g + 8][kk + cc + 4];
            }
            #pragma unroll
            for (int nt = 0; nt < 4; nt++) {
                int nb = wn * 32 + nt * 8;
                b[nt][0] = Bs[cur][kk + cc    ][nb + g];
                b[nt][1] = Bs[cur][kk + cc + 4][nb + g];
            }
            #pragma unroll
            for (int mt = 0; mt < 4; mt++)
                #pragma unroll
                for (int nt = 0; nt < 4; nt++)
                    mma_tf32(acc[mt][nt], a[mt], b[nt]);
        }

        if (more) {
            int nxt = cur ^ 1;
            As[nxt][a_row0][a_c4*4+0] = f2tf(av0.x); As[nxt][a_row0][a_c4*4+1] = f2tf(av0.y);
            As[nxt][a_row0][a_c4*4+2] = f2tf(av0.z); As[nxt][a_row0][a_c4*4+3] = f2tf(av0.w);
            As[nxt][a_row1][a_c4*4+0] = f2tf(av1.x); As[nxt][a_row1][a_c4*4+1] = f2tf(av1.y);
            As[nxt][a_row1][a_c4*4+2] = f2tf(av1.z); As[nxt][a_row1][a_c4*4+3] = f2tf(av1.w);
            *(uint4*)&Bs[nxt][b_row0][b_c4*4] =
                make_uint4(f2tf(bv0.x), f2tf(bv0.y), f2tf(bv0.z), f2tf(bv0.w));
            *(uint4*)&Bs[nxt][b_row1][b_c4*4] =
                make_uint4(f2tf(bv1.x), f2tf(bv1.y), f2tf(bv1.z), f2tf(bv1.w));
        }
        __syncthreads();
        cur ^= 1;
    }

    #pragma unroll
    for (int mt = 0; mt < 4; mt++) {
        int r0 = brow + wm * 64 + mt * 16 + g;
        int r1 = r0 + 8;
        float mk0 = 1.f, mk1 = 1.f;
        if (epi == 2) {
            mk0 = mask[r0] ? 1.f : 0.f;
            mk1 = mask[r1] ? 1.f : 0.f;
        }
        #pragma unroll
        for (int nt = 0; nt < 4; nt++) {
            int ncol = bcol + wn * 32 + nt * 8 + cc * 2;
            float2 bv = *(const float2*)(bias + ncol);
            float2 o0, o1;
            o0.x = acc[mt][nt][0] + bv.x; o0.y = acc[mt][nt][1] + bv.y;
            o1.x = acc[mt][nt][2] + bv.x; o1.y = acc[mt][nt][3] + bv.y;
            if (epi == 1) {
                o0.x = fmaxf(o0.x, 0.f); o0.y = fmaxf(o0.y, 0.f);
                o1.x = fmaxf(o1.x, 0.f); o1.y = fmaxf(o1.y, 0.f);
            } else if (epi == 2) {
                float2 rv0 = *(const float2*)(res + (size_t)r0 * N + ncol);
                float2 rv1 = *(const float2*)(res + (size_t)r1 * N + ncol);
                o0.x = (o0.x + rv0.x) * mk0; o0.y = (o0.y + rv0.y) * mk0;
                o1.x = (o1.x + rv1.x) * mk1; o1.y = (o1.y + rv1.y) * mk1;
            }
            *(float2*)(C + (size_t)r0 * N + ncol) = o0;
            *(float2*)(C + (size_t)r1 * N + ncol) = o1;
        }
    }
}

// ---------------- Tensor-core flash attention (TF32 mma) ---------------------
// grid: (S/64, H, B), 128 threads = 4 warps. Warp owns 16 q-rows.
// KT=32 keys per iteration. QK^T and PV on mma.m16n8k8.
#define AQT 64
#define AKT 32
#define QPAD 68   // Qs/Ks row stride: A/B frag patterns conflict-free (4g+cc)
#define VPAD 72   // Vs row stride: B frag pattern conflict-free (8cc+g)
#define PPAD 36   // Ps row stride: A frag pattern conflict-free (4g+cc)

__global__ __launch_bounds__(128)
void attn_mma_kernel(const float* __restrict__ Q, const float* __restrict__ K,
                     const float* __restrict__ V, const int* __restrict__ npm,
                     float* __restrict__ O)
{
    __shared__ unsigned Qs[AQT][QPAD];
    __shared__ unsigned Ks[AKT][QPAD];
    __shared__ unsigned Vs[AKT][VPAD];
    __shared__ unsigned Ps[AQT][PPAD];
    __shared__ float kms[AKT];

    const int b = blockIdx.z, h = blockIdx.y, qt = blockIdx.x;
    const int tid  = threadIdx.x;
    const int lane = tid & 31;
    const int wq   = tid >> 5;        // 0..3
    const int g    = lane >> 2;       // 0..7
    const int cc   = lane & 3;        // 0..3
    const int wr   = wq * 16;         // warp row base in tile

    // load Q tile (64 x 64) -> tf32
    const float* Qbase = Q + (size_t)(b * SS + qt * AQT) * DD + h * 64;
    #pragma unroll
    for (int i = tid; i < AQT * 16; i += 128) {
        int r = i >> 4, c4 = (i & 15) << 2;
        float4 v4 = *(const float4*)(Qbase + (size_t)r * DD + c4);
        Qs[r][c4+0] = f2tf(v4.x); Qs[r][c4+1] = f2tf(v4.y);
        Qs[r][c4+2] = f2tf(v4.z); Qs[r][c4+3] = f2tf(v4.w);
    }

    float m0 = -1e30f, m1 = -1e30f, l0 = 0.f, l1 = 0.f;
    float o[8][4];
    #pragma unroll
    for (int nt = 0; nt < 8; nt++) {
        o[nt][0] = 0.f; o[nt][1] = 0.f; o[nt][2] = 0.f; o[nt][3] = 0.f;
    }

    for (int kt = 0; kt < SS / AKT; kt++) {
        __syncthreads();
        const float* Kbase = K + (size_t)(b * SS + kt * AKT) * DD + h * 64;
        const float* Vbase = V + (size_t)(b * SS + kt * AKT) * DD + h * 64;
        #pragma unroll
        for (int i = tid; i < AKT * 16; i += 128) {
            int r = i >> 4, c4 = (i & 15) << 2;
            float4 kv = *(const float4*)(Kbase + (size_t)r * DD + c4);
            Ks[r][c4+0] = f2tf(kv.x); Ks[r][c4+1] = f2tf(kv.y);
            Ks[r][c4+2] = f2tf(kv.z); Ks[r][c4+3] = f2tf(kv.w);
            float4 vv = *(const float4*)(Vbase + (size_t)r * DD + c4);
            Vs[r][c4+0] = f2tf(vv.x); Vs[r][c4+1] = f2tf(vv.y);
            Vs[r][c4+2] = f2tf(vv.z); Vs[r][c4+3] = f2tf(vv.w);
        }
        if (tid < AKT) kms[tid] = npm[b * SS + kt * AKT + tid] ? 1.f : 0.f;
        __syncthreads();

        // ---- S = Q @ K^T (16 x 32 per warp) ----
        float s[4][4];
        #pragma unroll
        for (int nt = 0; nt < 4; nt++) {
            s[nt][0] = 0.f; s[nt][1] = 0.f; s[nt][2] = 0.f; s[nt][3] = 0.f;
        }
        #pragma unroll
        for (int ks = 0; ks < 8; ks++) {
            unsigned a[4];
            a[0] = Qs[wr + g    ][ks*8 + cc    ];
            a[1] = Qs[wr + g + 8][ks*8 + cc    ];
            a[2] = Qs[wr + g    ][ks*8 + cc + 4];
            a[3] = Qs[wr + g + 8][ks*8 + cc + 4];
            #pragma unroll
            for (int nt = 0; nt < 4; nt++) {
                unsigned bf[2];
                bf[0] = Ks[nt*8 + g][ks*8 + cc    ];
                bf[1] = Ks[nt*8 + g][ks*8 + cc + 4];
                mma_tf32(s[nt], a, bf);
            }
        }

        // ---- mask + scale ----
        #pragma unroll
        for (int nt = 0; nt < 4; nt++) {
            float k0 = kms[nt*8 + 2*cc];
            float k1 = kms[nt*8 + 2*cc + 1];
            s[nt][0] = (k0 != 0.f) ? s[nt][0] * ATT_SCALE : -1e9f;
            s[nt][1] = (k1 != 0.f) ? s[nt][1] * ATT_SCALE : -1e9f;
            s[nt][2] = (k0 != 0.f) ? s[nt][2] * ATT_SCALE : -1e9f;
            s[nt][3] = (k1 != 0.f) ? s[nt][3] * ATT_SCALE : -1e9f;
        }

        // ---- online softmax (rows g and g+8) ----
        float tm0 = s[0][0], tm1 = s[0][2];
        #pragma unroll
        for (int nt = 0; nt < 4; nt++) {
            tm0 = fmaxf(tm0, fmaxf(s[nt][0], s[nt][1]));
            tm1 = fmaxf(tm1, fmaxf(s[nt][2], s[nt][3]));
        }
        tm0 = fmaxf(tm0, __shfl_xor_sync(0xffffffffu, tm0, 1));
        tm0 = fmaxf(tm0, __shfl_xor_sync(0xffffffffu, tm0, 2));
        tm1 = fmaxf(tm1, __shfl_xor_sync(0xffffffffu, tm1, 1));
        tm1 = fmaxf(tm1, __shfl_xor_sync(0xffffffffu, tm1, 2));
        float nm0 = fmaxf(m0, tm0), nm1 = fmaxf(m1, tm1);
        float f0 = __expf(m0 - nm0), f1 = __expf(m1 - nm1);

        float sum0 = 0.f, sum1 = 0.f;
        #pragma unroll
        for (int nt = 0; nt < 4; nt++) {
            float p00 = __expf(s[nt][0] - nm0);
            float p01 = __expf(s[nt][1] - nm0);
            float p10 = __expf(s[nt][2] - nm1);
            float p11 = __expf(s[nt][3] - nm1);
            sum0 += p00 + p01;
            sum1 += p10 + p11;
            *(uint2*)&Ps[wr + g    ][nt*8 + 2*cc] = make_uint2(f2tf(p00), f2tf(p01));
            *(uint2*)&Ps[wr + g + 8][nt*8 + 2*cc] = make_uint2(f2tf(p10), f2tf(p11));
        }
        sum0 += __shfl_xor_sync(0xffffffffu, sum0, 1);
        sum0 += __shfl_xor_sync(0xffffffffu, sum0, 2);
        sum1 += __shfl_xor_sync(0xffffffffu, sum1, 1);
        sum1 += __shfl_xor_sync(0xffffffffu, sum1, 2);
        l0 = l0 * f0 + sum0;
        l1 = l1 * f1 + sum1;
        m0 = nm0; m1 = nm1;

        #pragma unroll
        for (int nt = 0; nt < 8; nt++) {
            o[nt][0] *= f0; o[nt][1] *= f0;
            o[nt][2] *= f1; o[nt][3] *= f1;
        }
        __syncwarp();

        // ---- O += P @ V (16 x 64 per warp) ----
        #pragma unroll
        for (int ks = 0; ks < 4; ks++) {
            unsigned a[4];
            a[0] = Ps[wr + g    ][ks*8 + cc    ];
            a[1] = Ps[wr + g + 8][ks*8 + cc    ];
            a[2] = Ps[wr + g    ][ks*8 + cc + 4];
            a[3] = Ps[wr + g + 8][ks*8 + cc + 4];
            #pragma unroll
            for (int nt = 0; nt < 8; nt++) {
                unsigned bf[2];
                bf[0] = Vs[ks*8 + cc    ][nt*8 + g];
                bf[1] = Vs[ks*8 + cc + 4][nt*8 + g];
                mma_tf32(o[nt], a, bf);
            }
        }
    }

    // ---- normalize + write out ----
    float i0 = 1.f / l0, i1 = 1.f / l1;
    size_t r0 = (size_t)(b * SS + qt * AQT + wr + g) * DD + h * 64;
    size_t r1 = r0 + (size_t)8 * DD;
    #pragma unroll
    for (int nt = 0; nt < 8; nt++) {
        int ncol = nt * 8 + 2 * cc;
        float2 w0, w1;
        w0.x = o[nt][0] * i0; w0.y = o[nt][1] * i0;
        w1.x = o[nt][2] * i1; w1.y = o[nt][3] * i1;
        *(float2*)(O + r0 + ncol) = w0;
        *(float2*)(O + r1 + ncol) = w1;
    }
}

// ---------------- host orchestration ----------------
extern "C" void kernel_launch(void* const* d_in, const int* in_sizes, int n_in,
                              void* d_out, int out_size)
{
    const float* embed = (const float*)d_in[0];
    const int*   npm   = (const int*)  d_in[1];
    const float* pe    = (const float*)d_in[2];
    const float* Wq    = (const float*)d_in[3];
    const float* bq    = (const float*)d_in[4];
    const float* Wk    = (const float*)d_in[5];
    const float* bk    = (const float*)d_in[6];
    const float* Wv    = (const float*)d_in[7];
    const float* bv    = (const float*)d_in[8];
    const float* Wo    = (const float*)d_in[9];
    const float* bo    = (const float*)d_in[10];
    const float* ln1g  = (const float*)d_in[11];
    const float* ln1b  = (const float*)d_in[12];
    const float* W1    = (const float*)d_in[13];
    const float* b1    = (const float*)d_in[14];
    const float* W2    = (const float*)d_in[15];
    const float* b2    = (const float*)d_in[16];
    const float* ln2g  = (const float*)d_in[17];
    const float* ln2b  = (const float*)d_in[18];
    const float* lnfg  = (const float*)d_in[19];
    const float* lnfb  = (const float*)d_in[20];

    float *x, *hh, *x1, *qb, *kb, *vb, *ob, *ffb;
    cudaGetSymbolAddress((void**)&x,   g_x);
    cudaGetSymbolAddress((void**)&hh,  g_h);
    cudaGetSymbolAddress((void**)&x1,  g_x1);
    cudaGetSymbolAddress((void**)&qb,  g_q);
    cudaGetSymbolAddress((void**)&kb,  g_k);
    cudaGetSymbolAddress((void**)&vb,  g_v);
    cudaGetSymbolAddress((void**)&ob,  g_o);
    cudaGetSymbolAddress((void**)&ffb, g_ff);

    {
        int tot4 = MM * DD / 4;
        add_pe_kernel<<<(tot4 + 255) / 256, 256>>>(embed, pe, x);
    }

    dim3 gD(DD / BN, MM / BM);       // (8, 32)
    dim3 gF(FF / BN, MM / BM);       // (32, 32)
    dim3 gAttn(SS / AQT, HH, BB);    // (16, 16, 4)

    for (int l = 0; l < LYR; l++) {
        const float* wq = Wq + (size_t)l * DD * DD;
        const float* wk = Wk + (size_t)l * DD * DD;
        const float* wv = Wv + (size_t)l * DD * DD;
        const float* wo = Wo + (size_t)l * DD * DD;
        const float* w1 = W1 + (size_t)l * DD * FF;
        const float* w2 = W2 + (size_t)l * FF * DD;
        const float* lbq = bq + (size_t)l * DD;
        const float* lbk = bk + (size_t)l * DD;
        const float* lbv = bv + (size_t)l * DD;
        const float* lbo = bo + (size_t)l * DD;
        const float* lb1 = b1 + (size_t)l * FF;
        const float* lb2 = b2 + (size_t)l * DD;

        ln_kernel<<<MM, 256>>>(x, ln1g + (size_t)l * DD, ln1b + (size_t)l * DD, hh);
        mma_gemm_kernel<<<gD, 256>>>(hh, wq, lbq, nullptr, nullptr, qb, MM, DD, DD, 0);
        mma_gemm_kernel<<<gD, 256>>>(hh, wk, lbk, nullptr, nullptr, kb, MM, DD, DD, 0);
        mma_gemm_kernel<<<gD, 256>>>(hh, wv, lbv, nullptr, nullptr, vb, MM, DD, DD, 0);
        attn_mma_kernel<<<gAttn, 128>>>(qb, kb, vb, npm, ob);
        mma_gemm_kernel<<<gD, 256>>>(ob, wo, lbo, hh, npm, x1, MM, DD, DD, 2);
        ln_kernel<<<MM, 256>>>(x1, ln2g + (size_t)l * DD, ln2b + (size_t)l * DD, hh);
        mma_gemm_kernel<<<gF, 256>>>(hh, w1, lb1, nullptr, nullptr, ffb, MM, FF, DD, 1);
        mma_gemm_kernel<<<gD, 256>>>(ffb, w2, lb2, hh, npm, x, MM, DD, FF, 2);
    }

    ln_kernel<<<MM, 256>>>(x, lnfg, lnfb, (float*)d_out);
}

// round 5
// speedup vs baseline: 3.7993x; 1.3116x over previous
#include <cuda_runtime.h>
#include <math.h>

// Problem constants
#define LYR 6
#define BB  4
#define SS  1024
#define DD  1024
#define HH  16
#define DKK 64
#define FF  4096
#define MM  (BB*SS)          // 4096 rows
#define ATT_SCALE 0.125f     // 1/sqrt(64)
#define LN_EPS 1e-6f

// ---------------- scratch buffers (device globals; no allocation) -------------
__device__ float g_x [MM*DD];
__device__ float g_h [MM*DD];
__device__ float g_x1[MM*DD];
__device__ float g_q [MM*DD];
__device__ float g_k [MM*DD];
__device__ float g_v [MM*DD];
__device__ float g_o [MM*DD];
__device__ float g_ff[MM*FF];

// ---------------- PE add ----------------
__global__ void add_pe_kernel(const float* __restrict__ embed,
                              const float* __restrict__ pe,
                              float* __restrict__ x)
{
    int i = blockIdx.x * blockDim.x + threadIdx.x;
    const int TOT4 = MM * DD / 4;
    if (i >= TOT4) return;
    int pe4 = i % (SS * DD / 4);
    float4 e = ((const float4*)embed)[i];
    float4 p = ((const float4*)pe)[pe4];
    float4 r; r.x = e.x + p.x; r.y = e.y + p.y; r.z = e.z + p.z; r.w = e.w + p.w;
    ((float4*)x)[i] = r;
}

// ---------------- LayerNorm ----------------
__global__ void ln_kernel(const float* __restrict__ x,
                          const float* __restrict__ g,
                          const float* __restrict__ beta,
                          float* __restrict__ y)
{
    __shared__ float shm[32];
    __shared__ float s_mu, s_rstd;
    int row = blockIdx.x;
    int t   = threadIdx.x;
    const float4* xr = (const float4*)(x + (size_t)row * DD);
    float4 v = xr[t];
    float s = v.x + v.y + v.z + v.w;
    #pragma unroll
    for (int o = 16; o; o >>= 1) s += __shfl_xor_sync(0xffffffffu, s, o);
    if ((t & 31) == 0) shm[t >> 5] = s;
    __syncthreads();
    if (t < 32) {
        float tot = (t < 8) ? shm[t] : 0.f;
        #pragma unroll
        for (int o = 4; o; o >>= 1) tot += __shfl_xor_sync(0xffffffffu, tot, o);
        if (t == 0) s_mu = tot * (1.0f / DD);
    }
    __syncthreads();
    float mu = s_mu;
    float d0 = v.x - mu, d1 = v.y - mu, d2 = v.z - mu, d3 = v.w - mu;
    float s2 = d0*d0 + d1*d1 + d2*d2 + d3*d3;
    #pragma unroll
    for (int o = 16; o; o >>= 1) s2 += __shfl_xor_sync(0xffffffffu, s2, o);
    if ((t & 31) == 0) shm[t >> 5] = s2;
    __syncthreads();
    if (t < 32) {
        float tot = (t < 8) ? shm[t] : 0.f;
        #pragma unroll
        for (int o = 4; o; o >>= 1) tot += __shfl_xor_sync(0xffffffffu, tot, o);
        if (t == 0) s_rstd = rsqrtf(tot * (1.0f / DD) + LN_EPS);
    }
    __syncthreads();
    float rstd = s_rstd;
    float4 gg = ((const float4*)g)[t];
    float4 bb = ((const float4*)beta)[t];
    float4 out;
    out.x = d0 * rstd * gg.x + bb.x;
    out.y = d1 * rstd * gg.y + bb.y;
    out.z = d2 * rstd * gg.z + bb.z;
    out.w = d3 * rstd * gg.w + bb.w;
    ((float4*)(y + (size_t)row * DD))[t] = out;
}

// ---------------- TF32 helpers ----------------
__device__ __forceinline__ unsigned f2tf(float f) {
    unsigned u;
    asm("cvt.rna.tf32.f32 %0, %1;" : "=r"(u) : "f"(f));
    return u;
}

__device__ __forceinline__ void mma_tf32(float c[4], const unsigned a[4], const unsigned b[2]) {
    asm volatile("mma.sync.aligned.m16n8k8.row.col.f32.tf32.tf32.f32 "
        "{%0,%1,%2,%3}, {%4,%5,%6,%7}, {%8,%9}, {%0,%1,%2,%3};"
        : "+f"(c[0]), "+f"(c[1]), "+f"(c[2]), "+f"(c[3])
        : "r"(a[0]), "r"(a[1]), "r"(a[2]), "r"(a[3]), "r"(b[0]), "r"(b[1]));
}

__device__ __forceinline__ void cp16(unsigned dst, const void* src) {
    asm volatile("cp.async.cg.shared.global [%0], [%1], 16;" :: "r"(dst), "l"(src));
}
#define CP_COMMIT() asm volatile("cp.async.commit_group;" ::: "memory")
#define CP_WAIT2()  asm volatile("cp.async.wait_group 2;" ::: "memory")

// ---------------- TF32 GEMM, 4-stage cp.async pipeline -----------------------
// C[M,N] = A[M,K] @ W[K,N] (+ bias) (+relu) (+ residual, * seq mask)
#define BM 128
#define BN 128
#define BK 16
#define STAGES 4
#define ASTRF 20     // A smem row stride (floats); 80B rows, 16B aligned
#define BSTRF 136    // B smem row stride (floats); 544B rows, 16B aligned
#define A_STG (BM*ASTRF)   // 2560 floats / stage
#define B_STG (BK*BSTRF)   // 2176 floats / stage
#define GEMM_SMEM_BYTES (STAGES * (A_STG + B_STG) * 4)   // 75776

__global__ __launch_bounds__(256, 2)
void mma_gemm_kernel(const float* __restrict__ A, const float* __restrict__ W,
                     const float* __restrict__ bias, const float* __restrict__ res,
                     const int* __restrict__ mask, float* __restrict__ C,
                     int M, int N, int K, int epi)
{
    extern __shared__ float smemf[];
    float* Asm = smemf;                       // [STAGES][BM][ASTRF]
    float* Bsm = smemf + STAGES * A_STG;      // [STAGES][BK][BSTRF]
    const unsigned a_u = (unsigned)__cvta_generic_to_shared(Asm);
    const unsigned b_u = (unsigned)__cvta_generic_to_shared(Bsm);

    const int tid  = threadIdx.x;
    const int lane = tid & 31;
    const int wrp  = tid >> 5;
    const int wm   = wrp >> 2;       // 0..1
    const int wn   = wrp & 3;        // 0..3
    const int g    = lane >> 2;      // 0..7
    const int cc   = lane & 3;       // 0..3

    const int brow = blockIdx.y * BM;
    const int bcol = blockIdx.x * BN;

    // staging assignment: A — thread copies 32B: row tid>>1, col (tid&1)*8
    const int a_r = tid >> 1, a_c = (tid & 1) * 8;
    // B — thread copies 32B: row tid>>4, col (tid&15)*8
    const int b_r = tid >> 4, b_c = (tid & 15) * 8;

    const float* Ag = A + (size_t)(brow + a_r) * K + a_c;
    const float* Wg = W + bcol + b_c;

    const int NK = K / BK;

    // issue staging for stage s holding k-tile kt
    auto load_stage = [&](int s, int kt) {
        const float* ag = Ag + kt * BK;
        unsigned ad = a_u + (unsigned)((s * A_STG + a_r * ASTRF + a_c) * 4);
        cp16(ad, ag); cp16(ad + 16, ag + 4);
        const float* bg = Wg + (size_t)(kt * BK + b_r) * N;
        unsigned bd = b_u + (unsigned)((s * B_STG + b_r * BSTRF + b_c) * 4);
        cp16(bd, bg); cp16(bd + 16, bg + 4);
    };

    float acc[4][4][4];
    #pragma unroll
    for (int i = 0; i < 4; i++)
        #pragma unroll
        for (int j = 0; j < 4; j++) {
            acc[i][j][0] = 0.f; acc[i][j][1] = 0.f;
            acc[i][j][2] = 0.f; acc[i][j][3] = 0.f;
        }

    // prologue: stages 0..2 in flight
    load_stage(0, 0); CP_COMMIT();
    load_stage(1, 1); CP_COMMIT();
    load_stage(2, 2); CP_COMMIT();

    int cur = 0;
    for (int kt = 0; kt < NK; kt++) {
        CP_WAIT2();
        __syncthreads();

        if (kt + 3 < NK) load_stage((kt + 3) & 3, kt + 3);
        CP_COMMIT();

        const float* As_s = Asm + cur * A_STG;
        const float* Bs_s = Bsm + cur * B_STG;

        #pragma unroll
        for (int ks = 0; ks < 2; ks++) {
            const int kk = ks * 8;
            unsigned a[4][4], b[4][2];
            #pragma unroll
            for (int mt = 0; mt < 4; mt++) {
                int rb = wm * 64 + mt * 16;
                a[mt][0] = f2tf(As_s[(rb + g    ) * ASTRF + kk + cc    ]);
                a[mt][1] = f2tf(As_s[(rb + g + 8) * ASTRF + kk + cc    ]);
                a[mt][2] = f2tf(As_s[(rb + g    ) * ASTRF + kk + cc + 4]);
                a[mt][3] = f2tf(As_s[(rb + g + 8) * ASTRF + kk + cc + 4]);
            }
            #pragma unroll
            for (int nt = 0; nt < 4; nt++) {
                int nb = wn * 32 + nt * 8;
                b[nt][0] = f2tf(Bs_s[(kk + cc    ) * BSTRF + nb + g]);
                b[nt][1] = f2tf(Bs_s[(kk + cc + 4) * BSTRF + nb + g]);
            }
            #pragma unroll
            for (int mt = 0; mt < 4; mt++)
                #pragma unroll
                for (int nt = 0; nt < 4; nt++)
                    mma_tf32(acc[mt][nt], a[mt], b[nt]);
        }
        cur = (cur + 1) & 3;
    }

    // ---- epilogue ----
    #pragma unroll
    for (int mt = 0; mt < 4; mt++) {
        int r0 = brow + wm * 64 + mt * 16 + g;
        int r1 = r0 + 8;
        float mk0 = 1.f, mk1 = 1.f;
        if (epi == 2) {
            mk0 = mask[r0] ? 1.f : 0.f;
            mk1 = mask[r1] ? 1.f : 0.f;
        }
        #pragma unroll
        for (int nt = 0; nt < 4; nt++) {
            int ncol = bcol + wn * 32 + nt * 8 + cc * 2;
            float2 bv = *(const float2*)(bias + ncol);
            float2 o0, o1;
            o0.x = acc[mt][nt][0] + bv.x; o0.y = acc[mt][nt][1] + bv.y;
            o1.x = acc[mt][nt][2] + bv.x; o1.y = acc[mt][nt][3] + bv.y;
            if (epi == 1) {
                o0.x = fmaxf(o0.x, 0.f); o0.y = fmaxf(o0.y, 0.f);
                o1.x = fmaxf(o1.x, 0.f); o1.y = fmaxf(o1.y, 0.f);
            } else if (epi == 2) {
                float2 rv0 = *(const float2*)(res + (size_t)r0 * N + ncol);
                float2 rv1 = *(const float2*)(res + (size_t)r1 * N + ncol);
                o0.x = (o0.x + rv0.x) * mk0; o0.y = (o0.y + rv0.y) * mk0;
                o1.x = (o1.x + rv1.x) * mk1; o1.y = (o1.y + rv1.y) * mk1;
            }
            *(float2*)(C + (size_t)r0 * N + ncol) = o0;
            *(float2*)(C + (size_t)r1 * N + ncol) = o1;
        }
    }
}

// ---------------- Tensor-core flash attention (TF32 mma) ---------------------
#define AQT 64
#define AKT 32
#define QPAD 68
#define VPAD 72
#define PPAD 36

__global__ __launch_bounds__(128)
void attn_mma_kernel(const float* __restrict__ Q, const float* __restrict__ K,
                     const float* __restrict__ V, const int* __restrict__ npm,
                     float* __restrict__ O)
{
    __shared__ unsigned Qs[AQT][QPAD];
    __shared__ unsigned Ks[AKT][QPAD];
    __shared__ unsigned Vs[AKT][VPAD];
    __shared__ unsigned Ps[AQT][PPAD];
    __shared__ float kms[AKT];

    const int b = blockIdx.z, h = blockIdx.y, qt = blockIdx.x;
    const int tid  = threadIdx.x;
    const int lane = tid & 31;
    const int wq   = tid >> 5;
    const int g    = lane >> 2;
    const int cc   = lane & 3;
    const int wr   = wq * 16;

    const float* Qbase = Q + (size_t)(b * SS + qt * AQT) * DD + h * 64;
    #pragma unroll
    for (int i = tid; i < AQT * 16; i += 128) {
        int r = i >> 4, c4 = (i & 15) << 2;
        float4 v4 = *(const float4*)(Qbase + (size_t)r * DD + c4);
        Qs[r][c4+0] = f2tf(v4.x); Qs[r][c4+1] = f2tf(v4.y);
        Qs[r][c4+2] = f2tf(v4.z); Qs[r][c4+3] = f2tf(v4.w);
    }

    float m0 = -1e30f, m1 = -1e30f, l0 = 0.f, l1 = 0.f;
    float o[8][4];
    #pragma unroll
    for (int nt = 0; nt < 8; nt++) {
        o[nt][0] = 0.f; o[nt][1] = 0.f; o[nt][2] = 0.f; o[nt][3] = 0.f;
    }

    for (int kt = 0; kt < SS / AKT; kt++) {
        __syncthreads();
        const float* Kbase = K + (size_t)(b * SS + kt * AKT) * DD + h * 64;
        const float* Vbase = V + (size_t)(b * SS + kt * AKT) * DD + h * 64;
        #pragma unroll
        for (int i = tid; i < AKT * 16; i += 128) {
            int r = i >> 4, c4 = (i & 15) << 2;
            float4 kv = *(const float4*)(Kbase + (size_t)r * DD + c4);
            Ks[r][c4+0] = f2tf(kv.x); Ks[r][c4+1] = f2tf(kv.y);
            Ks[r][c4+2] = f2tf(kv.z); Ks[r][c4+3] = f2tf(kv.w);
            float4 vv = *(const float4*)(Vbase + (size_t)r * DD + c4);
            Vs[r][c4+0] = f2tf(vv.x); Vs[r][c4+1] = f2tf(vv.y);
            Vs[r][c4+2] = f2tf(vv.z); Vs[r][c4+3] = f2tf(vv.w);
        }
        if (tid < AKT) kms[tid] = npm[b * SS + kt * AKT + tid] ? 1.f : 0.f;
        __syncthreads();

        float s[4][4];
        #pragma unroll
        for (int nt = 0; nt < 4; nt++) {
            s[nt][0] = 0.f; s[nt][1] = 0.f; s[nt][2] = 0.f; s[nt][3] = 0.f;
        }
        #pragma unroll
        for (int ks = 0; ks < 8; ks++) {
            unsigned a[4];
            a[0] = Qs[wr + g    ][ks*8 + cc    ];
            a[1] = Qs[wr + g + 8][ks*8 + cc    ];
            a[2] = Qs[wr + g    ][ks*8 + cc + 4];
            a[3] = Qs[wr + g + 8][ks*8 + cc + 4];
            #pragma unroll
            for (int nt = 0; nt < 4; nt++) {
                unsigned bf[2];
                bf[0] = Ks[nt*8 + g][ks*8 + cc    ];
                bf[1] = Ks[nt*8 + g][ks*8 + cc + 4];
                mma_tf32(s[nt], a, bf);
            }
        }

        #pragma unroll
        for (int nt = 0; nt < 4; nt++) {
            float k0 = kms[nt*8 + 2*cc];
            float k1 = kms[nt*8 + 2*cc + 1];
            s[nt][0] = (k0 != 0.f) ? s[nt][0] * ATT_SCALE : -1e9f;
            s[nt][1] = (k1 != 0.f) ? s[nt][1] * ATT_SCALE : -1e9f;
            s[nt][2] = (k0 != 0.f) ? s[nt][2] * ATT_SCALE : -1e9f;
            s[nt][3] = (k1 != 0.f) ? s[nt][3] * ATT_SCALE : -1e9f;
        }

        float tm0 = s[0][0], tm1 = s[0][2];
        #pragma unroll
        for (int nt = 0; nt < 4; nt++) {
            tm0 = fmaxf(tm0, fmaxf(s[nt][0], s[nt][1]));
            tm1 = fmaxf(tm1, fmaxf(s[nt][2], s[nt][3]));
        }
        tm0 = fmaxf(tm0, __shfl_xor_sync(0xffffffffu, tm0, 1));
        tm0 = fmaxf(tm0, __shfl_xor_sync(0xffffffffu, tm0, 2));
        tm1 = fmaxf(tm1, __shfl_xor_sync(0xffffffffu, tm1, 1));
        tm1 = fmaxf(tm1, __shfl_xor_sync(0xffffffffu, tm1, 2));
        float nm0 = fmaxf(m0, tm0), nm1 = fmaxf(m1, tm1);
        float f0 = __expf(m0 - nm0), f1 = __expf(m1 - nm1);

        float sum0 = 0.f, sum1 = 0.f;
        #pragma unroll
        for (int nt = 0; nt < 4; nt++) {
            float p00 = __expf(s[nt][0] - nm0);
            float p01 = __expf(s[nt][1] - nm0);
            float p10 = __expf(s[nt][2] - nm1);
            float p11 = __expf(s[nt][3] - nm1);
            sum0 += p00 + p01;
            sum1 += p10 + p11;
            *(uint2*)&Ps[wr + g    ][nt*8 + 2*cc] = make_uint2(f2tf(p00), f2tf(p01));
            *(uint2*)&Ps[wr + g + 8][nt*8 + 2*cc] = make_uint2(f2tf(p10), f2tf(p11));
        }
        sum0 += __shfl_xor_sync(0xffffffffu, sum0, 1);
        sum0 += __shfl_xor_sync(0xffffffffu, sum0, 2);
        sum1 += __shfl_xor_sync(0xffffffffu, sum1, 1);
        sum1 += __shfl_xor_sync(0xffffffffu, sum1, 2);
        l0 = l0 * f0 + sum0;
        l1 = l1 * f1 + sum1;
        m0 = nm0; m1 = nm1;

        #pragma unroll
        for (int nt = 0; nt < 8; nt++) {
            o[nt][0] *= f0; o[nt][1] *= f0;
            o[nt][2] *= f1; o[nt][3] *= f1;
        }
        __syncwarp();

        #pragma unroll
        for (int ks = 0; ks < 4; ks++) {
            unsigned a[4];
            a[0] = Ps[wr + g    ][ks*8 + cc    ];
            a[1] = Ps[wr + g + 8][ks*8 + cc    ];
            a[2] = Ps[wr + g    ][ks*8 + cc + 4];
            a[3] = Ps[wr + g + 8][ks*8 + cc + 4];
            #pragma unroll
            for (int nt = 0; nt < 8; nt++) {
                unsigned bf[2];
                bf[0] = Vs[ks*8 + cc    ][nt*8 + g];
                bf[1] = Vs[ks*8 + cc + 4][nt*8 + g];
                mma_tf32(o[nt], a, bf);
            }
        }
    }

    float i0 = 1.f / l0, i1 = 1.f / l1;
    size_t r0 = (size_t)(b * SS + qt * AQT + wr + g) * DD + h * 64;
    size_t r1 = r0 + (size_t)8 * DD;
    #pragma unroll
    for (int nt = 0; nt < 8; nt++) {
        int ncol = nt * 8 + 2 * cc;
        float2 w0, w1;
        w0.x = o[nt][0] * i0; w0.y = o[nt][1] * i0;
        w1.x = o[nt][2] * i1; w1.y = o[nt][3] * i1;
        *(float2*)(O + r0 + ncol) = w0;
        *(float2*)(O + r1 + ncol) = w1;
    }
}

// ---------------- host orchestration ----------------
extern "C" void kernel_launch(void* const* d_in, const int* in_sizes, int n_in,
                              void* d_out, int out_size)
{
    const float* embed = (const float*)d_in[0];
    const int*   npm   = (const int*)  d_in[1];
    const float* pe    = (const float*)d_in[2];
    const float* Wq    = (const float*)d_in[3];
    const float* bq    = (const float*)d_in[4];
    const float* Wk    = (const float*)d_in[5];
    const float* bk    = (const float*)d_in[6];
    const float* Wv    = (const float*)d_in[7];
    const float* bv    = (const float*)d_in[8];
    const float* Wo    = (const float*)d_in[9];
    const float* bo    = (const float*)d_in[10];
    const float* ln1g  = (const float*)d_in[11];
    const float* ln1b  = (const float*)d_in[12];
    const float* W1    = (const float*)d_in[13];
    const float* b1    = (const float*)d_in[14];
    const float* W2    = (const float*)d_in[15];
    const float* b2    = (const float*)d_in[16];
    const float* ln2g  = (const float*)d_in[17];
    const float* ln2b  = (const float*)d_in[18];
    const float* lnfg  = (const float*)d_in[19];
    const float* lnfb  = (const float*)d_in[20];

    float *x, *hh, *x1, *qb, *kb, *vb, *ob, *ffb;
    cudaGetSymbolAddress((void**)&x,   g_x);
    cudaGetSymbolAddress((void**)&hh,  g_h);
    cudaGetSymbolAddress((void**)&x1,  g_x1);
    cudaGetSymbolAddress((void**)&qb,  g_q);
    cudaGetSymbolAddress((void**)&kb,  g_k);
    cudaGetSymbolAddress((void**)&vb,  g_v);
    cudaGetSymbolAddress((void**)&ob,  g_o);
    cudaGetSymbolAddress((void**)&ffb, g_ff);

    cudaFuncSetAttribute(mma_gemm_kernel,
                         cudaFuncAttributeMaxDynamicSharedMemorySize,
                         GEMM_SMEM_BYTES);

    {
        int tot4 = MM * DD / 4;
        add_pe_kernel<<<(tot4 + 255) / 256, 256>>>(embed, pe, x);
    }

    dim3 gD(DD / BN, MM / BM);       // (8, 32)
    dim3 gF(FF / BN, MM / BM);       // (32, 32)
    dim3 gAttn(SS / AQT, HH, BB);    // (16, 16, 4)

    for (int l = 0; l < LYR; l++) {
        const float* wq = Wq + (size_t)l * DD * DD;
        const float* wk = Wk + (size_t)l * DD * DD;
        const float* wv = Wv + (size_t)l * DD * DD;
        const float* wo = Wo + (size_t)l * DD * DD;
        const float* w1 = W1 + (size_t)l * DD * FF;
        const float* w2 = W2 + (size_t)l * FF * DD;
        const float* lbq = bq + (size_t)l * DD;
        const float* lbk = bk + (size_t)l * DD;
        const float* lbv = bv + (size_t)l * DD;
        const float* lbo = bo + (size_t)l * DD;
        const float* lb1 = b1 + (size_t)l * FF;
        const float* lb2 = b2 + (size_t)l * DD;

        ln_kernel<<<MM, 256>>>(x, ln1g + (size_t)l * DD, ln1b + (size_t)l * DD, hh);
        mma_gemm_kernel<<<gD, 256, GEMM_SMEM_BYTES>>>(hh, wq, lbq, nullptr, nullptr, qb, MM, DD, DD, 0);
        mma_gemm_kernel<<<gD, 256, GEMM_SMEM_BYTES>>>(hh, wk, lbk, nullptr, nullptr, kb, MM, DD, DD, 0);
        mma_gemm_kernel<<<gD, 256, GEMM_SMEM_BYTES>>>(hh, wv, lbv, nullptr, nullptr, vb, MM, DD, DD, 0);
        attn_mma_kernel<<<gAttn, 128>>>(qb, kb, vb, npm, ob);
        mma_gemm_kernel<<<gD, 256, GEMM_SMEM_BYTES>>>(ob, wo, lbo, hh, npm, x1, MM, DD, DD, 2);
        ln_kernel<<<MM, 256>>>(x1, ln2g + (size_t)l * DD, ln2b + (size_t)l * DD, hh);
        mma_gemm_kernel<<<gF, 256, GEMM_SMEM_BYTES>>>(hh, w1, lb1, nullptr, nullptr, ffb, MM, FF, DD, 1);
        mma_gemm_kernel<<<gD, 256, GEMM_SMEM_BYTES>>>(ffb, w2, lb2, hh, npm, x, MM, DD, FF, 2);
    }

    ln_kernel<<<MM, 256>>>(x, lnfg, lnfb, (float*)d_out);
}

// round 6
// speedup vs baseline: 3.9237x; 1.0328x over previous
#include <cuda_runtime.h>
#include <math.h>

// Problem constants
#define LYR 6
#define BB  4
#define SS  1024
#define DD  1024
#define HH  16
#define DKK 64
#define FF  4096
#define MM  (BB*SS)          // 4096 rows
#define ATT_SCALE 0.125f     // 1/sqrt(64)
#define LN_EPS 1e-6f

// ---------------- scratch buffers (device globals; no allocation) -------------
__device__ float g_x [MM*DD];
__device__ float g_h [MM*DD];
__device__ float g_htf[MM*DD];      // tf32-rounded LN output (GEMM A operand)
__device__ float g_x1[MM*DD];
__device__ float g_q [MM*DD];
__device__ float g_k [MM*DD];
__device__ float g_v [MM*DD];
__device__ float g_o [MM*DD];       // attn out, tf32-rounded
__device__ float g_ff[MM*FF];       // relu out, tf32-rounded
// pre-rounded weights (tf32 values stored as fp32)
__device__ float g_wqc[LYR*DD*DD];
__device__ float g_wkc[LYR*DD*DD];
__device__ float g_wvc[LYR*DD*DD];
__device__ float g_woc[LYR*DD*DD];
__device__ float g_w1c[LYR*DD*FF];
__device__ float g_w2c[LYR*FF*DD];

// ---------------- TF32 helpers ----------------
__device__ __forceinline__ unsigned f2tf(float f) {
    unsigned u;
    asm("cvt.rna.tf32.f32 %0, %1;" : "=r"(u) : "f"(f));
    return u;
}
__device__ __forceinline__ float f2tf_f(float f) {
    return __uint_as_float(f2tf(f));
}

__device__ __forceinline__ void mma_tf32(float c[4], const unsigned a[4], const unsigned b[2]) {
    asm volatile("mma.sync.aligned.m16n8k8.row.col.f32.tf32.tf32.f32 "
        "{%0,%1,%2,%3}, {%4,%5,%6,%7}, {%8,%9}, {%0,%1,%2,%3};"
        : "+f"(c[0]), "+f"(c[1]), "+f"(c[2]), "+f"(c[3])
        : "r"(a[0]), "r"(a[1]), "r"(a[2]), "r"(a[3]), "r"(b[0]), "r"(b[1]));
}

__device__ __forceinline__ void cp16(unsigned dst, const void* src) {
    asm volatile("cp.async.cg.shared.global [%0], [%1], 16;" :: "r"(dst), "l"(src));
}
#define CP_COMMIT() asm volatile("cp.async.commit_group;" ::: "memory")
#define CP_WAIT2()  asm volatile("cp.async.wait_group 2;" ::: "memory")

// ---------------- weight pre-rounding: dst = tf32(src) -----------------------
__global__ void tfconv_kernel(const float* __restrict__ src,
                              float* __restrict__ dst, int n4)
{
    int i = blockIdx.x * blockDim.x + threadIdx.x;
    if (i >= n4) return;
    float4 v = ((const float4*)src)[i];
    float4 r;
    r.x = f2tf_f(v.x); r.y = f2tf_f(v.y);
    r.z = f2tf_f(v.z); r.w = f2tf_f(v.w);
    ((float4*)dst)[i] = r;
}

// ---------------- PE add ----------------
__global__ void add_pe_kernel(const float* __restrict__ embed,
                              const float* __restrict__ pe,
                              float* __restrict__ x)
{
    int i = blockIdx.x * blockDim.x + threadIdx.x;
    const int TOT4 = MM * DD / 4;
    if (i >= TOT4) return;
    int pe4 = i % (SS * DD / 4);
    float4 e = ((const float4*)embed)[i];
    float4 p = ((const float4*)pe)[pe4];
    float4 r; r.x = e.x + p.x; r.y = e.y + p.y; r.z = e.z + p.z; r.w = e.w + p.w;
    ((float4*)x)[i] = r;
}

// ---------------- LayerNorm (dual output: fp32 + tf32-rounded) ---------------
__global__ void ln_kernel(const float* __restrict__ x,
                          const float* __restrict__ g,
                          const float* __restrict__ beta,
                          float* __restrict__ y,
                          float* __restrict__ ytf)
{
    __shared__ float shm[32];
    __shared__ float s_mu, s_rstd;
    int row = blockIdx.x;
    int t   = threadIdx.x;
    const float4* xr = (const float4*)(x + (size_t)row * DD);
    float4 v = xr[t];
    float s = v.x + v.y + v.z + v.w;
    #pragma unroll
    for (int o = 16; o; o >>= 1) s += __shfl_xor_sync(0xffffffffu, s, o);
    if ((t & 31) == 0) shm[t >> 5] = s;
    __syncthreads();
    if (t < 32) {
        float tot = (t < 8) ? shm[t] : 0.f;
        #pragma unroll
        for (int o = 4; o; o >>= 1) tot += __shfl_xor_sync(0xffffffffu, tot, o);
        if (t == 0) s_mu = tot * (1.0f / DD);
    }
    __syncthreads();
    float mu = s_mu;
    float d0 = v.x - mu, d1 = v.y - mu, d2 = v.z - mu, d3 = v.w - mu;
    float s2 = d0*d0 + d1*d1 + d2*d2 + d3*d3;
    #pragma unroll
    for (int o = 16; o; o >>= 1) s2 += __shfl_xor_sync(0xffffffffu, s2, o);
    if ((t & 31) == 0) shm[t >> 5] = s2;
    __syncthreads();
    if (t < 32) {
        float tot = (t < 8) ? shm[t] : 0.f;
        #pragma unroll
        for (int o = 4; o; o >>= 1) tot += __shfl_xor_sync(0xffffffffu, tot, o);
        if (t == 0) s_rstd = rsqrtf(tot * (1.0f / DD) + LN_EPS);
    }
    __syncthreads();
    float rstd = s_rstd;
    float4 gg = ((const float4*)g)[t];
    float4 bb = ((const float4*)beta)[t];
    float4 out;
    out.x = d0 * rstd * gg.x + bb.x;
    out.y = d1 * rstd * gg.y + bb.y;
    out.z = d2 * rstd * gg.z + bb.z;
    out.w = d3 * rstd * gg.w + bb.w;
    ((float4*)(y + (size_t)row * DD))[t] = out;
    if (ytf) {
        float4 rt;
        rt.x = f2tf_f(out.x); rt.y = f2tf_f(out.y);
        rt.z = f2tf_f(out.z); rt.w = f2tf_f(out.w);
        ((float4*)(ytf + (size_t)row * DD))[t] = rt;
    }
}

// ---------------- TF32 GEMM, 4-stage cp.async pipeline -----------------------
// Inputs A and W must already be tf32-rounded fp32 values.
// C = A @ W (+bias) (+relu->tf32) (+residual, *mask)
#define BM 128
#define BN 128
#define BK 16
#define STAGES 4
#define ASTRF 20
#define BSTRF 136
#define A_STG (BM*ASTRF)
#define B_STG (BK*BSTRF)
#define GEMM_SMEM_BYTES (STAGES * (A_STG + B_STG) * 4)   // 75776

__global__ __launch_bounds__(256, 2)
void mma_gemm_kernel(const float* __restrict__ A, const float* __restrict__ W,
                     const float* __restrict__ bias, const float* __restrict__ res,
                     const int* __restrict__ mask, float* __restrict__ C,
                     int M, int N, int K, int epi)
{
    extern __shared__ float smemf[];
    float* Asm = smemf;
    float* Bsm = smemf + STAGES * A_STG;
    const unsigned* Asu = (const unsigned*)Asm;
    const unsigned* Bsu = (const unsigned*)Bsm;
    const unsigned a_u = (unsigned)__cvta_generic_to_shared(Asm);
    const unsigned b_u = (unsigned)__cvta_generic_to_shared(Bsm);

    const int tid  = threadIdx.x;
    const int lane = tid & 31;
    const int wrp  = tid >> 5;
    const int wm   = wrp >> 2;
    const int wn   = wrp & 3;
    const int g    = lane >> 2;
    const int cc   = lane & 3;

    const int brow = blockIdx.y * BM;
    const int bcol = blockIdx.x * BN;

    const int a_r = tid >> 1, a_c = (tid & 1) * 8;
    const int b_r = tid >> 4, b_c = (tid & 15) * 8;

    const float* Ag = A + (size_t)(brow + a_r) * K + a_c;
    const float* Wg = W + bcol + b_c;

    const int NK = K / BK;

    auto load_stage = [&](int s, int kt) {
        const float* ag = Ag + kt * BK;
        unsigned ad = a_u + (unsigned)((s * A_STG + a_r * ASTRF + a_c) * 4);
        cp16(ad, ag); cp16(ad + 16, ag + 4);
        const float* bg = Wg + (size_t)(kt * BK + b_r) * N;
        unsigned bd = b_u + (unsigned)((s * B_STG + b_r * BSTRF + b_c) * 4);
        cp16(bd, bg); cp16(bd + 16, bg + 4);
    };

    float acc[4][4][4];
    #pragma unroll
    for (int i = 0; i < 4; i++)
        #pragma unroll
        for (int j = 0; j < 4; j++) {
            acc[i][j][0] = 0.f; acc[i][j][1] = 0.f;
            acc[i][j][2] = 0.f; acc[i][j][3] = 0.f;
        }

    load_stage(0, 0); CP_COMMIT();
    load_stage(1, 1); CP_COMMIT();
    load_stage(2, 2); CP_COMMIT();

    int cur = 0;
    for (int kt = 0; kt < NK; kt++) {
        CP_WAIT2();
        __syncthreads();

        if (kt + 3 < NK) load_stage((kt + 3) & 3, kt + 3);
        CP_COMMIT();

        const unsigned* As_s = Asu + cur * A_STG;
        const unsigned* Bs_s = Bsu + cur * B_STG;

        #pragma unroll
        for (int ks = 0; ks < 2; ks++) {
            const int kk = ks * 8;
            unsigned a[4][4], b[4][2];
            #pragma unroll
            for (int mt = 0; mt < 4; mt++) {
                int rb = wm * 64 + mt * 16;
                a[mt][0] = As_s[(rb + g    ) * ASTRF + kk + cc    ];
                a[mt][1] = As_s[(rb + g + 8) * ASTRF + kk + cc    ];
                a[mt][2] = As_s[(rb + g    ) * ASTRF + kk + cc + 4];
                a[mt][3] = As_s[(rb + g + 8) * ASTRF + kk + cc + 4];
            }
            #pragma unroll
            for (int nt = 0; nt < 4; nt++) {
                int nb = wn * 32 + nt * 8;
                b[nt][0] = Bs_s[(kk + cc    ) * BSTRF + nb + g];
                b[nt][1] = Bs_s[(kk + cc + 4) * BSTRF + nb + g];
            }
            #pragma unroll
            for (int mt = 0; mt < 4; mt++)
                #pragma unroll
                for (int nt = 0; nt < 4; nt++)
                    mma_tf32(acc[mt][nt], a[mt], b[nt]);
        }
        cur = (cur + 1) & 3;
    }

    // ---- epilogue ----
    #pragma unroll
    for (int mt = 0; mt < 4; mt++) {
        int r0 = brow + wm * 64 + mt * 16 + g;
        int r1 = r0 + 8;
        float mk0 = 1.f, mk1 = 1.f;
        if (epi == 2) {
            mk0 = mask[r0] ? 1.f : 0.f;
            mk1 = mask[r1] ? 1.f : 0.f;
        }
        #pragma unroll
        for (int nt = 0; nt < 4; nt++) {
            int ncol = bcol + wn * 32 + nt * 8 + cc * 2;
            float2 bv = *(const float2*)(bias + ncol);
            float2 o0, o1;
            o0.x = acc[mt][nt][0] + bv.x; o0.y = acc[mt][nt][1] + bv.y;
            o1.x = acc[mt][nt][2] + bv.x; o1.y = acc[mt][nt][3] + bv.y;
            if (epi == 1) {
                // relu + tf32 round (output feeds next GEMM's A operand)
                o0.x = f2tf_f(fmaxf(o0.x, 0.f)); o0.y = f2tf_f(fmaxf(o0.y, 0.f));
                o1.x = f2tf_f(fmaxf(o1.x, 0.f)); o1.y = f2tf_f(fmaxf(o1.y, 0.f));
            } else if (epi == 2) {
                float2 rv0 = *(const float2*)(res + (size_t)r0 * N + ncol);
                float2 rv1 = *(const float2*)(res + (size_t)r1 * N + ncol);
                o0.x = (o0.x + rv0.x) * mk0; o0.y = (o0.y + rv0.y) * mk0;
                o1.x = (o1.x + rv1.x) * mk1; o1.y = (o1.y + rv1.y) * mk1;
            }
            *(float2*)(C + (size_t)r0 * N + ncol) = o0;
            *(float2*)(C + (size_t)r1 * N + ncol) = o1;
        }
    }
}

// ---------------- Tensor-core flash attention (TF32 mma) ---------------------
#define AQT 64
#define AKT 32
#define QPAD 68
#define VPAD 72
#define PPAD 36

__global__ __launch_bounds__(128)
void attn_mma_kernel(const float* __restrict__ Q, const float* __restrict__ K,
                     const float* __restrict__ V, const int* __restrict__ npm,
                     float* __restrict__ O)
{
    __shared__ unsigned Qs[AQT][QPAD];
    __shared__ unsigned Ks[AKT][QPAD];
    __shared__ unsigned Vs[AKT][VPAD];
    __shared__ unsigned Ps[AQT][PPAD];
    __shared__ float kms[AKT];

    const int b = blockIdx.z, h = blockIdx.y, qt = blockIdx.x;
    const int tid  = threadIdx.x;
    const int lane = tid & 31;
    const int wq   = tid >> 5;
    const int g    = lane >> 2;
    const int cc   = lane & 3;
    const int wr   = wq * 16;

    const float* Qbase = Q + (size_t)(b * SS + qt * AQT) * DD + h * 64;
    #pragma unroll
    for (int i = tid; i < AQT * 16; i += 128) {
        int r = i >> 4, c4 = (i & 15) << 2;
        float4 v4 = *(const float4*)(Qbase + (size_t)r * DD + c4);
        Qs[r][c4+0] = f2tf(v4.x); Qs[r][c4+1] = f2tf(v4.y);
        Qs[r][c4+2] = f2tf(v4.z); Qs[r][c4+3] = f2tf(v4.w);
    }

    float m0 = -1e30f, m1 = -1e30f, l0 = 0.f, l1 = 0.f;
    float o[8][4];
    #pragma unroll
    for (int nt = 0; nt < 8; nt++) {
        o[nt][0] = 0.f; o[nt][1] = 0.f; o[nt][2] = 0.f; o[nt][3] = 0.f;
    }

    for (int kt = 0; kt < SS / AKT; kt++) {
        __syncthreads();
        const float* Kbase = K + (size_t)(b * SS + kt * AKT) * DD + h * 64;
        const float* Vbase = V + (size_t)(b * SS + kt * AKT) * DD + h * 64;
        #pragma unroll
        for (int i = tid; i < AKT * 16; i += 128) {
            int r = i >> 4, c4 = (i & 15) << 2;
            float4 kv = *(const float4*)(Kbase + (size_t)r * DD + c4);
            Ks[r][c4+0] = f2tf(kv.x); Ks[r][c4+1] = f2tf(kv.y);
            Ks[r][c4+2] = f2tf(kv.z); Ks[r][c4+3] = f2tf(kv.w);
            float4 vv = *(const float4*)(Vbase + (size_t)r * DD + c4);
            Vs[r][c4+0] = f2tf(vv.x); Vs[r][c4+1] = f2tf(vv.y);
            Vs[r][c4+2] = f2tf(vv.z); Vs[r][c4+3] = f2tf(vv.w);
        }
        if (tid < AKT) kms[tid] = npm[b * SS + kt * AKT + tid] ? 1.f : 0.f;
        __syncthreads();

        float s[4][4];
        #pragma unroll
        for (int nt = 0; nt < 4; nt++) {
            s[nt][0] = 0.f; s[nt][1] = 0.f; s[nt][2] = 0.f; s[nt][3] = 0.f;
        }
        #pragma unroll
        for (int ks = 0; ks < 8; ks++) {
            unsigned a[4];
            a[0] = Qs[wr + g    ][ks*8 + cc    ];
            a[1] = Qs[wr + g + 8][ks*8 + cc    ];
            a[2] = Qs[wr + g    ][ks*8 + cc + 4];
            a[3] = Qs[wr + g + 8][ks*8 + cc + 4];
            #pragma unroll
            for (int nt = 0; nt < 4; nt++) {
                unsigned bf[2];
                bf[0] = Ks[nt*8 + g][ks*8 + cc    ];
                bf[1] = Ks[nt*8 + g][ks*8 + cc + 4];
                mma_tf32(s[nt], a, bf);
            }
        }

        #pragma unroll
        for (int nt = 0; nt < 4; nt++) {
            float k0 = kms[nt*8 + 2*cc];
            float k1 = kms[nt*8 + 2*cc + 1];
            s[nt][0] = (k0 != 0.f) ? s[nt][0] * ATT_SCALE : -1e9f;
            s[nt][1] = (k1 != 0.f) ? s[nt][1] * ATT_SCALE : -1e9f;
            s[nt][2] = (k0 != 0.f) ? s[nt][2] * ATT_SCALE : -1e9f;
            s[nt][3] = (k1 != 0.f) ? s[nt][3] * ATT_SCALE : -1e9f;
        }

        float tm0 = s[0][0], tm1 = s[0][2];
        #pragma unroll
        for (int nt = 0; nt < 4; nt++) {
            tm0 = fmaxf(tm0, fmaxf(s[nt][0], s[nt][1]));
            tm1 = fmaxf(tm1, fmaxf(s[nt][2], s[nt][3]));
        }
        tm0 = fmaxf(tm0, __shfl_xor_sync(0xffffffffu, tm0, 1));
        tm0 = fmaxf(tm0, __shfl_xor_sync(0xffffffffu, tm0, 2));
        tm1 = fmaxf(tm1, __shfl_xor_sync(0xffffffffu, tm1, 1));
        tm1 = fmaxf(tm1, __shfl_xor_sync(0xffffffffu, tm1, 2));
        float nm0 = fmaxf(m0, tm0), nm1 = fmaxf(m1, tm1);
        float f0 = __expf(m0 - nm0), f1 = __expf(m1 - nm1);

        float sum0 = 0.f, sum1 = 0.f;
        #pragma unroll
        for (int nt = 0; nt < 4; nt++) {
            float p00 = __expf(s[nt][0] - nm0);
            float p01 = __expf(s[nt][1] - nm0);
            float p10 = __expf(s[nt][2] - nm1);
            float p11 = __expf(s[nt][3] - nm1);
            sum0 += p00 + p01;
            sum1 += p10 + p11;
            *(uint2*)&Ps[wr + g    ][nt*8 + 2*cc] = make_uint2(f2tf(p00), f2tf(p01));
            *(uint2*)&Ps[wr + g + 8][nt*8 + 2*cc] = make_uint2(f2tf(p10), f2tf(p11));
        }
        sum0 += __shfl_xor_sync(0xffffffffu, sum0, 1);
        sum0 += __shfl_xor_sync(0xffffffffu, sum0, 2);
        sum1 += __shfl_xor_sync(0xffffffffu, sum1, 1);
        sum1 += __shfl_xor_sync(0xffffffffu, sum1, 2);
        l0 = l0 * f0 + sum0;
        l1 = l1 * f1 + sum1;
        m0 = nm0; m1 = nm1;

        #pragma unroll
        for (int nt = 0; nt < 8; nt++) {
            o[nt][0] *= f0; o[nt][1] *= f0;
            o[nt][2] *= f1; o[nt][3] *= f1;
        }
        __syncwarp();

        #pragma unroll
        for (int ks = 0; ks < 4; ks++) {
            unsigned a[4];
            a[0] = Ps[wr + g    ][ks*8 + cc    ];
            a[1] = Ps[wr + g + 8][ks*8 + cc    ];
            a[2] = Ps[wr + g    ][ks*8 + cc + 4];
            a[3] = Ps[wr + g + 8][ks*8 + cc + 4];
            #pragma unroll
            for (int nt = 0; nt < 8; nt++) {
                unsigned bf[2];
                bf[0] = Vs[ks*8 + cc    ][nt*8 + g];
                bf[1] = Vs[ks*8 + cc + 4][nt*8 + g];
                mma_tf32(o[nt], a, bf);
            }
        }
    }

    // output is only consumed as the Wo-GEMM A operand -> write tf32-rounded
    float i0 = 1.f / l0, i1 = 1.f / l1;
    size_t r0 = (size_t)(b * SS + qt * AQT + wr + g) * DD + h * 64;
    size_t r1 = r0 + (size_t)8 * DD;
    #pragma unroll
    for (int nt = 0; nt < 8; nt++) {
        int ncol = nt * 8 + 2 * cc;
        float2 w0, w1;
        w0.x = f2tf_f(o[nt][0] * i0); w0.y = f2tf_f(o[nt][1] * i0);
        w1.x = f2tf_f(o[nt][2] * i1); w1.y = f2tf_f(o[nt][3] * i1);
        *(float2*)(O + r0 + ncol) = w0;
        *(float2*)(O + r1 + ncol) = w1;
    }
}

// ---------------- host orchestration ----------------
extern "C" void kernel_launch(void* const* d_in, const int* in_sizes, int n_in,
                              void* d_out, int out_size)
{
    const float* embed = (const float*)d_in[0];
    const int*   npm   = (const int*)  d_in[1];
    const float* pe    = (const float*)d_in[2];
    const float* Wq    = (const float*)d_in[3];
    const float* bq    = (const float*)d_in[4];
    const float* Wk    = (const float*)d_in[5];
    const float* bk    = (const float*)d_in[6];
    const float* Wv    = (const float*)d_in[7];
    const float* bv    = (const float*)d_in[8];
    const float* Wo    = (const float*)d_in[9];
    const float* bo    = (const float*)d_in[10];
    const float* ln1g  = (const float*)d_in[11];
    const float* ln1b  = (const float*)d_in[12];
    const float* W1    = (const float*)d_in[13];
    const float* b1    = (const float*)d_in[14];
    const float* W2    = (const float*)d_in[15];
    const float* b2    = (const float*)d_in[16];
    const float* ln2g  = (const float*)d_in[17];
    const float* ln2b  = (const float*)d_in[18];
    const float* lnfg  = (const float*)d_in[19];
    const float* lnfb  = (const float*)d_in[20];

    float *x, *hh, *htf, *x1, *qb, *kb, *vb, *ob, *ffb;
    float *wqc, *wkc, *wvc, *woc, *w1c, *w2c;
    cudaGetSymbolAddress((void**)&x,   g_x);
    cudaGetSymbolAddress((void**)&hh,  g_h);
    cudaGetSymbolAddress((void**)&htf, g_htf);
    cudaGetSymbolAddress((void**)&x1,  g_x1);
    cudaGetSymbolAddress((void**)&qb,  g_q);
    cudaGetSymbolAddress((void**)&kb,  g_k);
    cudaGetSymbolAddress((void**)&vb,  g_v);
    cudaGetSymbolAddress((void**)&ob,  g_o);
    cudaGetSymbolAddress((void**)&ffb, g_ff);
    cudaGetSymbolAddress((void**)&wqc, g_wqc);
    cudaGetSymbolAddress((void**)&wkc, g_wkc);
    cudaGetSymbolAddress((void**)&wvc, g_wvc);
    cudaGetSymbolAddress((void**)&woc, g_woc);
    cudaGetSymbolAddress((void**)&w1c, g_w1c);
    cudaGetSymbolAddress((void**)&w2c, g_w2c);

    cudaFuncSetAttribute(mma_gemm_kernel,
                         cudaFuncAttributeMaxDynamicSharedMemorySize,
                         GEMM_SMEM_BYTES);

    // pre-round weights to tf32
    {
        int nD = LYR * DD * DD / 4, nF = LYR * DD * FF / 4;
        tfconv_kernel<<<(nD + 255) / 256, 256>>>(Wq, wqc, nD);
        tfconv_kernel<<<(nD + 255) / 256, 256>>>(Wk, wkc, nD);
        tfconv_kernel<<<(nD + 255) / 256, 256>>>(Wv, wvc, nD);
        tfconv_kernel<<<(nD + 255) / 256, 256>>>(Wo, woc, nD);
        tfconv_kernel<<<(nF + 255) / 256, 256>>>(W1, w1c, nF);
        tfconv_kernel<<<(nF + 255) / 256, 256>>>(W2, w2c, nF);
    }

    {
        int tot4 = MM * DD / 4;
        add_pe_kernel<<<(tot4 + 255) / 256, 256>>>(embed, pe, x);
    }

    dim3 gD(DD / BN, MM / BM);       // (8, 32)
    dim3 gF(FF / BN, MM / BM);       // (32, 32)
    dim3 gAttn(SS / AQT, HH, BB);    // (16, 16, 4)

    for (int l = 0; l < LYR; l++) {
        const float* wq = wqc + (size_t)l * DD * DD;
        const float* wk = wkc + (size_t)l * DD * DD;
        const float* wv = wvc + (size_t)l * DD * DD;
        const float* wo = woc + (size_t)l * DD * DD;
        const float* w1 = w1c + (size_t)l * DD * FF;
        const float* w2 = w2c + (size_t)l * FF * DD;
        const float* lbq = bq + (size_t)l * DD;
        const float* lbk = bk + (size_t)l * DD;
        const float* lbv = bv + (size_t)l * DD;
        const float* lbo = bo + (size_t)l * DD;
        const float* lb1 = b1 + (size_t)l * FF;
        const float* lb2 = b2 + (size_t)l * DD;

        ln_kernel<<<MM, 256>>>(x, ln1g + (size_t)l * DD, ln1b + (size_t)l * DD, hh, htf);
        mma_gemm_kernel<<<gD, 256, GEMM_SMEM_BYTES>>>(htf, wq, lbq, nullptr, nullptr, qb, MM, DD, DD, 0);
        mma_gemm_kernel<<<gD, 256, GEMM_SMEM_BYTES>>>(htf, wk, lbk, nullptr, nullptr, kb, MM, DD, DD, 0);
        mma_gemm_kernel<<<gD, 256, GEMM_SMEM_BYTES>>>(htf, wv, lbv, nullptr, nullptr, vb, MM, DD, DD, 0);
        attn_mma_kernel<<<gAttn, 128>>>(qb, kb, vb, npm, ob);
        mma_gemm_kernel<<<gD, 256, GEMM_SMEM_BYTES>>>(ob, wo, lbo, hh, npm, x1, MM, DD, DD, 2);
        ln_kernel<<<MM, 256>>>(x1, ln2g + (size_t)l * DD, ln2b + (size_t)l * DD, hh, htf);
        mma_gemm_kernel<<<gF, 256, GEMM_SMEM_BYTES>>>(htf, w1, lb1, nullptr, nullptr, ffb, MM, FF, DD, 1);
        mma_gemm_kernel<<<gD, 256, GEMM_SMEM_BYTES>>>(ffb, w2, lb2, hh, npm, x, MM, DD, FF, 2);
    }

    ln_kernel<<<MM, 256>>>(x, lnfg, lnfb, (float*)d_out, nullptr);
}

// round 7
// speedup vs baseline: 3.9512x; 1.0070x over previous
#include <cuda_runtime.h>
#include <math.h>

// Problem constants
#define LYR 6
#define BB  4
#define SS  1024
#define DD  1024
#define HH  16
#define DKK 64
#define FF  4096
#define MM  (BB*SS)          // 4096 rows
#define ATT_SCALE 0.125f     // 1/sqrt(64)
#define LN_EPS 1e-6f

// ---------------- scratch buffers (device globals; no allocation) -------------
__device__ float g_x [MM*DD];
__device__ float g_h [MM*DD];
__device__ float g_htf[MM*DD];      // tf32-rounded LN output (GEMM A operand)
__device__ float g_x1[MM*DD];
__device__ float g_q [MM*DD];
__device__ float g_k [MM*DD];
__device__ float g_v [MM*DD];
__device__ float g_o [MM*DD];       // attn out, tf32-rounded
__device__ float g_ff[MM*FF];       // relu out, tf32-rounded
// pre-rounded weights (tf32 values stored as fp32)
__device__ float g_wqc[LYR*DD*DD];
__device__ float g_wkc[LYR*DD*DD];
__device__ float g_wvc[LYR*DD*DD];
__device__ float g_woc[LYR*DD*DD];
__device__ float g_w1c[LYR*DD*FF];
__device__ float g_w2c[LYR*FF*DD];

// ---------------- TF32 helpers ----------------
__device__ __forceinline__ unsigned f2tf(float f) {
    unsigned u;
    asm("cvt.rna.tf32.f32 %0, %1;" : "=r"(u) : "f"(f));
    return u;
}
__device__ __forceinline__ float f2tf_f(float f) {
    return __uint_as_float(f2tf(f));
}

__device__ __forceinline__ void mma_tf32(float c[4], const unsigned a[4], const unsigned b[2]) {
    asm volatile("mma.sync.aligned.m16n8k8.row.col.f32.tf32.tf32.f32 "
        "{%0,%1,%2,%3}, {%4,%5,%6,%7}, {%8,%9}, {%0,%1,%2,%3};"
        : "+f"(c[0]), "+f"(c[1]), "+f"(c[2]), "+f"(c[3])
        : "r"(a[0]), "r"(a[1]), "r"(a[2]), "r"(a[3]), "r"(b[0]), "r"(b[1]));
}

__device__ __forceinline__ void ldsm4(unsigned r[4], unsigned addr) {
    asm volatile("ldmatrix.sync.aligned.m8n8.x4.shared.b16 {%0,%1,%2,%3}, [%4];"
        : "=r"(r[0]), "=r"(r[1]), "=r"(r[2]), "=r"(r[3]) : "r"(addr));
}

__device__ __forceinline__ void cp16(unsigned dst, const void* src) {
    asm volatile("cp.async.cg.shared.global [%0], [%1], 16;" :: "r"(dst), "l"(src));
}
__device__ __forceinline__ void cp4(unsigned dst, const void* src) {
    asm volatile("cp.async.ca.shared.global [%0], [%1], 4;" :: "r"(dst), "l"(src));
}
#define CP_COMMIT() asm volatile("cp.async.commit_group;" ::: "memory")
#define CP_WAIT2()  asm volatile("cp.async.wait_group 2;" ::: "memory")

// ---------------- weight pre-rounding: dst = tf32(src) -----------------------
__global__ void tfconv_kernel(const float* __restrict__ src,
                              float* __restrict__ dst, int n4)
{
    int i = blockIdx.x * blockDim.x + threadIdx.x;
    if (i >= n4) return;
    float4 v = ((const float4*)src)[i];
    float4 r;
    r.x = f2tf_f(v.x); r.y = f2tf_f(v.y);
    r.z = f2tf_f(v.z); r.w = f2tf_f(v.w);
    ((float4*)dst)[i] = r;
}

// ---------------- PE add ----------------
__global__ void add_pe_kernel(const float* __restrict__ embed,
                              const float* __restrict__ pe,
                              float* __restrict__ x)
{
    int i = blockIdx.x * blockDim.x + threadIdx.x;
    const int TOT4 = MM * DD / 4;
    if (i >= TOT4) return;
    int pe4 = i % (SS * DD / 4);
    float4 e = ((const float4*)embed)[i];
    float4 p = ((const float4*)pe)[pe4];
    float4 r; r.x = e.x + p.x; r.y = e.y + p.y; r.z = e.z + p.z; r.w = e.w + p.w;
    ((float4*)x)[i] = r;
}

// ---------------- LayerNorm (dual output: fp32 + tf32-rounded) ---------------
__global__ void ln_kernel(const float* __restrict__ x,
                          const float* __restrict__ g,
                          const float* __restrict__ beta,
                          float* __restrict__ y,
                          float* __restrict__ ytf)
{
    __shared__ float shm[32];
    __shared__ float s_mu, s_rstd;
    int row = blockIdx.x;
    int t   = threadIdx.x;
    const float4* xr = (const float4*)(x + (size_t)row * DD);
    float4 v = xr[t];
    float s = v.x + v.y + v.z + v.w;
    #pragma unroll
    for (int o = 16; o; o >>= 1) s += __shfl_xor_sync(0xffffffffu, s, o);
    if ((t & 31) == 0) shm[t >> 5] = s;
    __syncthreads();
    if (t < 32) {
        float tot = (t < 8) ? shm[t] : 0.f;
        #pragma unroll
        for (int o = 4; o; o >>= 1) tot += __shfl_xor_sync(0xffffffffu, tot, o);
        if (t == 0) s_mu = tot * (1.0f / DD);
    }
    __syncthreads();
    float mu = s_mu;
    float d0 = v.x - mu, d1 = v.y - mu, d2 = v.z - mu, d3 = v.w - mu;
    float s2 = d0*d0 + d1*d1 + d2*d2 + d3*d3;
    #pragma unroll
    for (int o = 16; o; o >>= 1) s2 += __shfl_xor_sync(0xffffffffu, s2, o);
    if ((t & 31) == 0) shm[t >> 5] = s2;
    __syncthreads();
    if (t < 32) {
        float tot = (t < 8) ? shm[t] : 0.f;
        #pragma unroll
        for (int o = 4; o; o >>= 1) tot += __shfl_xor_sync(0xffffffffu, tot, o);
        if (t == 0) s_rstd = rsqrtf(tot * (1.0f / DD) + LN_EPS);
    }
    __syncthreads();
    float rstd = s_rstd;
    float4 gg = ((const float4*)g)[t];
    float4 bb = ((const float4*)beta)[t];
    float4 out;
    out.x = d0 * rstd * gg.x + bb.x;
    out.y = d1 * rstd * gg.y + bb.y;
    out.z = d2 * rstd * gg.z + bb.z;
    out.w = d3 * rstd * gg.w + bb.w;
    ((float4*)(y + (size_t)row * DD))[t] = out;
    if (ytf) {
        float4 rt;
        rt.x = f2tf_f(out.x); rt.y = f2tf_f(out.y);
        rt.z = f2tf_f(out.z); rt.w = f2tf_f(out.w);
        ((float4*)(ytf + (size_t)row * DD))[t] = rt;
    }
}

// ---------------- TF32 GEMM, 4-stage cp.async pipeline -----------------------
// Inputs A and W must already be tf32-rounded fp32 values.
// A frags: ldmatrix.x4. B frags: LDS.128 via n-permuted smem layout.
#define BM 128
#define BN 128
#define BK 16
#define STAGES 4
#define ASTRF 20
#define BSTRF 136
#define A_STG (BM*ASTRF)
#define B_STG (BK*BSTRF)
#define GEMM_SMEM_BYTES (STAGES * (A_STG + B_STG) * 4)   // 75776

__global__ __launch_bounds__(256, 2)
void mma_gemm_kernel(const float* __restrict__ A, const float* __restrict__ W,
                     const float* __restrict__ bias, const float* __restrict__ res,
                     const int* __restrict__ mask, float* __restrict__ C,
                     int M, int N, int K, int epi)
{
    extern __shared__ float smemf[];
    float* Asm = smemf;
    float* Bsm = smemf + STAGES * A_STG;
    const unsigned* Bsu = (const unsigned*)Bsm;
    const unsigned a_u = (unsigned)__cvta_generic_to_shared(Asm);
    const unsigned b_u = (unsigned)__cvta_generic_to_shared(Bsm);

    const int tid  = threadIdx.x;
    const int lane = tid & 31;
    const int wrp  = tid >> 5;
    const int wm   = wrp >> 2;
    const int wn   = wrp & 3;
    const int g    = lane >> 2;
    const int cc   = lane & 3;
    const int l15  = lane & 15;
    const int lhi  = lane >> 4;

    const int brow = blockIdx.y * BM;
    const int bcol = blockIdx.x * BN;

    // A staging: thread copies 32B: row tid>>1, col (tid&1)*8
    const int a_r = tid >> 1, a_c = (tid & 1) * 8;
    // B staging: thread copies 8 x 4B: n = tid&127 (fixed), k = (tid>>7) + 2j
    const int b_n  = tid & 127;
    const int b_k0 = tid >> 7;
    const int b_cp = (b_n & ~31) + ((b_n & 7) << 2) + ((b_n & 31) >> 3);  // permuted col

    const float* Ag = A + (size_t)(brow + a_r) * K + a_c;
    const float* Wg = W + bcol + b_n;

    const int NK = K / BK;

    auto load_stage = [&](int s, int kt) {
        const float* ag = Ag + kt * BK;
        unsigned ad = a_u + (unsigned)((s * A_STG + a_r * ASTRF + a_c) * 4);
        cp16(ad, ag); cp16(ad + 16, ag + 4);
        const float* bg = Wg + (size_t)(kt * BK + b_k0) * N;
        unsigned bd = b_u + (unsigned)((s * B_STG + b_k0 * BSTRF + b_cp) * 4);
        #pragma unroll
        for (int j = 0; j < 8; j++) {
            cp4(bd, bg);
            bd += 2 * BSTRF * 4;
            bg += 2 * N;
        }
    };

    float acc[4][4][4];
    #pragma unroll
    for (int i = 0; i < 4; i++)
        #pragma unroll
        for (int j = 0; j < 4; j++) {
            acc[i][j][0] = 0.f; acc[i][j][1] = 0.f;
            acc[i][j][2] = 0.f; acc[i][j][3] = 0.f;
        }

    load_stage(0, 0); CP_COMMIT();
    load_stage(1, 1); CP_COMMIT();
    load_stage(2, 2); CP_COMMIT();

    // per-thread ldmatrix base (within a stage): row wm*64 + l15, col lhi*4
    const unsigned a_frag_off = (unsigned)(((wm * 64 + l15) * ASTRF + lhi * 4) * 4);

    int cur = 0;
    for (int kt = 0; kt < NK; kt++) {
        CP_WAIT2();
        __syncthreads();

        if (kt + 3 < NK) load_stage((kt + 3) & 3, kt + 3);
        CP_COMMIT();

        const unsigned abase = a_u + (unsigned)(cur * A_STG * 4) + a_frag_off;
        const unsigned* Bs_s = Bsu + cur * B_STG;

        #pragma unroll
        for (int ks = 0; ks < 2; ks++) {
            unsigned a[4][4];
            #pragma unroll
            for (int mt = 0; mt < 4; mt++)
                ldsm4(a[mt], abase + (unsigned)(mt * 16 * ASTRF * 4 + ks * 32));

            unsigned b0[4], b1[4];
            const unsigned* br0 = Bs_s + (ks * 8 + cc) * BSTRF + wn * 32 + 4 * g;
            *(uint4*)b0 = *(const uint4*)br0;
            *(uint4*)b1 = *(const uint4*)(br0 + 4 * BSTRF);

            #pragma unroll
            for (int mt = 0; mt < 4; mt++)
                #pragma unroll
                for (int nt = 0; nt < 4; nt++) {
                    unsigned bf[2] = { b0[nt], b1[nt] };
                    mma_tf32(acc[mt][nt], a[mt], bf);
                }
        }
        cur = (cur + 1) & 3;
    }

    // ---- epilogue ----
    #pragma unroll
    for (int mt = 0; mt < 4; mt++) {
        int r0 = brow + wm * 64 + mt * 16 + g;
        int r1 = r0 + 8;
        float mk0 = 1.f, mk1 = 1.f;
        if (epi == 2) {
            mk0 = mask[r0] ? 1.f : 0.f;
            mk1 = mask[r1] ? 1.f : 0.f;
        }
        #pragma unroll
        for (int nt = 0; nt < 4; nt++) {
            int ncol = bcol + wn * 32 + nt * 8 + cc * 2;
            float2 bv = *(const float2*)(bias + ncol);
            float2 o0, o1;
            o0.x = acc[mt][nt][0] + bv.x; o0.y = acc[mt][nt][1] + bv.y;
            o1.x = acc[mt][nt][2] + bv.x; o1.y = acc[mt][nt][3] + bv.y;
            if (epi == 1) {
                o0.x = f2tf_f(fmaxf(o0.x, 0.f)); o0.y = f2tf_f(fmaxf(o0.y, 0.f));
                o1.x = f2tf_f(fmaxf(o1.x, 0.f)); o1.y = f2tf_f(fmaxf(o1.y, 0.f));
            } else if (epi == 2) {
                float2 rv0 = *(const float2*)(res + (size_t)r0 * N + ncol);
                float2 rv1 = *(const float2*)(res + (size_t)r1 * N + ncol);
                o0.x = (o0.x + rv0.x) * mk0; o0.y = (o0.y + rv0.y) * mk0;
                o1.x = (o1.x + rv1.x) * mk1; o1.y = (o1.y + rv1.y) * mk1;
            }
            *(float2*)(C + (size_t)r0 * N + ncol) = o0;
            *(float2*)(C + (size_t)r1 * N + ncol) = o1;
        }
    }
}

// ---------------- Tensor-core flash attention (TF32 mma) ---------------------
#define AQT 64
#define AKT 32
#define QPAD 68
#define VPAD 72
#define PPAD 36

__global__ __launch_bounds__(128)
void attn_mma_kernel(const float* __restrict__ Q, const float* __restrict__ K,
                     const float* __restrict__ V, const int* __restrict__ npm,
                     float* __restrict__ O)
{
    __shared__ unsigned Qs[AQT][QPAD];
    __shared__ unsigned Ks[AKT][QPAD];
    __shared__ unsigned Vs[AKT][VPAD];
    __shared__ unsigned Ps[AQT][PPAD];
    __shared__ float kms[AKT];

    const int b = blockIdx.z, h = blockIdx.y, qt = blockIdx.x;
    const int tid  = threadIdx.x;
    const int lane = tid & 31;
    const int wq   = tid >> 5;
    const int g    = lane >> 2;
    const int cc   = lane & 3;
    const int wr   = wq * 16;

    const float* Qbase = Q + (size_t)(b * SS + qt * AQT) * DD + h * 64;
    #pragma unroll
    for (int i = tid; i < AQT * 16; i += 128) {
        int r = i >> 4, c4 = (i & 15) << 2;
        float4 v4 = *(const float4*)(Qbase + (size_t)r * DD + c4);
        Qs[r][c4+0] = f2tf(v4.x); Qs[r][c4+1] = f2tf(v4.y);
        Qs[r][c4+2] = f2tf(v4.z); Qs[r][c4+3] = f2tf(v4.w);
    }

    float m0 = -1e30f, m1 = -1e30f, l0 = 0.f, l1 = 0.f;
    float o[8][4];
    #pragma unroll
    for (int nt = 0; nt < 8; nt++) {
        o[nt][0] = 0.f; o[nt][1] = 0.f; o[nt][2] = 0.f; o[nt][3] = 0.f;
    }

    for (int kt = 0; kt < SS / AKT; kt++) {
        __syncthreads();
        const float* Kbase = K + (size_t)(b * SS + kt * AKT) * DD + h * 64;
        const float* Vbase = V + (size_t)(b * SS + kt * AKT) * DD + h * 64;
        #pragma unroll
        for (int i = tid; i < AKT * 16; i += 128) {
            int r = i >> 4, c4 = (i & 15) << 2;
            float4 kv = *(const float4*)(Kbase + (size_t)r * DD + c4);
            Ks[r][c4+0] = f2tf(kv.x); Ks[r][c4+1] = f2tf(kv.y);
            Ks[r][c4+2] = f2tf(kv.z); Ks[r][c4+3] = f2tf(kv.w);
            float4 vv = *(const float4*)(Vbase + (size_t)r * DD + c4);
            Vs[r][c4+0] = f2tf(vv.x); Vs[r][c4+1] = f2tf(vv.y);
            Vs[r][c4+2] = f2tf(vv.z); Vs[r][c4+3] = f2tf(vv.w);
        }
        if (tid < AKT) kms[tid] = npm[b * SS + kt * AKT + tid] ? 1.f : 0.f;
        __syncthreads();

        float s[4][4];
        #pragma unroll
        for (int nt = 0; nt < 4; nt++) {
            s[nt][0] = 0.f; s[nt][1] = 0.f; s[nt][2] = 0.f; s[nt][3] = 0.f;
        }
        #pragma unroll
        for (int ks = 0; ks < 8; ks++) {
            unsigned a[4];
            a[0] = Qs[wr + g    ][ks*8 + cc    ];
            a[1] = Qs[wr + g + 8][ks*8 + cc    ];
            a[2] = Qs[wr + g    ][ks*8 + cc + 4];
            a[3] = Qs[wr + g + 8][ks*8 + cc + 4];
            #pragma unroll
            for (int nt = 0; nt < 4; nt++) {
                unsigned bf[2];
                bf[0] = Ks[nt*8 + g][ks*8 + cc    ];
                bf[1] = Ks[nt*8 + g][ks*8 + cc + 4];
                mma_tf32(s[nt], a, bf);
            }
        }

        #pragma unroll
        for (int nt = 0; nt < 4; nt++) {
            float k0 = kms[nt*8 + 2*cc];
            float k1 = kms[nt*8 + 2*cc + 1];
            s[nt][0] = (k0 != 0.f) ? s[nt][0] * ATT_SCALE : -1e9f;
            s[nt][1] = (k1 != 0.f) ? s[nt][1] * ATT_SCALE : -1e9f;
            s[nt][2] = (k0 != 0.f) ? s[nt][2] * ATT_SCALE : -1e9f;
            s[nt][3] = (k1 != 0.f) ? s[nt][3] * ATT_SCALE : -1e9f;
        }

        float tm0 = s[0][0], tm1 = s[0][2];
        #pragma unroll
        for (int nt = 0; nt < 4; nt++) {
            tm0 = fmaxf(tm0, fmaxf(s[nt][0], s[nt][1]));
            tm1 = fmaxf(tm1, fmaxf(s[nt][2], s[nt][3]));
        }
        tm0 = fmaxf(tm0, __shfl_xor_sync(0xffffffffu, tm0, 1));
        tm0 = fmaxf(tm0, __shfl_xor_sync(0xffffffffu, tm0, 2));
        tm1 = fmaxf(tm1, __shfl_xor_sync(0xffffffffu, tm1, 1));
        tm1 = fmaxf(tm1, __shfl_xor_sync(0xffffffffu, tm1, 2));
        float nm0 = fmaxf(m0, tm0), nm1 = fmaxf(m1, tm1);
        float f0 = __expf(m0 - nm0), f1 = __expf(m1 - nm1);

        float sum0 = 0.f, sum1 = 0.f;
        #pragma unroll
        for (int nt = 0; nt < 4; nt++) {
            float p00 = __expf(s[nt][0] - nm0);
            float p01 = __expf(s[nt][1] - nm0);
            float p10 = __expf(s[nt][2] - nm1);
            float p11 = __expf(s[nt][3] - nm1);
            sum0 += p00 + p01;
            sum1 += p10 + p11;
            *(uint2*)&Ps[wr + g    ][nt*8 + 2*cc] = make_uint2(f2tf(p00), f2tf(p01));
            *(uint2*)&Ps[wr + g + 8][nt*8 + 2*cc] = make_uint2(f2tf(p10), f2tf(p11));
        }
        sum0 += __shfl_xor_sync(0xffffffffu, sum0, 1);
        sum0 += __shfl_xor_sync(0xffffffffu, sum0, 2);
        sum1 += __shfl_xor_sync(0xffffffffu, sum1, 1);
        sum1 += __shfl_xor_sync(0xffffffffu, sum1, 2);
        l0 = l0 * f0 + sum0;
        l1 = l1 * f1 + sum1;
        m0 = nm0; m1 = nm1;

        #pragma unroll
        for (int nt = 0; nt < 8; nt++) {
            o[nt][0] *= f0; o[nt][1] *= f0;
            o[nt][2] *= f1; o[nt][3] *= f1;
        }
        __syncwarp();

        #pragma unroll
        for (int ks = 0; ks < 4; ks++) {
            unsigned a[4];
            a[0] = Ps[wr + g    ][ks*8 + cc    ];
            a[1] = Ps[wr + g + 8][ks*8 + cc    ];
            a[2] = Ps[wr + g    ][ks*8 + cc + 4];
            a[3] = Ps[wr + g + 8][ks*8 + cc + 4];
            #pragma unroll
            for (int nt = 0; nt < 8; nt++) {
                unsigned bf[2];
                bf[0] = Vs[ks*8 + cc    ][nt*8 + g];
                bf[1] = Vs[ks*8 + cc + 4][nt*8 + g];
                mma_tf32(o[nt], a, bf);
            }
        }
    }

    float i0 = 1.f / l0, i1 = 1.f / l1;
    size_t r0 = (size_t)(b * SS + qt * AQT + wr + g) * DD + h * 64;
    size_t r1 = r0 + (size_t)8 * DD;
    #pragma unroll
    for (int nt = 0; nt < 8; nt++) {
        int ncol = nt * 8 + 2 * cc;
        float2 w0, w1;
        w0.x = f2tf_f(o[nt][0] * i0); w0.y = f2tf_f(o[nt][1] * i0);
        w1.x = f2tf_f(o[nt][2] * i1); w1.y = f2tf_f(o[nt][3] * i1);
        *(float2*)(O + r0 + ncol) = w0;
        *(float2*)(O + r1 + ncol) = w1;
    }
}

// ---------------- host orchestration ----------------
extern "C" void kernel_launch(void* const* d_in, const int* in_sizes, int n_in,
                              void* d_out, int out_size)
{
    const float* embed = (const float*)d_in[0];
    const int*   npm   = (const int*)  d_in[1];
    const float* pe    = (const float*)d_in[2];
    const float* Wq    = (const float*)d_in[3];
    const float* bq    = (const float*)d_in[4];
    const float* Wk    = (const float*)d_in[5];
    const float* bk    = (const float*)d_in[6];
    const float* Wv    = (const float*)d_in[7];
    const float* bv    = (const float*)d_in[8];
    const float* Wo    = (const float*)d_in[9];
    const float* bo    = (const float*)d_in[10];
    const float* ln1g  = (const float*)d_in[11];
    const float* ln1b  = (const float*)d_in[12];
    const float* W1    = (const float*)d_in[13];
    const float* b1    = (const float*)d_in[14];
    const float* W2    = (const float*)d_in[15];
    const float* b2    = (const float*)d_in[16];
    const float* ln2g  = (const float*)d_in[17];
    const float* ln2b  = (const float*)d_in[18];
    const float* lnfg  = (const float*)d_in[19];
    const float* lnfb  = (const float*)d_in[20];

    float *x, *hh, *htf, *x1, *qb, *kb, *vb, *ob, *ffb;
    float *wqc, *wkc, *wvc, *woc, *w1c, *w2c;
    cudaGetSymbolAddress((void**)&x,   g_x);
    cudaGetSymbolAddress((void**)&hh,  g_h);
    cudaGetSymbolAddress((void**)&htf, g_htf);
    cudaGetSymbolAddress((void**)&x1,  g_x1);
    cudaGetSymbolAddress((void**)&qb,  g_q);
    cudaGetSymbolAddress((void**)&kb,  g_k);
    cudaGetSymbolAddress((void**)&vb,  g_v);
    cudaGetSymbolAddress((void**)&ob,  g_o);
    cudaGetSymbolAddress((void**)&ffb, g_ff);
    cudaGetSymbolAddress((void**)&wqc, g_wqc);
    cudaGetSymbolAddress((void**)&wkc, g_wkc);
    cudaGetSymbolAddress((void**)&wvc, g_wvc);
    cudaGetSymbolAddress((void**)&woc, g_woc);
    cudaGetSymbolAddress((void**)&w1c, g_w1c);
    cudaGetSymbolAddress((void**)&w2c, g_w2c);

    cudaFuncSetAttribute(mma_gemm_kernel,
                         cudaFuncAttributeMaxDynamicSharedMemorySize,
                         GEMM_SMEM_BYTES);

    // pre-round weights to tf32
    {
        int nD = LYR * DD * DD / 4, nF = LYR * DD * FF / 4;
        tfconv_kernel<<<(nD + 255) / 256, 256>>>(Wq, wqc, nD);
        tfconv_kernel<<<(nD + 255) / 256, 256>>>(Wk, wkc, nD);
        tfconv_kernel<<<(nD + 255) / 256, 256>>>(Wv, wvc, nD);
        tfconv_kernel<<<(nD + 255) / 256, 256>>>(Wo, woc, nD);
        tfconv_kernel<<<(nF + 255) / 256, 256>>>(W1, w1c, nF);
        tfconv_kernel<<<(nF + 255) / 256, 256>>>(W2, w2c, nF);
    }

    {
        int tot4 = MM * DD / 4;
        add_pe_kernel<<<(tot4 + 255) / 256, 256>>>(embed, pe, x);
    }

    dim3 gD(DD / BN, MM / BM);       // (8, 32)
    dim3 gF(FF / BN, MM / BM);       // (32, 32)
    dim3 gAttn(SS / AQT, HH, BB);    // (16, 16, 4)

    for (int l = 0; l < LYR; l++) {
        const float* wq = wqc + (size_t)l * DD * DD;
        const float* wk = wkc + (size_t)l * DD * DD;
        const float* wv = wvc + (size_t)l * DD * DD;
        const float* wo = woc + (size_t)l * DD * DD;
        const float* w1 = w1c + (size_t)l * DD * FF;
        const float* w2 = w2c + (size_t)l * FF * DD;
        const float* lbq = bq + (size_t)l * DD;
        const float* lbk = bk + (size_t)l * DD;
        const float* lbv = bv + (size_t)l * DD;
        const float* lbo = bo + (size_t)l * DD;
        const float* lb1 = b1 + (size_t)l * FF;
        const float* lb2 = b2 + (size_t)l * DD;

        ln_kernel<<<MM, 256>>>(x, ln1g + (size_t)l * DD, ln1b + (size_t)l * DD, hh, htf);
        mma_gemm_kernel<<<gD, 256, GEMM_SMEM_BYTES>>>(htf, wq, lbq, nullptr, nullptr, qb, MM, DD, DD, 0);
        mma_gemm_kernel<<<gD, 256, GEMM_SMEM_BYTES>>>(htf, wk, lbk, nullptr, nullptr, kb, MM, DD, DD, 0);
        mma_gemm_kernel<<<gD, 256, GEMM_SMEM_BYTES>>>(htf, wv, lbv, nullptr, nullptr, vb, MM, DD, DD, 0);
        attn_mma_kernel<<<gAttn, 128>>>(qb, kb, vb, npm, ob);
        mma_gemm_kernel<<<gD, 256, GEMM_SMEM_BYTES>>>(ob, wo, lbo, hh, npm, x1, MM, DD, DD, 2);
        ln_kernel<<<MM, 256>>>(x1, ln2g + (size_t)l * DD, ln2b + (size_t)l * DD, hh, htf);
        mma_gemm_kernel<<<gF, 256, GEMM_SMEM_BYTES>>>(htf, w1, lb1, nullptr, nullptr, ffb, MM, FF, DD, 1);
        mma_gemm_kernel<<<gD, 256, GEMM_SMEM_BYTES>>>(ffb, w2, lb2, hh, npm, x, MM, DD, FF, 2);
    }

    ln_kernel<<<MM, 256>>>(x, lnfg, lnfb, (float*)d_out, nullptr);
}

// round 9
// speedup vs baseline: 4.1319x; 1.0457x over previous
#include <cuda_runtime.h>
#include <math.h>
#include <stdint.h>

// Problem constants
#define LYR 6
#define BB  4
#define SS  1024
#define DD  1024
#define HH  16
#define DKK 64
#define FF  4096
#define MM  (BB*SS)          // 4096 rows
#define ATT_SCALE 0.125f     // 1/sqrt(64)
#define LN_EPS 1e-6f

// ---------------- scratch buffers (device globals; no allocation) -------------
__device__ float g_x [MM*DD];
__device__ float g_h [MM*DD];
__device__ float g_htf[MM*DD];      // tf32-rounded LN output (GEMM A operand)
__device__ float g_x1[MM*DD];
__device__ float g_q [MM*DD];
__device__ float g_k [MM*DD];
__device__ float g_v [MM*DD];
__device__ float g_o [MM*DD];       // attn out, tf32-rounded
__device__ float g_ff[MM*FF];       // relu out, tf32-rounded
// pre-rounded + TRANSPOSED weights: Bt[n][k] = tf32(W[k][n])
__device__ float g_wqc[LYR*DD*DD];
__device__ float g_wkc[LYR*DD*DD];
__device__ float g_wvc[LYR*DD*DD];
__device__ float g_woc[LYR*DD*DD];
__device__ float g_w1c[LYR*DD*FF];
__device__ float g_w2c[LYR*FF*DD];

// ---------------- TF32 helpers ----------------
__device__ __forceinline__ unsigned f2tf(float f) {
    unsigned u;
    asm("cvt.rna.tf32.f32 %0, %1;" : "=r"(u) : "f"(f));
    return u;
}
__device__ __forceinline__ float f2tf_f(float f) {
    return __uint_as_float(f2tf(f));
}

__device__ __forceinline__ void mma_tf32(float c[4], const unsigned a[4], const unsigned b[2]) {
    asm volatile("mma.sync.aligned.m16n8k8.row.col.f32.tf32.tf32.f32 "
        "{%0,%1,%2,%3}, {%4,%5,%6,%7}, {%8,%9}, {%0,%1,%2,%3};"
        : "+f"(c[0]), "+f"(c[1]), "+f"(c[2]), "+f"(c[3])
        : "r"(a[0]), "r"(a[1]), "r"(a[2]), "r"(a[3]), "r"(b[0]), "r"(b[1]));
}

__device__ __forceinline__ void ldsm4(unsigned r[4], unsigned addr) {
    asm volatile("ldmatrix.sync.aligned.m8n8.x4.shared.b16 {%0,%1,%2,%3}, [%4];"
        : "=r"(r[0]), "=r"(r[1]), "=r"(r[2]), "=r"(r[3]) : "r"(addr));
}

__device__ __forceinline__ void cp16(unsigned dst, const void* src) {
    asm volatile("cp.async.cg.shared.global [%0], [%1], 16;" :: "r"(dst), "l"(src));
}
#define CP_COMMIT() asm volatile("cp.async.commit_group;" ::: "memory")
#define CP_WAIT2()  asm volatile("cp.async.wait_group 2;" ::: "memory")

// ---------------- weight prep: dst[n][k] = tf32(src[k][n]) -------------------
__global__ void tfconv_t_kernel(const float* __restrict__ src,
                                float* __restrict__ dst, int K, int N)
{
    __shared__ float t[32][33];
    int l = blockIdx.z;
    const float* s = src + (size_t)l * K * N;
    float* d = dst + (size_t)l * K * N;
    int n0 = blockIdx.x * 32, k0 = blockIdx.y * 32;
    int tx = threadIdx.x, ty = threadIdx.y;   // 32 x 8
    #pragma unroll
    for (int i = 0; i < 32; i += 8)
        t[ty + i][tx] = s[(size_t)(k0 + ty + i) * N + n0 + tx];
    __syncthreads();
    #pragma unroll
    for (int i = 0; i < 32; i += 8)
        d[(size_t)(n0 + ty + i) * K + k0 + tx] = f2tf_f(t[tx][ty + i]);
}

// ---------------- PE add ----------------
__global__ void add_pe_kernel(const float* __restrict__ embed,
                              const float* __restrict__ pe,
                              float* __restrict__ x)
{
    int i = blockIdx.x * blockDim.x + threadIdx.x;
    const int TOT4 = MM * DD / 4;
    if (i >= TOT4) return;
    int pe4 = i % (SS * DD / 4);
    float4 e = ((const float4*)embed)[i];
    float4 p = ((const float4*)pe)[pe4];
    float4 r; r.x = e.x + p.x; r.y = e.y + p.y; r.z = e.z + p.z; r.w = e.w + p.w;
    ((float4*)x)[i] = r;
}

// ---------------- LayerNorm (dual output: fp32 + tf32-rounded) ---------------
__global__ void ln_kernel(const float* __restrict__ x,
                          const float* __restrict__ g,
                          const float* __restrict__ beta,
                          float* __restrict__ y,
                          float* __restrict__ ytf)
{
    __shared__ float shm[32];
    __shared__ float s_mu, s_rstd;
    int row = blockIdx.x;
    int t   = threadIdx.x;
    const float4* xr = (const float4*)(x + (size_t)row * DD);
    float4 v = xr[t];
    float s = v.x + v.y + v.z + v.w;
    #pragma unroll
    for (int o = 16; o; o >>= 1) s += __shfl_xor_sync(0xffffffffu, s, o);
    if ((t & 31) == 0) shm[t >> 5] = s;
    __syncthreads();
    if (t < 32) {
        float tot = (t < 8) ? shm[t] : 0.f;
        #pragma unroll
        for (int o = 4; o; o >>= 1) tot += __shfl_xor_sync(0xffffffffu, tot, o);
        if (t == 0) s_mu = tot * (1.0f / DD);
    }
    __syncthreads();
    float mu = s_mu;
    float d0 = v.x - mu, d1 = v.y - mu, d2 = v.z - mu, d3 = v.w - mu;
    float s2 = d0*d0 + d1*d1 + d2*d2 + d3*d3;
    #pragma unroll
    for (int o = 16; o; o >>= 1) s2 += __shfl_xor_sync(0xffffffffu, s2, o);
    if ((t & 31) == 0) shm[t >> 5] = s2;
    __syncthreads();
    if (t < 32) {
        float tot = (t < 8) ? shm[t] : 0.f;
        #pragma unroll
        for (int o = 4; o; o >>= 1) tot += __shfl_xor_sync(0xffffffffu, tot, o);
        if (t == 0) s_rstd = rsqrtf(tot * (1.0f / DD) + LN_EPS);
    }
    __syncthreads();
    float rstd = s_rstd;
    float4 gg = ((const float4*)g)[t];
    float4 bb = ((const float4*)beta)[t];
    float4 out;
    out.x = d0 * rstd * gg.x + bb.x;
    out.y = d1 * rstd * gg.y + bb.y;
    out.z = d2 * rstd * gg.z + bb.z;
    out.w = d3 * rstd * gg.w + bb.w;
    ((float4*)(y + (size_t)row * DD))[t] = out;
    if (ytf) {
        float4 rt;
        rt.x = f2tf_f(out.x); rt.y = f2tf_f(out.y);
        rt.z = f2tf_f(out.z); rt.w = f2tf_f(out.w);
        ((float4*)(ytf + (size_t)row * DD))[t] = rt;
    }
}

// ---------------- TF32 GEMM (mma.sync), 4-stage cp.async ---------------------
// C[M,N] = A[M,K] @ Bt[N,K]^T  (+bias) (+relu->tf32) (+residual,*mask)
// Both operands K-major in smem, pad 20; all fragments via ldmatrix.x4.
#define BM 128
#define BN 128
#define BK 16
#define STAGES 4
#define STRF 20
#define T_STG (BM*STRF)              // per-operand floats per stage
#define GEMM_SMEM_BYTES (STAGES * 2 * T_STG * 4)   // 81920

__global__ __launch_bounds__(256, 2)
void mma_gemm_kernel(const float* __restrict__ A, const float* __restrict__ Bt,
                     const float* __restrict__ bias, const float* __restrict__ res,
                     const int* __restrict__ mask, float* __restrict__ C,
                     int M, int N, int K, int epi)
{
    extern __shared__ float smemf[];
    float* Asm = smemf;                       // [STAGES][BM][STRF]
    float* Bsm = smemf + STAGES * T_STG;      // [STAGES][BN][STRF]
    const unsigned a_u = (unsigned)__cvta_generic_to_shared(Asm);
    const unsigned b_u = (unsigned)__cvta_generic_to_shared(Bsm);

    const int tid  = threadIdx.x;
    const int lane = tid & 31;
    const int wrp  = tid >> 5;
    const int wm   = wrp >> 2;       // 0..1 -> 64 rows
    const int wn   = wrp & 3;        // 0..3 -> 32 cols
    const int l15  = lane & 15;
    const int lhi  = lane >> 4;
    const int g    = lane >> 2;
    const int cc   = lane & 3;

    const int brow = blockIdx.y * BM;
    const int bcol = blockIdx.x * BN;

    // staging: thread copies 32B of A and 32B of B: row tid>>1, col (tid&1)*8
    const int s_r = tid >> 1, s_c = (tid & 1) * 8;
    const float* Ag = A  + (size_t)(brow + s_r) * K + s_c;
    const float* Bg = Bt + (size_t)(bcol + s_r) * K + s_c;

    const int NK = K / BK;

    auto load_stage = [&](int s, int kt) {
        const float* ag = Ag + kt * BK;
        const float* bg = Bg + kt * BK;
        unsigned d = (unsigned)((s * T_STG + s_r * STRF + s_c) * 4);
        cp16(a_u + d, ag); cp16(a_u + d + 16, ag + 4);
        cp16(b_u + d, bg); cp16(b_u + d + 16, bg + 4);
    };

    float acc[4][4][4];
    #pragma unroll
    for (int i = 0; i < 4; i++)
        #pragma unroll
        for (int j = 0; j < 4; j++) {
            acc[i][j][0] = 0.f; acc[i][j][1] = 0.f;
            acc[i][j][2] = 0.f; acc[i][j][3] = 0.f;
        }

    load_stage(0, 0); CP_COMMIT();
    load_stage(1, 1); CP_COMMIT();
    load_stage(2, 2); CP_COMMIT();

    // per-thread ldmatrix bases (within a stage)
    const unsigned a_frag_off = (unsigned)(((wm * 64 + l15) * STRF + lhi * 4) * 4);
    const unsigned b_frag_off = (unsigned)(((wn * 32 + l15) * STRF + lhi * 4) * 4);

    int cur = 0;
    for (int kt = 0; kt < NK; kt++) {
        CP_WAIT2();
        __syncthreads();

        if (kt + 3 < NK) load_stage((kt + 3) & 3, kt + 3);
        CP_COMMIT();

        const unsigned abase = a_u + (unsigned)(cur * T_STG * 4) + a_frag_off;
        const unsigned bbase = b_u + (unsigned)(cur * T_STG * 4) + b_frag_off;

        #pragma unroll
        for (int ks = 0; ks < 2; ks++) {
            unsigned a[4][4], b[2][4];
            #pragma unroll
            for (int mt = 0; mt < 4; mt++)
                ldsm4(a[mt], abase + (unsigned)(mt * 16 * STRF * 4 + ks * 32));
            #pragma unroll
            for (int bt = 0; bt < 2; bt++)
                ldsm4(b[bt], bbase + (unsigned)(bt * 16 * STRF * 4 + ks * 32));

            #pragma unroll
            for (int mt = 0; mt < 4; mt++) {
                {   unsigned bf[2] = { b[0][0], b[0][2] };  // nt=0: rows +g
                    mma_tf32(acc[mt][0], a[mt], bf); }
                {   unsigned bf[2] = { b[0][1], b[0][3] };  // nt=1: rows +8+g
                    mma_tf32(acc[mt][1], a[mt], bf); }
                {   unsigned bf[2] = { b[1][0], b[1][2] };  // nt=2
                    mma_tf32(acc[mt][2], a[mt], bf); }
                {   unsigned bf[2] = { b[1][1], b[1][3] };  // nt=3
                    mma_tf32(acc[mt][3], a[mt], bf); }
            }
        }
        cur = (cur + 1) & 3;
    }

    // ---- epilogue ----
    #pragma unroll
    for (int mt = 0; mt < 4; mt++) {
        int r0 = brow + wm * 64 + mt * 16 + g;
        int r1 = r0 + 8;
        float mk0 = 1.f, mk1 = 1.f;
        if (epi == 2) {
            mk0 = mask[r0] ? 1.f : 0.f;
            mk1 = mask[r1] ? 1.f : 0.f;
        }
        #pragma unroll
        for (int nt = 0; nt < 4; nt++) {
            int ncol = bcol + wn * 32 + nt * 8 + cc * 2;
            float2 bv = *(const float2*)(bias + ncol);
            float2 o0, o1;
            o0.x = acc[mt][nt][0] + bv.x; o0.y = acc[mt][nt][1] + bv.y;
            o1.x = acc[mt][nt][2] + bv.x; o1.y = acc[mt][nt][3] + bv.y;
            if (epi == 1) {
                o0.x = f2tf_f(fmaxf(o0.x, 0.f)); o0.y = f2tf_f(fmaxf(o0.y, 0.f));
                o1.x = f2tf_f(fmaxf(o1.x, 0.f)); o1.y = f2tf_f(fmaxf(o1.y, 0.f));
            } else if (epi == 2) {
                float2 rv0 = *(const float2*)(res + (size_t)r0 * N + ncol);
                float2 rv1 = *(const float2*)(res + (size_t)r1 * N + ncol);
                o0.x = (o0.x + rv0.x) * mk0; o0.y = (o0.y + rv0.y) * mk0;
                o1.x = (o1.x + rv1.x) * mk1; o1.y = (o1.y + rv1.y) * mk1;
            }
            *(float2*)(C + (size_t)r0 * N + ncol) = o0;
            *(float2*)(C + (size_t)r1 * N + ncol) = o1;
        }
    }
}

// ---------------- Tensor-core flash attention (TF32 mma.sync) ----------------
#define AQT 64
#define AKT 32
#define QPAD 68
#define VPAD 72
#define PPAD 36

__global__ __launch_bounds__(128)
void attn_mma_kernel(const float* __restrict__ Q, const float* __restrict__ K,
                     const float* __restrict__ V, const int* __restrict__ npm,
                     float* __restrict__ O)
{
    __shared__ unsigned Qs[AQT][QPAD];
    __shared__ unsigned Ks[AKT][QPAD];
    __shared__ unsigned Vs[AKT][VPAD];
    __shared__ unsigned Ps[AQT][PPAD];
    __shared__ float kms[AKT];

    const int b = blockIdx.z, h = blockIdx.y, qt = blockIdx.x;
    const int tid  = threadIdx.x;
    const int lane = tid & 31;
    const int wq   = tid >> 5;
    const int g    = lane >> 2;
    const int cc   = lane & 3;
    const int wr   = wq * 16;

    const float* Qbase = Q + (size_t)(b * SS + qt * AQT) * DD + h * 64;
    #pragma unroll
    for (int i = tid; i < AQT * 16; i += 128) {
        int r = i >> 4, c4 = (i & 15) << 2;
        float4 v4 = *(const float4*)(Qbase + (size_t)r * DD + c4);
        Qs[r][c4+0] = f2tf(v4.x); Qs[r][c4+1] = f2tf(v4.y);
        Qs[r][c4+2] = f2tf(v4.z); Qs[r][c4+3] = f2tf(v4.w);
    }

    float m0 = -1e30f, m1 = -1e30f, l0 = 0.f, l1 = 0.f;
    float o[8][4];
    #pragma unroll
    for (int nt = 0; nt < 8; nt++) {
        o[nt][0] = 0.f; o[nt][1] = 0.f; o[nt][2] = 0.f; o[nt][3] = 0.f;
    }

    for (int kt = 0; kt < SS / AKT; kt++) {
        __syncthreads();
        const float* Kbase = K + (size_t)(b * SS + kt * AKT) * DD + h * 64;
        const float* Vbase = V + (size_t)(b * SS + kt * AKT) * DD + h * 64;
        #pragma unroll
        for (int i = tid; i < AKT * 16; i += 128) {
            int r = i >> 4, c4 = (i & 15) << 2;
            float4 kv = *(const float4*)(Kbase + (size_t)r * DD + c4);
            Ks[r][c4+0] = f2tf(kv.x); Ks[r][c4+1] = f2tf(kv.y);
            Ks[r][c4+2] = f2tf(kv.z); Ks[r][c4+3] = f2tf(kv.w);
            float4 vv = *(const float4*)(Vbase + (size_t)r * DD + c4);
            Vs[r][c4+0] = f2tf(vv.x); Vs[r][c4+1] = f2tf(vv.y);
            Vs[r][c4+2] = f2tf(vv.z); Vs[r][c4+3] = f2tf(vv.w);
        }
        if (tid < AKT) kms[tid] = npm[b * SS + kt * AKT + tid] ? 1.f : 0.f;
        __syncthreads();

        float s[4][4];
        #pragma unroll
        for (int nt = 0; nt < 4; nt++) {
            s[nt][0] = 0.f; s[nt][1] = 0.f; s[nt][2] = 0.f; s[nt][3] = 0.f;
        }
        #pragma unroll
        for (int ks = 0; ks < 8; ks++) {
            unsigned a[4];
            a[0] = Qs[wr + g    ][ks*8 + cc    ];
            a[1] = Qs[wr + g + 8][ks*8 + cc    ];
            a[2] = Qs[wr + g    ][ks*8 + cc + 4];
            a[3] = Qs[wr + g + 8][ks*8 + cc + 4];
            #pragma unroll
            for (int nt = 0; nt < 4; nt++) {
                unsigned bf[2];
                bf[0] = Ks[nt*8 + g][ks*8 + cc    ];
                bf[1] = Ks[nt*8 + g][ks*8 + cc + 4];
                mma_tf32(s[nt], a, bf);
            }
        }

        #pragma unroll
        for (int nt = 0; nt < 4; nt++) {
            float k0 = kms[nt*8 + 2*cc];
            float k1 = kms[nt*8 + 2*cc + 1];
            s[nt][0] = (k0 != 0.f) ? s[nt][0] * ATT_SCALE : -1e9f;
            s[nt][1] = (k1 != 0.f) ? s[nt][1] * ATT_SCALE : -1e9f;
            s[nt][2] = (k0 != 0.f) ? s[nt][2] * ATT_SCALE : -1e9f;
            s[nt][3] = (k1 != 0.f) ? s[nt][3] * ATT_SCALE : -1e9f;
        }

        float tm0 = s[0][0], tm1 = s[0][2];
        #pragma unroll
        for (int nt = 0; nt < 4; nt++) {
            tm0 = fmaxf(tm0, fmaxf(s[nt][0], s[nt][1]));
            tm1 = fmaxf(tm1, fmaxf(s[nt][2], s[nt][3]));
        }
        tm0 = fmaxf(tm0, __shfl_xor_sync(0xffffffffu, tm0, 1));
        tm0 = fmaxf(tm0, __shfl_xor_sync(0xffffffffu, tm0, 2));
        tm1 = fmaxf(tm1, __shfl_xor_sync(0xffffffffu, tm1, 1));
        tm1 = fmaxf(tm1, __shfl_xor_sync(0xffffffffu, tm1, 2));
        float nm0 = fmaxf(m0, tm0), nm1 = fmaxf(m1, tm1);
        float f0 = __expf(m0 - nm0), f1 = __expf(m1 - nm1);

        float sum0 = 0.f, sum1 = 0.f;
        #pragma unroll
        for (int nt = 0; nt < 4; nt++) {
            float p00 = __expf(s[nt][0] - nm0);
            float p01 = __expf(s[nt][1] - nm0);
            float p10 = __expf(s[nt][2] - nm1);
            float p11 = __expf(s[nt][3] - nm1);
            sum0 += p00 + p01;
            sum1 += p10 + p11;
            *(uint2*)&Ps[wr + g    ][nt*8 + 2*cc] = make_uint2(f2tf(p00), f2tf(p01));
            *(uint2*)&Ps[wr + g + 8][nt*8 + 2*cc] = make_uint2(f2tf(p10), f2tf(p11));
        }
        sum0 += __shfl_xor_sync(0xffffffffu, sum0, 1);
        sum0 += __shfl_xor_sync(0xffffffffu, sum0, 2);
        sum1 += __shfl_xor_sync(0xffffffffu, sum1, 1);
        sum1 += __shfl_xor_sync(0xffffffffu, sum1, 2);
        l0 = l0 * f0 + sum0;
        l1 = l1 * f1 + sum1;
        m0 = nm0; m1 = nm1;

        #pragma unroll
        for (int nt = 0; nt < 8; nt++) {
            o[nt][0] *= f0; o[nt][1] *= f0;
            o[nt][2] *= f1; o[nt][3] *= f1;
        }
        __syncwarp();

        #pragma unroll
        for (int ks = 0; ks < 4; ks++) {
            unsigned a[4];
            a[0] = Ps[wr + g    ][ks*8 + cc    ];
            a[1] = Ps[wr + g + 8][ks*8 + cc    ];
            a[2] = Ps[wr + g    ][ks*8 + cc + 4];
            a[3] = Ps[wr + g + 8][ks*8 + cc + 4];
            #pragma unroll
            for (int nt = 0; nt < 8; nt++) {
                unsigned bf[2];
                bf[0] = Vs[ks*8 + cc    ][nt*8 + g];
                bf[1] = Vs[ks*8 + cc + 4][nt*8 + g];
                mma_tf32(o[nt], a, bf);
            }
        }
    }

    float i0 = 1.f / l0, i1 = 1.f / l1;
    size_t r0 = (size_t)(b * SS + qt * AQT + wr + g) * DD + h * 64;
    size_t r1 = r0 + (size_t)8 * DD;
    #pragma unroll
    for (int nt = 0; nt < 8; nt++) {
        int ncol = nt * 8 + 2 * cc;
        float2 w0, w1;
        w0.x = f2tf_f(o[nt][0] * i0); w0.y = f2tf_f(o[nt][1] * i0);
        w1.x = f2tf_f(o[nt][2] * i1); w1.y = f2tf_f(o[nt][3] * i1);
        *(float2*)(O + r0 + ncol) = w0;
        *(float2*)(O + r1 + ncol) = w1;
    }
}

// ---------------- host orchestration ----------------
extern "C" void kernel_launch(void* const* d_in, const int* in_sizes, int n_in,
                              void* d_out, int out_size)
{
    const float* embed = (const float*)d_in[0];
    const int*   npm   = (const int*)  d_in[1];
    const float* pe    = (const float*)d_in[2];
    const float* Wq    = (const float*)d_in[3];
    const float* bq    = (const float*)d_in[4];
    const float* Wk    = (const float*)d_in[5];
    const float* bk    = (const float*)d_in[6];
    const float* Wv    = (const float*)d_in[7];
    const float* bv    = (const float*)d_in[8];
    const float* Wo    = (const float*)d_in[9];
    const float* bo    = (const float*)d_in[10];
    const float* ln1g  = (const float*)d_in[11];
    const float* ln1b  = (const float*)d_in[12];
    const float* W1    = (const float*)d_in[13];
    const float* b1    = (const float*)d_in[14];
    const float* W2    = (const float*)d_in[15];
    const float* b2    = (const float*)d_in[16];
    const float* ln2g  = (const float*)d_in[17];
    const float* ln2b  = (const float*)d_in[18];
    const float* lnfg  = (const float*)d_in[19];
    const float* lnfb  = (const float*)d_in[20];

    float *x, *hh, *htf, *x1, *qb, *kb, *vb, *ob, *ffb;
    float *wqc, *wkc, *wvc, *woc, *w1c, *w2c;
    cudaGetSymbolAddress((void**)&x,   g_x);
    cudaGetSymbolAddress((void**)&hh,  g_h);
    cudaGetSymbolAddress((void**)&htf, g_htf);
    cudaGetSymbolAddress((void**)&x1,  g_x1);
    cudaGetSymbolAddress((void**)&qb,  g_q);
    cudaGetSymbolAddress((void**)&kb,  g_k);
    cudaGetSymbolAddress((void**)&vb,  g_v);
    cudaGetSymbolAddress((void**)&ob,  g_o);
    cudaGetSymbolAddress((void**)&ffb, g_ff);
    cudaGetSymbolAddress((void**)&wqc, g_wqc);
    cudaGetSymbolAddress((void**)&wkc, g_wkc);
    cudaGetSymbolAddress((void**)&wvc, g_wvc);
    cudaGetSymbolAddress((void**)&woc, g_woc);
    cudaGetSymbolAddress((void**)&w1c, g_w1c);
    cudaGetSymbolAddress((void**)&w2c, g_w2c);

    cudaFuncSetAttribute(mma_gemm_kernel,
                         cudaFuncAttributeMaxDynamicSharedMemorySize,
                         GEMM_SMEM_BYTES);

    // weight prep: transpose + tf32 round
    {
        dim3 blk(32, 8);
        tfconv_t_kernel<<<dim3(DD/32, DD/32, LYR), blk>>>(Wq, wqc, DD, DD);
        tfconv_t_kernel<<<dim3(DD/32, DD/32, LYR), blk>>>(Wk, wkc, DD, DD);
        tfconv_t_kernel<<<dim3(DD/32, DD/32, LYR), blk>>>(Wv, wvc, DD, DD);
        tfconv_t_kernel<<<dim3(DD/32, DD/32, LYR), blk>>>(Wo, woc, DD, DD);
        tfconv_t_kernel<<<dim3(FF/32, DD/32, LYR), blk>>>(W1, w1c, DD, FF);
        tfconv_t_kernel<<<dim3(DD/32, FF/32, LYR), blk>>>(W2, w2c, FF, DD);
    }

    {
        int tot4 = MM * DD / 4;
        add_pe_kernel<<<(tot4 + 255) / 256, 256>>>(embed, pe, x);
    }

    dim3 gD(DD / BN, MM / BM);       // (8, 32)
    dim3 gF(FF / BN, MM / BM);       // (32, 32)
    dim3 gAttn(SS / AQT, HH, BB);    // (16, 16, 4)

    for (int l = 0; l < LYR; l++) {
        const float* wq = wqc + (size_t)l * DD * DD;
        const float* wk = wkc + (size_t)l * DD * DD;
        const float* wv = wvc + (size_t)l * DD * DD;
        const float* wo = woc + (size_t)l * DD * DD;
        const float* w1 = w1c + (size_t)l * DD * FF;
        const float* w2 = w2c + (size_t)l * FF * DD;
        const float* lbq = bq + (size_t)l * DD;
        const float* lbk = bk + (size_t)l * DD;
        const float* lbv = bv + (size_t)l * DD;
        const float* lbo = bo + (size_t)l * DD;
        const float* lb1 = b1 + (size_t)l * FF;
        const float* lb2 = b2 + (size_t)l * DD;

        ln_kernel<<<MM, 256>>>(x, ln1g + (size_t)l * DD, ln1b + (size_t)l * DD, hh, htf);
        mma_gemm_kernel<<<gD, 256, GEMM_SMEM_BYTES>>>(htf, wq, lbq, nullptr, nullptr, qb, MM, DD, DD, 0);
        mma_gemm_kernel<<<gD, 256, GEMM_SMEM_BYTES>>>(htf, wk, lbk, nullptr, nullptr, kb, MM, DD, DD, 0);
        mma_gemm_kernel<<<gD, 256, GEMM_SMEM_BYTES>>>(htf, wv, lbv, nullptr, nullptr, vb, MM, DD, DD, 0);
        attn_mma_kernel<<<gAttn, 128>>>(qb, kb, vb, npm, ob);
        mma_gemm_kernel<<<gD, 256, GEMM_SMEM_BYTES>>>(ob, wo, lbo, hh, npm, x1, MM, DD, DD, 2);
        ln_kernel<<<MM, 256>>>(x1, ln2g + (size_t)l * DD, ln2b + (size_t)l * DD, hh, htf);
        mma_gemm_kernel<<<gF, 256, GEMM_SMEM_BYTES>>>(htf, w1, lb1, nullptr, nullptr, ffb, MM, FF, DD, 1);
        mma_gemm_kernel<<<gD, 256, GEMM_SMEM_BYTES>>>(ffb, w2, lb2, hh, npm, x, MM, DD, FF, 2);
    }

    ln_kernel<<<MM, 256>>>(x, lnfg, lnfb, (float*)d_out, nullptr);
}

// round 10
// speedup vs baseline: 6.6906x; 1.6193x over previous
#include <cuda_runtime.h>
#include <cuda_fp16.h>
#include <math.h>
#include <stdint.h>

// Problem constants
#define LYR 6
#define BB  4
#define SS  1024
#define DD  1024
#define HH  16
#define DKK 64
#define FF  4096
#define MM  (BB*SS)          // 4096 rows
#define ATT_SCALE 0.125f     // 1/sqrt(64)
#define LN_EPS 1e-6f

// ---------------- scratch buffers (device globals; no allocation) -------------
__device__ float  g_x [MM*DD];
__device__ float  g_h [MM*DD];
__device__ __half g_htf[MM*DD];     // fp16 LN output (GEMM A operand)
__device__ float  g_x1[MM*DD];
__device__ float  g_q [MM*DD];
__device__ float  g_k [MM*DD];
__device__ float  g_v [MM*DD];
__device__ __half g_o [MM*DD];      // attn out, fp16
__device__ __half g_ff[MM*FF];      // relu out, fp16
// pre-converted + TRANSPOSED weights: Bt[n][k] = fp16(W[k][n])
__device__ __half g_wqc[LYR*DD*DD];
__device__ __half g_wkc[LYR*DD*DD];
__device__ __half g_wvc[LYR*DD*DD];
__device__ __half g_woc[LYR*DD*DD];
__device__ __half g_w1c[LYR*DD*FF];
__device__ __half g_w2c[LYR*FF*DD];

// ---------------- helpers ----------------
__device__ __forceinline__ unsigned f2tf(float f) {
    unsigned u;
    asm("cvt.rna.tf32.f32 %0, %1;" : "=r"(u) : "f"(f));
    return u;
}

__device__ __forceinline__ void mma_tf32(float c[4], const unsigned a[4], const unsigned b[2]) {
    asm volatile("mma.sync.aligned.m16n8k8.row.col.f32.tf32.tf32.f32 "
        "{%0,%1,%2,%3}, {%4,%5,%6,%7}, {%8,%9}, {%0,%1,%2,%3};"
        : "+f"(c[0]), "+f"(c[1]), "+f"(c[2]), "+f"(c[3])
        : "r"(a[0]), "r"(a[1]), "r"(a[2]), "r"(a[3]), "r"(b[0]), "r"(b[1]));
}

__device__ __forceinline__ void mma_f16(float c[4], const unsigned a[4], const unsigned b[2]) {
    asm volatile("mma.sync.aligned.m16n8k16.row.col.f32.f16.f16.f32 "
        "{%0,%1,%2,%3}, {%4,%5,%6,%7}, {%8,%9}, {%0,%1,%2,%3};"
        : "+f"(c[0]), "+f"(c[1]), "+f"(c[2]), "+f"(c[3])
        : "r"(a[0]), "r"(a[1]), "r"(a[2]), "r"(a[3]), "r"(b[0]), "r"(b[1]));
}

__device__ __forceinline__ void ldsm4(unsigned r[4], unsigned addr) {
    asm volatile("ldmatrix.sync.aligned.m8n8.x4.shared.b16 {%0,%1,%2,%3}, [%4];"
        : "=r"(r[0]), "=r"(r[1]), "=r"(r[2]), "=r"(r[3]) : "r"(addr));
}

__device__ __forceinline__ void cp16(unsigned dst, const void* src) {
    asm volatile("cp.async.cg.shared.global [%0], [%1], 16;" :: "r"(dst), "l"(src));
}
#define CP_COMMIT() asm volatile("cp.async.commit_group;" ::: "memory")
#define CP_WAIT2()  asm volatile("cp.async.wait_group 2;" ::: "memory")

// ---------------- weight prep: dst[n][k] = fp16(src[k][n]) -------------------
__global__ void h16conv_t_kernel(const float* __restrict__ src,
                                 __half* __restrict__ dst, int K, int N)
{
    __shared__ float t[32][33];
    int l = blockIdx.z;
    const float* s = src + (size_t)l * K * N;
    __half* d = dst + (size_t)l * K * N;
    int n0 = blockIdx.x * 32, k0 = blockIdx.y * 32;
    int tx = threadIdx.x, ty = threadIdx.y;   // 32 x 8
    #pragma unroll
    for (int i = 0; i < 32; i += 8)
        t[ty + i][tx] = s[(size_t)(k0 + ty + i) * N + n0 + tx];
    __syncthreads();
    #pragma unroll
    for (int i = 0; i < 32; i += 8)
        d[(size_t)(n0 + ty + i) * K + k0 + tx] = __float2half_rn(t[tx][ty + i]);
}

// ---------------- PE add ----------------
__global__ void add_pe_kernel(const float* __restrict__ embed,
                              const float* __restrict__ pe,
                              float* __restrict__ x)
{
    int i = blockIdx.x * blockDim.x + threadIdx.x;
    const int TOT4 = MM * DD / 4;
    if (i >= TOT4) return;
    int pe4 = i % (SS * DD / 4);
    float4 e = ((const float4*)embed)[i];
    float4 p = ((const float4*)pe)[pe4];
    float4 r; r.x = e.x + p.x; r.y = e.y + p.y; r.z = e.z + p.z; r.w = e.w + p.w;
    ((float4*)x)[i] = r;
}

// ---------------- LayerNorm (dual output: fp32 + fp16) -----------------------
__global__ void ln_kernel(const float* __restrict__ x,
                          const float* __restrict__ g,
                          const float* __restrict__ beta,
                          float* __restrict__ y,
                          __half* __restrict__ ytf)
{
    __shared__ float shm[32];
    __shared__ float s_mu, s_rstd;
    int row = blockIdx.x;
    int t   = threadIdx.x;
    const float4* xr = (const float4*)(x + (size_t)row * DD);
    float4 v = xr[t];
    float s = v.x + v.y + v.z + v.w;
    #pragma unroll
    for (int o = 16; o; o >>= 1) s += __shfl_xor_sync(0xffffffffu, s, o);
    if ((t & 31) == 0) shm[t >> 5] = s;
    __syncthreads();
    if (t < 32) {
        float tot = (t < 8) ? shm[t] : 0.f;
        #pragma unroll
        for (int o = 4; o; o >>= 1) tot += __shfl_xor_sync(0xffffffffu, tot, o);
        if (t == 0) s_mu = tot * (1.0f / DD);
    }
    __syncthreads();
    float mu = s_mu;
    float d0 = v.x - mu, d1 = v.y - mu, d2 = v.z - mu, d3 = v.w - mu;
    float s2 = d0*d0 + d1*d1 + d2*d2 + d3*d3;
    #pragma unroll
    for (int o = 16; o; o >>= 1) s2 += __shfl_xor_sync(0xffffffffu, s2, o);
    if ((t & 31) == 0) shm[t >> 5] = s2;
    __syncthreads();
    if (t < 32) {
        float tot = (t < 8) ? shm[t] : 0.f;
        #pragma unroll
        for (int o = 4; o; o >>= 1) tot += __shfl_xor_sync(0xffffffffu, tot, o);
        if (t == 0) s_rstd = rsqrtf(tot * (1.0f / DD) + LN_EPS);
    }
    __syncthreads();
    float rstd = s_rstd;
    float4 gg = ((const float4*)g)[t];
    float4 bb = ((const float4*)beta)[t];
    float4 out;
    out.x = d0 * rstd * gg.x + bb.x;
    out.y = d1 * rstd * gg.y + bb.y;
    out.z = d2 * rstd * gg.z + bb.z;
    out.w = d3 * rstd * gg.w + bb.w;
    ((float4*)(y + (size_t)row * DD))[t] = out;
    if (ytf) {
        __half2* yh = (__half2*)(ytf + (size_t)row * DD);
        yh[2*t    ] = __floats2half2_rn(out.x, out.y);
        yh[2*t + 1] = __floats2half2_rn(out.z, out.w);
    }
}

// ---------------- FP16 GEMM (mma.sync m16n8k16), 4-stage cp.async ------------
// C[M,N] = A[M,K] @ Bt[N,K]^T  (+bias) (+relu->fp16) (+residual,*mask)
// Both operands fp16 K-major in smem, 32-k slabs, stride 40 halfs (80B rows).
#define BM 128
#define BN 128
#define BKH 32               // k halfs per stage
#define STAGES 4
#define STRH 40              // smem row stride in halfs
#define T_STG (BM*STRH)      // halfs per operand per stage
#define GEMM_SMEM_BYTES (STAGES * 2 * T_STG * 2)   // 81920

__global__ __launch_bounds__(256, 2)
void mma_gemm_kernel(const __half* __restrict__ A, const __half* __restrict__ Bt,
                     const float* __restrict__ bias, const float* __restrict__ res,
                     const int* __restrict__ mask, void* __restrict__ Cv,
                     int M, int N, int K, int epi)
{
    extern __shared__ __half smemh[];
    __half* Asm = smemh;                      // [STAGES][BM][STRH]
    __half* Bsm = smemh + STAGES * T_STG;     // [STAGES][BN][STRH]
    const unsigned a_u = (unsigned)__cvta_generic_to_shared(Asm);
    const unsigned b_u = (unsigned)__cvta_generic_to_shared(Bsm);

    const int tid  = threadIdx.x;
    const int lane = tid & 31;
    const int wrp  = tid >> 5;
    const int wm   = wrp >> 2;       // 0..1 -> 64 rows
    const int wn   = wrp & 3;        // 0..3 -> 32 cols
    const int l15  = lane & 15;
    const int lhi  = lane >> 4;
    const int g    = lane >> 2;
    const int cc   = lane & 3;

    const int brow = blockIdx.y * BM;
    const int bcol = blockIdx.x * BN;

    // staging: thread copies 32B (16 halfs) of A and of B: row tid>>1
    const int s_r = tid >> 1, s_c = (tid & 1) * 16;   // halfs
    const __half* Ag = A  + (size_t)(brow + s_r) * K + s_c;
    const __half* Bg = Bt + (size_t)(bcol + s_r) * K + s_c;

    const int NK = K / BKH;

    auto load_stage = [&](int s, int kt) {
        const __half* ag = Ag + kt * BKH;
        const __half* bg = Bg + kt * BKH;
        unsigned d = (unsigned)((s * T_STG + s_r * STRH + s_c) * 2);
        cp16(a_u + d, ag); cp16(a_u + d + 16, ag + 8);
        cp16(b_u + d, bg); cp16(b_u + d + 16, bg + 8);
    };

    float acc[4][4][4];
    #pragma unroll
    for (int i = 0; i < 4; i++)
        #pragma unroll
        for (int j = 0; j < 4; j++) {
            acc[i][j][0] = 0.f; acc[i][j][1] = 0.f;
            acc[i][j][2] = 0.f; acc[i][j][3] = 0.f;
        }

    load_stage(0, 0); CP_COMMIT();
    load_stage(1, 1); CP_COMMIT();
    load_stage(2, 2); CP_COMMIT();

    // ldmatrix bases (bytes within a stage):
    // lanes 0-7: rows+0..7 col0 | 8-15: rows+8..15 col0 | 16-23: rows+0..7 col8 | 24-31: rows+8..15 col8
    const unsigned a_frag_off = (unsigned)(((wm * 64 + l15) * STRH + lhi * 8) * 2);
    const unsigned b_frag_off = (unsigned)(((wn * 32 + l15) * STRH + lhi * 8) * 2);

    int cur = 0;
    for (int kt = 0; kt < NK; kt++) {
        CP_WAIT2();
        __syncthreads();

        if (kt + 3 < NK) load_stage((kt + 3) & 3, kt + 3);
        CP_COMMIT();

        const unsigned abase = a_u + (unsigned)(cur * T_STG * 2) + a_frag_off;
        const unsigned bbase = b_u + (unsigned)(cur * T_STG * 2) + b_frag_off;

        #pragma unroll
        for (int ks = 0; ks < 2; ks++) {      // two k16 groups per 32-k slab
            unsigned a[4][4], b[2][4];
            #pragma unroll
            for (int mt = 0; mt < 4; mt++)
                ldsm4(a[mt], abase + (unsigned)(mt * 16 * STRH * 2 + ks * 32));
            #pragma unroll
            for (int bt = 0; bt < 2; bt++)
                ldsm4(b[bt], bbase + (unsigned)(bt * 16 * STRH * 2 + ks * 32));

            #pragma unroll
            for (int mt = 0; mt < 4; mt++) {
                {   unsigned bf[2] = { b[0][0], b[0][2] };   // nt=0 (n rows +g)
                    mma_f16(acc[mt][0], a[mt], bf); }
                {   unsigned bf[2] = { b[0][1], b[0][3] };   // nt=1 (n rows +8+g)
                    mma_f16(acc[mt][1], a[mt], bf); }
                {   unsigned bf[2] = { b[1][0], b[1][2] };   // nt=2
                    mma_f16(acc[mt][2], a[mt], bf); }
                {   unsigned bf[2] = { b[1][1], b[1][3] };   // nt=3
                    mma_f16(acc[mt][3], a[mt], bf); }
            }
        }
        cur = (cur + 1) & 3;
    }

    // ---- epilogue ----
    #pragma unroll
    for (int mt = 0; mt < 4; mt++) {
        int r0 = brow + wm * 64 + mt * 16 + g;
        int r1 = r0 + 8;
        float mk0 = 1.f, mk1 = 1.f;
        if (epi == 2) {
            mk0 = mask[r0] ? 1.f : 0.f;
            mk1 = mask[r1] ? 1.f : 0.f;
        }
        #pragma unroll
        for (int nt = 0; nt < 4; nt++) {
            int ncol = bcol + wn * 32 + nt * 8 + cc * 2;
            float2 bv = *(const float2*)(bias + ncol);
            float2 o0, o1;
            o0.x = acc[mt][nt][0] + bv.x; o0.y = acc[mt][nt][1] + bv.y;
            o1.x = acc[mt][nt][2] + bv.x; o1.y = acc[mt][nt][3] + bv.y;
            if (epi == 1) {
                // relu -> fp16 (feeds next GEMM's A operand)
                __half* Ch = (__half*)Cv;
                *(__half2*)(Ch + (size_t)r0 * N + ncol) =
                    __floats2half2_rn(fmaxf(o0.x, 0.f), fmaxf(o0.y, 0.f));
                *(__half2*)(Ch + (size_t)r1 * N + ncol) =
                    __floats2half2_rn(fmaxf(o1.x, 0.f), fmaxf(o1.y, 0.f));
            } else {
                float* Cf = (float*)Cv;
                if (epi == 2) {
                    float2 rv0 = *(const float2*)(res + (size_t)r0 * N + ncol);
                    float2 rv1 = *(const float2*)(res + (size_t)r1 * N + ncol);
                    o0.x = (o0.x + rv0.x) * mk0; o0.y = (o0.y + rv0.y) * mk0;
                    o1.x = (o1.x + rv1.x) * mk1; o1.y = (o1.y + rv1.y) * mk1;
                }
                *(float2*)(Cf + (size_t)r0 * N + ncol) = o0;
                *(float2*)(Cf + (size_t)r1 * N + ncol) = o1;
            }
        }
    }
}

// ---------------- Tensor-core flash attention (TF32 mma.sync) ----------------
#define AQT 64
#define AKT 32
#define QPAD 68
#define VPAD 72
#define PPAD 36

__global__ __launch_bounds__(128)
void attn_mma_kernel(const float* __restrict__ Q, const float* __restrict__ K,
                     const float* __restrict__ V, const int* __restrict__ npm,
                     __half* __restrict__ O)
{
    __shared__ unsigned Qs[AQT][QPAD];
    __shared__ unsigned Ks[AKT][QPAD];
    __shared__ unsigned Vs[AKT][VPAD];
    __shared__ unsigned Ps[AQT][PPAD];
    __shared__ float kms[AKT];

    const int b = blockIdx.z, h = blockIdx.y, qt = blockIdx.x;
    const int tid  = threadIdx.x;
    const int lane = tid & 31;
    const int wq   = tid >> 5;
    const int g    = lane >> 2;
    const int cc   = lane & 3;
    const int wr   = wq * 16;

    const float* Qbase = Q + (size_t)(b * SS + qt * AQT) * DD + h * 64;
    #pragma unroll
    for (int i = tid; i < AQT * 16; i += 128) {
        int r = i >> 4, c4 = (i & 15) << 2;
        float4 v4 = *(const float4*)(Qbase + (size_t)r * DD + c4);
        Qs[r][c4+0] = f2tf(v4.x); Qs[r][c4+1] = f2tf(v4.y);
        Qs[r][c4+2] = f2tf(v4.z); Qs[r][c4+3] = f2tf(v4.w);
    }

    float m0 = -1e30f, m1 = -1e30f, l0 = 0.f, l1 = 0.f;
    float o[8][4];
    #pragma unroll
    for (int nt = 0; nt < 8; nt++) {
        o[nt][0] = 0.f; o[nt][1] = 0.f; o[nt][2] = 0.f; o[nt][3] = 0.f;
    }

    for (int kt = 0; kt < SS / AKT; kt++) {
        __syncthreads();
        const float* Kbase = K + (size_t)(b * SS + kt * AKT) * DD + h * 64;
        const float* Vbase = V + (size_t)(b * SS + kt * AKT) * DD + h * 64;
        #pragma unroll
        for (int i = tid; i < AKT * 16; i += 128) {
            int r = i >> 4, c4 = (i & 15) << 2;
            float4 kv = *(const float4*)(Kbase + (size_t)r * DD + c4);
            Ks[r][c4+0] = f2tf(kv.x); Ks[r][c4+1] = f2tf(kv.y);
            Ks[r][c4+2] = f2tf(kv.z); Ks[r][c4+3] = f2tf(kv.w);
            float4 vv = *(const float4*)(Vbase + (size_t)r * DD + c4);
            Vs[r][c4+0] = f2tf(vv.x); Vs[r][c4+1] = f2tf(vv.y);
            Vs[r][c4+2] = f2tf(vv.z); Vs[r][c4+3] = f2tf(vv.w);
        }
        if (tid < AKT) kms[tid] = npm[b * SS + kt * AKT + tid] ? 1.f : 0.f;
        __syncthreads();

        float s[4][4];
        #pragma unroll
        for (int nt = 0; nt < 4; nt++) {
            s[nt][0] = 0.f; s[nt][1] = 0.f; s[nt][2] = 0.f; s[nt][3] = 0.f;
        }
        #pragma unroll
        for (int ks = 0; ks < 8; ks++) {
            unsigned a[4];
            a[0] = Qs[wr + g    ][ks*8 + cc    ];
            a[1] = Qs[wr + g + 8][ks*8 + cc    ];
            a[2] = Qs[wr + g    ][ks*8 + cc + 4];
            a[3] = Qs[wr + g + 8][ks*8 + cc + 4];
            #pragma unroll
            for (int nt = 0; nt < 4; nt++) {
                unsigned bf[2];
                bf[0] = Ks[nt*8 + g][ks*8 + cc    ];
                bf[1] = Ks[nt*8 + g][ks*8 + cc + 4];
                mma_tf32(s[nt], a, bf);
            }
        }

        #pragma unroll
        for (int nt = 0; nt < 4; nt++) {
            float k0 = kms[nt*8 + 2*cc];
            float k1 = kms[nt*8 + 2*cc + 1];
            s[nt][0] = (k0 != 0.f) ? s[nt][0] * ATT_SCALE : -1e9f;
            s[nt][1] = (k1 != 0.f) ? s[nt][1] * ATT_SCALE : -1e9f;
            s[nt][2] = (k0 != 0.f) ? s[nt][2] * ATT_SCALE : -1e9f;
            s[nt][3] = (k1 != 0.f) ? s[nt][3] * ATT_SCALE : -1e9f;
        }

        float tm0 = s[0][0], tm1 = s[0][2];
        #pragma unroll
        for (int nt = 0; nt < 4; nt++) {
            tm0 = fmaxf(tm0, fmaxf(s[nt][0], s[nt][1]));
            tm1 = fmaxf(tm1, fmaxf(s[nt][2], s[nt][3]));
        }
        tm0 = fmaxf(tm0, __shfl_xor_sync(0xffffffffu, tm0, 1));
        tm0 = fmaxf(tm0, __shfl_xor_sync(0xffffffffu, tm0, 2));
        tm1 = fmaxf(tm1, __shfl_xor_sync(0xffffffffu, tm1, 1));
        tm1 = fmaxf(tm1, __shfl_xor_sync(0xffffffffu, tm1, 2));
        float nm0 = fmaxf(m0, tm0), nm1 = fmaxf(m1, tm1);
        float f0 = __expf(m0 - nm0), f1 = __expf(m1 - nm1);

        float sum0 = 0.f, sum1 = 0.f;
        #pragma unroll
        for (int nt = 0; nt < 4; nt++) {
            float p00 = __expf(s[nt][0] - nm0);
            float p01 = __expf(s[nt][1] - nm0);
            float p10 = __expf(s[nt][2] - nm1);
            float p11 = __expf(s[nt][3] - nm1);
            sum0 += p00 + p01;
            sum1 += p10 + p11;
            *(uint2*)&Ps[wr + g    ][nt*8 + 2*cc] = make_uint2(f2tf(p00), f2tf(p01));
            *(uint2*)&Ps[wr + g + 8][nt*8 + 2*cc] = make_uint2(f2tf(p10), f2tf(p11));
        }
        sum0 += __shfl_xor_sync(0xffffffffu, sum0, 1);
        sum0 += __shfl_xor_sync(0xffffffffu, sum0, 2);
        sum1 += __shfl_xor_sync(0xffffffffu, sum1, 1);
        sum1 += __shfl_xor_sync(0xffffffffu, sum1, 2);
        l0 = l0 * f0 + sum0;
        l1 = l1 * f1 + sum1;
        m0 = nm0; m1 = nm1;

        #pragma unroll
        for (int nt = 0; nt < 8; nt++) {
            o[nt][0] *= f0; o[nt][1] *= f0;
            o[nt][2] *= f1; o[nt][3] *= f1;
        }
        __syncwarp();

        #pragma unroll
        for (int ks = 0; ks < 4; ks++) {
            unsigned a[4];
            a[0] = Ps[wr + g    ][ks*8 + cc    ];
            a[1] = Ps[wr + g + 8][ks*8 + cc    ];
            a[2] = Ps[wr + g    ][ks*8 + cc + 4];
            a[3] = Ps[wr + g + 8][ks*8 + cc + 4];
            #pragma unroll
            for (int nt = 0; nt < 8; nt++) {
                unsigned bf[2];
                bf[0] = Vs[ks*8 + cc    ][nt*8 + g];
                bf[1] = Vs[ks*8 + cc + 4][nt*8 + g];
                mma_tf32(o[nt], a, bf);
            }
        }
    }

    // output feeds Wo-GEMM A operand -> fp16
    float i0 = 1.f / l0, i1 = 1.f / l1;
    size_t r0 = (size_t)(b * SS + qt * AQT + wr + g) * DD + h * 64;
    size_t r1 = r0 + (size_t)8 * DD;
    #pragma unroll
    for (int nt = 0; nt < 8; nt++) {
        int ncol = nt * 8 + 2 * cc;
        *(__half2*)(O + r0 + ncol) = __floats2half2_rn(o[nt][0] * i0, o[nt][1] * i0);
        *(__half2*)(O + r1 + ncol) = __floats2half2_rn(o[nt][2] * i1, o[nt][3] * i1);
    }
}

// ---------------- host orchestration ----------------
extern "C" void kernel_launch(void* const* d_in, const int* in_sizes, int n_in,
                              void* d_out, int out_size)
{
    const float* embed = (const float*)d_in[0];
    const int*   npm   = (const int*)  d_in[1];
    const float* pe    = (const float*)d_in[2];
    const float* Wq    = (const float*)d_in[3];
    const float* bq    = (const float*)d_in[4];
    const float* Wk    = (const float*)d_in[5];
    const float* bk    = (const float*)d_in[6];
    const float* Wv    = (const float*)d_in[7];
    const float* bv    = (const float*)d_in[8];
    const float* Wo    = (const float*)d_in[9];
    const float* bo    = (const float*)d_in[10];
    const float* ln1g  = (const float*)d_in[11];
    const float* ln1b  = (const float*)d_in[12];
    const float* W1    = (const float*)d_in[13];
    const float* b1    = (const float*)d_in[14];
    const float* W2    = (const float*)d_in[15];
    const float* b2    = (const float*)d_in[16];
    const float* ln2g  = (const float*)d_in[17];
    const float* ln2b  = (const float*)d_in[18];
    const float* lnfg  = (const float*)d_in[19];
    const float* lnfb  = (const float*)d_in[20];

    float *x, *hh, *x1, *qb, *kb, *vb;
    __half *htf, *ob, *ffb;
    __half *wqc, *wkc, *wvc, *woc, *w1c, *w2c;
    cudaGetSymbolAddress((void**)&x,   g_x);
    cudaGetSymbolAddress((void**)&hh,  g_h);
    cudaGetSymbolAddress((void**)&htf, g_htf);
    cudaGetSymbolAddress((void**)&x1,  g_x1);
    cudaGetSymbolAddress((void**)&qb,  g_q);
    cudaGetSymbolAddress((void**)&kb,  g_k);
    cudaGetSymbolAddress((void**)&vb,  g_v);
    cudaGetSymbolAddress((void**)&ob,  g_o);
    cudaGetSymbolAddress((void**)&ffb, g_ff);
    cudaGetSymbolAddress((void**)&wqc, g_wqc);
    cudaGetSymbolAddress((void**)&wkc, g_wkc);
    cudaGetSymbolAddress((void**)&wvc, g_wvc);
    cudaGetSymbolAddress((void**)&woc, g_woc);
    cudaGetSymbolAddress((void**)&w1c, g_w1c);
    cudaGetSymbolAddress((void**)&w2c, g_w2c);

    cudaFuncSetAttribute(mma_gemm_kernel,
                         cudaFuncAttributeMaxDynamicSharedMemorySize,
                         GEMM_SMEM_BYTES);

    // weight prep: transpose + fp16 convert
    {
        dim3 blk(32, 8);
        h16conv_t_kernel<<<dim3(DD/32, DD/32, LYR), blk>>>(Wq, wqc, DD, DD);
        h16conv_t_kernel<<<dim3(DD/32, DD/32, LYR), blk>>>(Wk, wkc, DD, DD);
        h16conv_t_kernel<<<dim3(DD/32, DD/32, LYR), blk>>>(Wv, wvc, DD, DD);
        h16conv_t_kernel<<<dim3(DD/32, DD/32, LYR), blk>>>(Wo, woc, DD, DD);
        h16conv_t_kernel<<<dim3(FF/32, DD/32, LYR), blk>>>(W1, w1c, DD, FF);
        h16conv_t_kernel<<<dim3(DD/32, FF/32, LYR), blk>>>(W2, w2c, FF, DD);
    }

    {
        int tot4 = MM * DD / 4;
        add_pe_kernel<<<(tot4 + 255) / 256, 256>>>(embed, pe, x);
    }

    dim3 gD(DD / BN, MM / BM);       // (8, 32)
    dim3 gF(FF / BN, MM / BM);       // (32, 32)
    dim3 gAttn(SS / AQT, HH, BB);    // (16, 16, 4)

    for (int l = 0; l < LYR; l++) {
        const __half* wq = wqc + (size_t)l * DD * DD;
        const __half* wk = wkc + (size_t)l * DD * DD;
        const __half* wv = wvc + (size_t)l * DD * DD;
        const __half* wo = woc + (size_t)l * DD * DD;
        const __half* w1 = w1c + (size_t)l * DD * FF;
        const __half* w2 = w2c + (size_t)l * FF * DD;
        const float* lbq = bq + (size_t)l * DD;
        const float* lbk = bk + (size_t)l * DD;
        const float* lbv = bv + (size_t)l * DD;
        const float* lbo = bo + (size_t)l * DD;
        const float* lb1 = b1 + (size_t)l * FF;
        const float* lb2 = b2 + (size_t)l * DD;

        ln_kernel<<<MM, 256>>>(x, ln1g + (size_t)l * DD, ln1b + (size_t)l * DD, hh, htf);
        mma_gemm_kernel<<<gD, 256, GEMM_SMEM_BYTES>>>(htf, wq, lbq, nullptr, nullptr, qb, MM, DD, DD, 0);
        mma_gemm_kernel<<<gD, 256, GEMM_SMEM_BYTES>>>(htf, wk, lbk, nullptr, nullptr, kb, MM, DD, DD, 0);
        mma_gemm_kernel<<<gD, 256, GEMM_SMEM_BYTES>>>(htf, wv, lbv, nullptr, nullptr, vb, MM, DD, DD, 0);
        attn_mma_kernel<<<gAttn, 128>>>(qb, kb, vb, npm, ob);
        mma_gemm_kernel<<<gD, 256, GEMM_SMEM_BYTES>>>(ob, wo, lbo, hh, npm, x1, MM, DD, DD, 2);
        ln_kernel<<<MM, 256>>>(x1, ln2g + (size_t)l * DD, ln2b + (size_t)l * DD, hh, htf);
        mma_gemm_kernel<<<gF, 256, GEMM_SMEM_BYTES>>>(htf, w1, lb1, nullptr, nullptr, ffb, MM, FF, DD, 1);
        mma_gemm_kernel<<<gD, 256, GEMM_SMEM_BYTES>>>(ffb, w2, lb2, hh, npm, x, MM, DD, FF, 2);
    }

    ln_kernel<<<MM, 256>>>(x, lnfg, lnfb, (float*)d_out, nullptr);
}

// round 11
// speedup vs baseline: 6.9100x; 1.0328x over previous
#include <cuda_runtime.h>
#include <cuda_fp16.h>
#include <math.h>
#include <stdint.h>

// Problem constants
#define LYR 6
#define BB  4
#define SS  1024
#define DD  1024
#define HH  16
#define DKK 64
#define FF  4096
#define MM  (BB*SS)          // 4096 rows
#define ATT_SCALE 0.125f     // 1/sqrt(64)
#define LN_EPS 1e-6f

// ---------------- scratch buffers (device globals; no allocation) -------------
__device__ float  g_x [MM*DD];
__device__ float  g_h [MM*DD];
__device__ __half g_htf[MM*DD];     // fp16 LN output (GEMM A operand)
__device__ float  g_x1[MM*DD];
__device__ __half g_q [MM*DD];
__device__ __half g_k [MM*DD];
__device__ __half g_v [MM*DD];
__device__ __half g_o [MM*DD];      // attn out, fp16
__device__ __half g_ff[MM*FF];      // relu out, fp16
// pre-converted + TRANSPOSED weights: Bt[n][k] = fp16(W[k][n])
__device__ __half g_wqc[LYR*DD*DD];
__device__ __half g_wkc[LYR*DD*DD];
__device__ __half g_wvc[LYR*DD*DD];
__device__ __half g_woc[LYR*DD*DD];
__device__ __half g_w1c[LYR*DD*FF];
__device__ __half g_w2c[LYR*FF*DD];

// ---------------- helpers ----------------
__device__ __forceinline__ void mma_f16(float c[4], const unsigned a[4], const unsigned b[2]) {
    asm volatile("mma.sync.aligned.m16n8k16.row.col.f32.f16.f16.f32 "
        "{%0,%1,%2,%3}, {%4,%5,%6,%7}, {%8,%9}, {%0,%1,%2,%3};"
        : "+f"(c[0]), "+f"(c[1]), "+f"(c[2]), "+f"(c[3])
        : "r"(a[0]), "r"(a[1]), "r"(a[2]), "r"(a[3]), "r"(b[0]), "r"(b[1]));
}

__device__ __forceinline__ void ldsm4(unsigned r[4], unsigned addr) {
    asm volatile("ldmatrix.sync.aligned.m8n8.x4.shared.b16 {%0,%1,%2,%3}, [%4];"
        : "=r"(r[0]), "=r"(r[1]), "=r"(r[2]), "=r"(r[3]) : "r"(addr));
}

__device__ __forceinline__ void cp16(unsigned dst, const void* src) {
    asm volatile("cp.async.cg.shared.global [%0], [%1], 16;" :: "r"(dst), "l"(src));
}
#define CP_COMMIT() asm volatile("cp.async.commit_group;" ::: "memory")
#define CP_WAIT2()  asm volatile("cp.async.wait_group 2;" ::: "memory")

__device__ __forceinline__ unsigned packh2(float a, float b) {
    __half2 h = __floats2half2_rn(a, b);
    return *(unsigned*)&h;
}

// ---------------- weight prep: dst[n][k] = fp16(src[k][n]) -------------------
__global__ void h16conv_t_kernel(const float* __restrict__ src,
                                 __half* __restrict__ dst, int K, int N)
{
    __shared__ float t[32][33];
    int l = blockIdx.z;
    const float* s = src + (size_t)l * K * N;
    __half* d = dst + (size_t)l * K * N;
    int n0 = blockIdx.x * 32, k0 = blockIdx.y * 32;
    int tx = threadIdx.x, ty = threadIdx.y;   // 32 x 8
    #pragma unroll
    for (int i = 0; i < 32; i += 8)
        t[ty + i][tx] = s[(size_t)(k0 + ty + i) * N + n0 + tx];
    __syncthreads();
    #pragma unroll
    for (int i = 0; i < 32; i += 8)
        d[(size_t)(n0 + ty + i) * K + k0 + tx] = __float2half_rn(t[tx][ty + i]);
}

// ---------------- PE add ----------------
__global__ void add_pe_kernel(const float* __restrict__ embed,
                              const float* __restrict__ pe,
                              float* __restrict__ x)
{
    int i = blockIdx.x * blockDim.x + threadIdx.x;
    const int TOT4 = MM * DD / 4;
    if (i >= TOT4) return;
    int pe4 = i % (SS * DD / 4);
    float4 e = ((const float4*)embed)[i];
    float4 p = ((const float4*)pe)[pe4];
    float4 r; r.x = e.x + p.x; r.y = e.y + p.y; r.z = e.z + p.z; r.w = e.w + p.w;
    ((float4*)x)[i] = r;
}

// ---------------- LayerNorm (dual output: fp32 + fp16) -----------------------
__global__ void ln_kernel(const float* __restrict__ x,
                          const float* __restrict__ g,
                          const float* __restrict__ beta,
                          float* __restrict__ y,
                          __half* __restrict__ ytf)
{
    __shared__ float shm[32];
    __shared__ float s_mu, s_rstd;
    int row = blockIdx.x;
    int t   = threadIdx.x;
    const float4* xr = (const float4*)(x + (size_t)row * DD);
    float4 v = xr[t];
    float s = v.x + v.y + v.z + v.w;
    #pragma unroll
    for (int o = 16; o; o >>= 1) s += __shfl_xor_sync(0xffffffffu, s, o);
    if ((t & 31) == 0) shm[t >> 5] = s;
    __syncthreads();
    if (t < 32) {
        float tot = (t < 8) ? shm[t] : 0.f;
        #pragma unroll
        for (int o = 4; o; o >>= 1) tot += __shfl_xor_sync(0xffffffffu, tot, o);
        if (t == 0) s_mu = tot * (1.0f / DD);
    }
    __syncthreads();
    float mu = s_mu;
    float d0 = v.x - mu, d1 = v.y - mu, d2 = v.z - mu, d3 = v.w - mu;
    float s2 = d0*d0 + d1*d1 + d2*d2 + d3*d3;
    #pragma unroll
    for (int o = 16; o; o >>= 1) s2 += __shfl_xor_sync(0xffffffffu, s2, o);
    if ((t & 31) == 0) shm[t >> 5] = s2;
    __syncthreads();
    if (t < 32) {
        float tot = (t < 8) ? shm[t] : 0.f;
        #pragma unroll
        for (int o = 4; o; o >>= 1) tot += __shfl_xor_sync(0xffffffffu, tot, o);
        if (t == 0) s_rstd = rsqrtf(tot * (1.0f / DD) + LN_EPS);
    }
    __syncthreads();
    float rstd = s_rstd;
    float4 gg = ((const float4*)g)[t];
    float4 bb = ((const float4*)beta)[t];
    float4 out;
    out.x = d0 * rstd * gg.x + bb.x;
    out.y = d1 * rstd * gg.y + bb.y;
    out.z = d2 * rstd * gg.z + bb.z;
    out.w = d3 * rstd * gg.w + bb.w;
    ((float4*)(y + (size_t)row * DD))[t] = out;
    if (ytf) {
        __half2* yh = (__half2*)(ytf + (size_t)row * DD);
        yh[2*t    ] = __floats2half2_rn(out.x, out.y);
        yh[2*t + 1] = __floats2half2_rn(out.z, out.w);
    }
}

// ---------------- FP16 GEMM (mma.sync m16n8k16), 4-stage cp.async ------------
// C[M,N] = A[M,K] @ Bt[N,K]^T
// epi 0: +bias -> fp16 out.  epi 1: +bias, relu -> fp16 out.
// epi 2: +bias +residual *mask -> fp32 out.
#define BM 128
#define BN 128
#define BKH 32               // k halfs per stage
#define STAGES 4
#define STRH 40              // smem row stride in halfs
#define T_STG (BM*STRH)
#define GEMM_SMEM_BYTES (STAGES * 2 * T_STG * 2)   // 81920

__global__ __launch_bounds__(256, 2)
void mma_gemm_kernel(const __half* __restrict__ A, const __half* __restrict__ Bt,
                     const float* __restrict__ bias, const float* __restrict__ res,
                     const int* __restrict__ mask, void* __restrict__ Cv,
                     int M, int N, int K, int epi)
{
    extern __shared__ __half smemh[];
    __half* Asm = smemh;
    __half* Bsm = smemh + STAGES * T_STG;
    const unsigned a_u = (unsigned)__cvta_generic_to_shared(Asm);
    const unsigned b_u = (unsigned)__cvta_generic_to_shared(Bsm);

    const int tid  = threadIdx.x;
    const int lane = tid & 31;
    const int wrp  = tid >> 5;
    const int wm   = wrp >> 2;
    const int wn   = wrp & 3;
    const int l15  = lane & 15;
    const int lhi  = lane >> 4;
    const int g    = lane >> 2;
    const int cc   = lane & 3;

    const int brow = blockIdx.y * BM;
    const int bcol = blockIdx.x * BN;

    const int s_r = tid >> 1, s_c = (tid & 1) * 16;
    const __half* Ag = A  + (size_t)(brow + s_r) * K + s_c;
    const __half* Bg = Bt + (size_t)(bcol + s_r) * K + s_c;

    const int NK = K / BKH;

    auto load_stage = [&](int s, int kt) {
        const __half* ag = Ag + kt * BKH;
        const __half* bg = Bg + kt * BKH;
        unsigned d = (unsigned)((s * T_STG + s_r * STRH + s_c) * 2);
        cp16(a_u + d, ag); cp16(a_u + d + 16, ag + 8);
        cp16(b_u + d, bg); cp16(b_u + d + 16, bg + 8);
    };

    float acc[4][4][4];
    #pragma unroll
    for (int i = 0; i < 4; i++)
        #pragma unroll
        for (int j = 0; j < 4; j++) {
            acc[i][j][0] = 0.f; acc[i][j][1] = 0.f;
            acc[i][j][2] = 0.f; acc[i][j][3] = 0.f;
        }

    load_stage(0, 0); CP_COMMIT();
    load_stage(1, 1); CP_COMMIT();
    load_stage(2, 2); CP_COMMIT();

    const unsigned a_frag_off = (unsigned)(((wm * 64 + l15) * STRH + lhi * 8) * 2);
    const unsigned b_frag_off = (unsigned)(((wn * 32 + l15) * STRH + lhi * 8) * 2);

    int cur = 0;
    for (int kt = 0; kt < NK; kt++) {
        CP_WAIT2();
        __syncthreads();

        if (kt + 3 < NK) load_stage((kt + 3) & 3, kt + 3);
        CP_COMMIT();

        const unsigned abase = a_u + (unsigned)(cur * T_STG * 2) + a_frag_off;
        const unsigned bbase = b_u + (unsigned)(cur * T_STG * 2) + b_frag_off;

        #pragma unroll
        for (int ks = 0; ks < 2; ks++) {
            unsigned a[4][4], b[2][4];
            #pragma unroll
            for (int mt = 0; mt < 4; mt++)
                ldsm4(a[mt], abase + (unsigned)(mt * 16 * STRH * 2 + ks * 32));
            #pragma unroll
            for (int bt = 0; bt < 2; bt++)
                ldsm4(b[bt], bbase + (unsigned)(bt * 16 * STRH * 2 + ks * 32));

            #pragma unroll
            for (int mt = 0; mt < 4; mt++) {
                {   unsigned bf[2] = { b[0][0], b[0][2] };
                    mma_f16(acc[mt][0], a[mt], bf); }
                {   unsigned bf[2] = { b[0][1], b[0][3] };
                    mma_f16(acc[mt][1], a[mt], bf); }
                {   unsigned bf[2] = { b[1][0], b[1][2] };
                    mma_f16(acc[mt][2], a[mt], bf); }
                {   unsigned bf[2] = { b[1][1], b[1][3] };
                    mma_f16(acc[mt][3], a[mt], bf); }
            }
        }
        cur = (cur + 1) & 3;
    }

    // ---- epilogue ----
    #pragma unroll
    for (int mt = 0; mt < 4; mt++) {
        int r0 = brow + wm * 64 + mt * 16 + g;
        int r1 = r0 + 8;
        float mk0 = 1.f, mk1 = 1.f;
        if (epi == 2) {
            mk0 = mask[r0] ? 1.f : 0.f;
            mk1 = mask[r1] ? 1.f : 0.f;
        }
        #pragma unroll
        for (int nt = 0; nt < 4; nt++) {
            int ncol = bcol + wn * 32 + nt * 8 + cc * 2;
            float2 bv = *(const float2*)(bias + ncol);
            float2 o0, o1;
            o0.x = acc[mt][nt][0] + bv.x; o0.y = acc[mt][nt][1] + bv.y;
            o1.x = acc[mt][nt][2] + bv.x; o1.y = acc[mt][nt][3] + bv.y;
            if (epi == 0) {
                __half* Ch = (__half*)Cv;
                *(__half2*)(Ch + (size_t)r0 * N + ncol) = __floats2half2_rn(o0.x, o0.y);
                *(__half2*)(Ch + (size_t)r1 * N + ncol) = __floats2half2_rn(o1.x, o1.y);
            } else if (epi == 1) {
                __half* Ch = (__half*)Cv;
                *(__half2*)(Ch + (size_t)r0 * N + ncol) =
                    __floats2half2_rn(fmaxf(o0.x, 0.f), fmaxf(o0.y, 0.f));
                *(__half2*)(Ch + (size_t)r1 * N + ncol) =
                    __floats2half2_rn(fmaxf(o1.x, 0.f), fmaxf(o1.y, 0.f));
            } else {
                float* Cf = (float*)Cv;
                float2 rv0 = *(const float2*)(res + (size_t)r0 * N + ncol);
                float2 rv1 = *(const float2*)(res + (size_t)r1 * N + ncol);
                o0.x = (o0.x + rv0.x) * mk0; o0.y = (o0.y + rv0.y) * mk0;
                o1.x = (o1.x + rv1.x) * mk1; o1.y = (o1.y + rv1.y) * mk1;
                *(float2*)(Cf + (size_t)r0 * N + ncol) = o0;
                *(float2*)(Cf + (size_t)r1 * N + ncol) = o1;
            }
        }
    }
}

// ---------------- FP16 flash attention (mma m16n8k16) ------------------------
// grid (S/64, H, B), 128 threads = 4 warps, warp owns 16 q-rows. KT=32.
#define AQT 64
#define AKT 32
#define QSTR 72   // Qs/Ks row stride (halfs); 144B rows, ldsm chunks conflict-free
#define VSTR 40   // Vt row stride (halfs)

__global__ __launch_bounds__(128)
void attn_f16_kernel(const __half* __restrict__ Q, const __half* __restrict__ K,
                     const __half* __restrict__ V, const int* __restrict__ npm,
                     __half* __restrict__ O)
{
    __shared__ __half Qs[AQT][QSTR];
    __shared__ __half Ks[AKT][QSTR];
    __shared__ __half Vt[64][VSTR];          // transposed V: [dk][key]
    __shared__ float kms[AKT];

    const unsigned q_u = (unsigned)__cvta_generic_to_shared(Qs);
    const unsigned k_u = (unsigned)__cvta_generic_to_shared(Ks);
    const unsigned v_u = (unsigned)__cvta_generic_to_shared(Vt);

    const int b = blockIdx.z, h = blockIdx.y, qt = blockIdx.x;
    const int tid  = threadIdx.x;
    const int lane = tid & 31;
    const int wq   = tid >> 5;
    const int g    = lane >> 2;
    const int cc   = lane & 3;
    const int l15  = lane & 15;
    const int lhi  = lane >> 4;
    const int wr   = wq * 16;

    // load Q tile (64 x 64 halfs)
    const __half* Qbase = Q + (size_t)(b * SS + qt * AQT) * DD + h * 64;
    #pragma unroll
    for (int i = tid; i < AQT * 8; i += 128) {
        int r = i >> 3, c = (i & 7) * 8;
        *(uint4*)&Qs[r][c] = *(const uint4*)(Qbase + (size_t)r * DD + c);
    }

    float m0 = -1e30f, m1 = -1e30f, l0 = 0.f, l1 = 0.f;
    float o[8][4];
    #pragma unroll
    for (int nt = 0; nt < 8; nt++) {
        o[nt][0] = 0.f; o[nt][1] = 0.f; o[nt][2] = 0.f; o[nt][3] = 0.f;
    }

    const unsigned qf_off = (unsigned)(((wr + l15) * QSTR + lhi * 8) * 2);

    for (int kt = 0; kt < SS / AKT; kt++) {
        __syncthreads();
        const __half* Kbase = K + (size_t)(b * SS + kt * AKT) * DD + h * 64;
        const __half* Vbase = V + (size_t)(b * SS + kt * AKT) * DD + h * 64;
        #pragma unroll
        for (int i = tid; i < AKT * 8; i += 128) {
            int r = i >> 3, c = (i & 7) * 8;
            *(uint4*)&Ks[r][c] = *(const uint4*)(Kbase + (size_t)r * DD + c);
            // V transposed store
            uint4 u = *(const uint4*)(Vbase + (size_t)r * DD + c);
            __half2* p2 = (__half2*)&u;
            #pragma unroll
            for (int j = 0; j < 4; j++) {
                Vt[c + 2*j    ][r] = __low2half(p2[j]);
                Vt[c + 2*j + 1][r] = __high2half(p2[j]);
            }
        }
        if (tid < AKT) kms[tid] = npm[b * SS + kt * AKT + tid] ? 1.f : 0.f;
        __syncthreads();

        // ---- S = Q @ K^T (16 x 32 per warp) ----
        float s[4][4];
        #pragma unroll
        for (int nt = 0; nt < 4; nt++) {
            s[nt][0] = 0.f; s[nt][1] = 0.f; s[nt][2] = 0.f; s[nt][3] = 0.f;
        }
        #pragma unroll
        for (int ks = 0; ks < 4; ks++) {     // dk: 4 x k16
            unsigned a[4];
            ldsm4(a, q_u + qf_off + (unsigned)(ks * 32));
            #pragma unroll
            for (int bt = 0; bt < 2; bt++) {
                unsigned bfr[4];
                ldsm4(bfr, k_u + (unsigned)(((bt * 16 + l15) * QSTR + lhi * 8) * 2 + ks * 32));
                {   unsigned bf[2] = { bfr[0], bfr[2] };
                    mma_f16(s[bt*2    ], a, bf); }
                {   unsigned bf[2] = { bfr[1], bfr[3] };
                    mma_f16(s[bt*2 + 1], a, bf); }
            }
        }

        // ---- mask + scale ----
        #pragma unroll
        for (int nt = 0; nt < 4; nt++) {
            float k0 = kms[nt*8 + 2*cc];
            float k1 = kms[nt*8 + 2*cc + 1];
            s[nt][0] = (k0 != 0.f) ? s[nt][0] * ATT_SCALE : -1e9f;
            s[nt][1] = (k1 != 0.f) ? s[nt][1] * ATT_SCALE : -1e9f;
            s[nt][2] = (k0 != 0.f) ? s[nt][2] * ATT_SCALE : -1e9f;
            s[nt][3] = (k1 != 0.f) ? s[nt][3] * ATT_SCALE : -1e9f;
        }

        // ---- online softmax (rows g / g+8) ----
        float tm0 = s[0][0], tm1 = s[0][2];
        #pragma unroll
        for (int nt = 0; nt < 4; nt++) {
            tm0 = fmaxf(tm0, fmaxf(s[nt][0], s[nt][1]));
            tm1 = fmaxf(tm1, fmaxf(s[nt][2], s[nt][3]));
        }
        tm0 = fmaxf(tm0, __shfl_xor_sync(0xffffffffu, tm0, 1));
        tm0 = fmaxf(tm0, __shfl_xor_sync(0xffffffffu, tm0, 2));
        tm1 = fmaxf(tm1, __shfl_xor_sync(0xffffffffu, tm1, 1));
        tm1 = fmaxf(tm1, __shfl_xor_sync(0xffffffffu, tm1, 2));
        float nm0 = fmaxf(m0, tm0), nm1 = fmaxf(m1, tm1);
        float f0 = __expf(m0 - nm0), f1 = __expf(m1 - nm1);

        float sum0 = 0.f, sum1 = 0.f;
        unsigned ap[2][4];                  // P fragments (packed fp16), in regs
        #pragma unroll
        for (int nt = 0; nt < 4; nt++) {
            float p0 = __expf(s[nt][0] - nm0);
            float p1 = __expf(s[nt][1] - nm0);
            float p2 = __expf(s[nt][2] - nm1);
            float p3 = __expf(s[nt][3] - nm1);
            sum0 += p0 + p1;
            sum1 += p2 + p3;
            int ks = nt >> 1, hi = (nt & 1) * 2;
            ap[ks][hi    ] = packh2(p0, p1);
            ap[ks][hi + 1] = packh2(p2, p3);
        }
        sum0 += __shfl_xor_sync(0xffffffffu, sum0, 1);
        sum0 += __shfl_xor_sync(0xffffffffu, sum0, 2);
        sum1 += __shfl_xor_sync(0xffffffffu, sum1, 1);
        sum1 += __shfl_xor_sync(0xffffffffu, sum1, 2);
        l0 = l0 * f0 + sum0;
        l1 = l1 * f1 + sum1;
        m0 = nm0; m1 = nm1;

        #pragma unroll
        for (int nt = 0; nt < 8; nt++) {
            o[nt][0] *= f0; o[nt][1] *= f0;
            o[nt][2] *= f1; o[nt][3] *= f1;
        }

        // ---- O += P @ V (16 x 64 per warp), P in registers ----
        #pragma unroll
        for (int ks = 0; ks < 2; ks++) {     // key: 2 x k16
            #pragma unroll
            for (int bt = 0; bt < 4; bt++) { // dk: 4 x 16 rows
                unsigned bfr[4];
                ldsm4(bfr, v_u + (unsigned)(((bt * 16 + l15) * VSTR + lhi * 8) * 2 + ks * 32));
                {   unsigned bf[2] = { bfr[0], bfr[2] };
                    mma_f16(o[bt*2    ], ap[ks], bf); }
                {   unsigned bf[2] = { bfr[1], bfr[3] };
                    mma_f16(o[bt*2 + 1], ap[ks], bf); }
            }
        }
    }

    // ---- normalize + write fp16 ----
    float i0 = 1.f / l0, i1 = 1.f / l1;
    size_t r0 = (size_t)(b * SS + qt * AQT + wr + g) * DD + h * 64;
    size_t r1 = r0 + (size_t)8 * DD;
    #pragma unroll
    for (int nt = 0; nt < 8; nt++) {
        int ncol = nt * 8 + 2 * cc;
        *(__half2*)(O + r0 + ncol) = __floats2half2_rn(o[nt][0] * i0, o[nt][1] * i0);
        *(__half2*)(O + r1 + ncol) = __floats2half2_rn(o[nt][2] * i1, o[nt][3] * i1);
    }
}

// ---------------- host orchestration ----------------
extern "C" void kernel_launch(void* const* d_in, const int* in_sizes, int n_in,
                              void* d_out, int out_size)
{
    const float* embed = (const float*)d_in[0];
    const int*   npm   = (const int*)  d_in[1];
    const float* pe    = (const float*)d_in[2];
    const float* Wq    = (const float*)d_in[3];
    const float* bq    = (const float*)d_in[4];
    const float* Wk    = (const float*)d_in[5];
    const float* bk    = (const float*)d_in[6];
    const float* Wv    = (const float*)d_in[7];
    const float* bv    = (const float*)d_in[8];
    const float* Wo    = (const float*)d_in[9];
    const float* bo    = (const float*)d_in[10];
    const float* ln1g  = (const float*)d_in[11];
    const float* ln1b  = (const float*)d_in[12];
    const float* W1    = (const float*)d_in[13];
    const float* b1    = (const float*)d_in[14];
    const float* W2    = (const float*)d_in[15];
    const float* b2    = (const float*)d_in[16];
    const float* ln2g  = (const float*)d_in[17];
    const float* ln2b  = (const float*)d_in[18];
    const float* lnfg  = (const float*)d_in[19];
    const float* lnfb  = (const float*)d_in[20];

    float *x, *hh, *x1;
    __half *htf, *qb, *kb, *vb, *ob, *ffb;
    __half *wqc, *wkc, *wvc, *woc, *w1c, *w2c;
    cudaGetSymbolAddress((void**)&x,   g_x);
    cudaGetSymbolAddress((void**)&hh,  g_h);
    cudaGetSymbolAddress((void**)&htf, g_htf);
    cudaGetSymbolAddress((void**)&x1,  g_x1);
    cudaGetSymbolAddress((void**)&qb,  g_q);
    cudaGetSymbolAddress((void**)&kb,  g_k);
    cudaGetSymbolAddress((void**)&vb,  g_v);
    cudaGetSymbolAddress((void**)&ob,  g_o);
    cudaGetSymbolAddress((void**)&ffb, g_ff);
    cudaGetSymbolAddress((void**)&wqc, g_wqc);
    cudaGetSymbolAddress((void**)&wkc, g_wkc);
    cudaGetSymbolAddress((void**)&wvc, g_wvc);
    cudaGetSymbolAddress((void**)&woc, g_woc);
    cudaGetSymbolAddress((void**)&w1c, g_w1c);
    cudaGetSymbolAddress((void**)&w2c, g_w2c);

    cudaFuncSetAttribute(mma_gemm_kernel,
                         cudaFuncAttributeMaxDynamicSharedMemorySize,
                         GEMM_SMEM_BYTES);

    // weight prep: transpose + fp16 convert
    {
        dim3 blk(32, 8);
        h16conv_t_kernel<<<dim3(DD/32, DD/32, LYR), blk>>>(Wq, wqc, DD, DD);
        h16conv_t_kernel<<<dim3(DD/32, DD/32, LYR), blk>>>(Wk, wkc, DD, DD);
        h16conv_t_kernel<<<dim3(DD/32, DD/32, LYR), blk>>>(Wv, wvc, DD, DD);
        h16conv_t_kernel<<<dim3(DD/32, DD/32, LYR), blk>>>(Wo, woc, DD, DD);
        h16conv_t_kernel<<<dim3(FF/32, DD/32, LYR), blk>>>(W1, w1c, DD, FF);
        h16conv_t_kernel<<<dim3(DD/32, FF/32, LYR), blk>>>(W2, w2c, FF, DD);
    }

    {
        int tot4 = MM * DD / 4;
        add_pe_kernel<<<(tot4 + 255) / 256, 256>>>(embed, pe, x);
    }

    dim3 gD(DD / BN, MM / BM);       // (8, 32)
    dim3 gF(FF / BN, MM / BM);       // (32, 32)
    dim3 gAttn(SS / AQT, HH, BB);    // (16, 16, 4)

    for (int l = 0; l < LYR; l++) {
        const __half* wq = wqc + (size_t)l * DD * DD;
        const __half* wk = wkc + (size_t)l * DD * DD;
        const __half* wv = wvc + (size_t)l * DD * DD;
        const __half* wo = woc + (size_t)l * DD * DD;
        const __half* w1 = w1c + (size_t)l * DD * FF;
        const __half* w2 = w2c + (size_t)l * FF * DD;
        const float* lbq = bq + (size_t)l * DD;
        const float* lbk = bk + (size_t)l * DD;
        const float* lbv = bv + (size_t)l * DD;
        const float* lbo = bo + (size_t)l * DD;
        const float* lb1 = b1 + (size_t)l * FF;
        const float* lb2 = b2 + (size_t)l * DD;

        ln_kernel<<<MM, 256>>>(x, ln1g + (size_t)l * DD, ln1b + (size_t)l * DD, hh, htf);
        mma_gemm_kernel<<<gD, 256, GEMM_SMEM_BYTES>>>(htf, wq, lbq, nullptr, nullptr, qb, MM, DD, DD, 0);
        mma_gemm_kernel<<<gD, 256, GEMM_SMEM_BYTES>>>(htf, wk, lbk, nullptr, nullptr, kb, MM, DD, DD, 0);
        mma_gemm_kernel<<<gD, 256, GEMM_SMEM_BYTES>>>(htf, wv, lbv, nullptr, nullptr, vb, MM, DD, DD, 0);
        attn_f16_kernel<<<gAttn, 128>>>(qb, kb, vb, npm, ob);
        mma_gemm_kernel<<<gD, 256, GEMM_SMEM_BYTES>>>(ob, wo, lbo, hh, npm, x1, MM, DD, DD, 2);
        ln_kernel<<<MM, 256>>>(x1, ln2g + (size_t)l * DD, ln2b + (size_t)l * DD, hh, htf);
        mma_gemm_kernel<<<gF, 256, GEMM_SMEM_BYTES>>>(htf, w1, lb1, nullptr, nullptr, ffb, MM, FF, DD, 1);
        mma_gemm_kernel<<<gD, 256, GEMM_SMEM_BYTES>>>(ffb, w2, lb2, hh, npm, x, MM, DD, FF, 2);
    }

    ln_kernel<<<MM, 256>>>(x, lnfg, lnfb, (float*)d_out, nullptr);
}

// round 12
// speedup vs baseline: 7.8554x; 1.1368x over previous
#include <cuda_runtime.h>
#include <cuda_fp16.h>
#include <math.h>
#include <stdint.h>

// Problem constants
#define LYR 6
#define BB  4
#define SS  1024
#define DD  1024
#define HH  16
#define DKK 64
#define FF  4096
#define MM  (BB*SS)          // 4096 rows
#define ATT_SCALE 0.125f     // 1/sqrt(64)
#define LN_EPS 1e-6f

// ---------------- scratch buffers (device globals; no allocation) -------------
__device__ float  g_x [MM*DD];
__device__ float  g_h [MM*DD];
__device__ __half g_htf[MM*DD];     // fp16 LN output (GEMM A operand)
__device__ float  g_x1[MM*DD];
__device__ __half g_qkv[MM*3*DD];   // fused QKV output
__device__ __half g_o [MM*DD];      // attn out, fp16
__device__ __half g_ff[MM*FF];      // relu out, fp16
// pre-converted + TRANSPOSED weights: Bt[n][k] = fp16(W[k][n])
__device__ __half g_wqkvc[LYR*3*DD*DD];
__device__ __half g_woc[LYR*DD*DD];
__device__ __half g_w1c[LYR*DD*FF];
__device__ __half g_w2c[LYR*FF*DD];
__device__ float  g_bqkv[LYR*3*DD];

// ---------------- helpers ----------------
__device__ __forceinline__ void mma_f16(float c[4], const unsigned a[4], const unsigned b[2]) {
    asm volatile("mma.sync.aligned.m16n8k16.row.col.f32.f16.f16.f32 "
        "{%0,%1,%2,%3}, {%4,%5,%6,%7}, {%8,%9}, {%0,%1,%2,%3};"
        : "+f"(c[0]), "+f"(c[1]), "+f"(c[2]), "+f"(c[3])
        : "r"(a[0]), "r"(a[1]), "r"(a[2]), "r"(a[3]), "r"(b[0]), "r"(b[1]));
}

__device__ __forceinline__ void ldsm4(unsigned r[4], unsigned addr) {
    asm volatile("ldmatrix.sync.aligned.m8n8.x4.shared.b16 {%0,%1,%2,%3}, [%4];"
        : "=r"(r[0]), "=r"(r[1]), "=r"(r[2]), "=r"(r[3]) : "r"(addr));
}

__device__ __forceinline__ void ldsm4t(unsigned r[4], unsigned addr) {
    asm volatile("ldmatrix.sync.aligned.m8n8.x4.trans.shared.b16 {%0,%1,%2,%3}, [%4];"
        : "=r"(r[0]), "=r"(r[1]), "=r"(r[2]), "=r"(r[3]) : "r"(addr));
}

__device__ __forceinline__ void cp16(unsigned dst, const void* src) {
    asm volatile("cp.async.cg.shared.global [%0], [%1], 16;" :: "r"(dst), "l"(src));
}
__device__ __forceinline__ void cp4(unsigned dst, const void* src) {
    asm volatile("cp.async.ca.shared.global [%0], [%1], 4;" :: "r"(dst), "l"(src));
}
#define CP_COMMIT() asm volatile("cp.async.commit_group;" ::: "memory")
#define CP_WAIT2()  asm volatile("cp.async.wait_group 2;" ::: "memory")
#define CP_WAIT1()  asm volatile("cp.async.wait_group 1;" ::: "memory")

__device__ __forceinline__ unsigned packh2(float a, float b) {
    __half2 h = __floats2half2_rn(a, b);
    return *(unsigned*)&h;
}

// ---------------- weight prep: dst[n][k] = fp16(src[k][n]) -------------------
__global__ void h16conv_t_kernel(const float* __restrict__ src,
                                 __half* __restrict__ dst, int K, int N,
                                 size_t dstLayerStride, int rowOff)
{
    __shared__ float t[32][33];
    int l = blockIdx.z;
    const float* s = src + (size_t)l * K * N;
    __half* d = dst + (size_t)l * dstLayerStride + (size_t)rowOff * K;
    int n0 = blockIdx.x * 32, k0 = blockIdx.y * 32;
    int tx = threadIdx.x, ty = threadIdx.y;   // 32 x 8
    #pragma unroll
    for (int i = 0; i < 32; i += 8)
        t[ty + i][tx] = s[(size_t)(k0 + ty + i) * N + n0 + tx];
    __syncthreads();
    #pragma unroll
    for (int i = 0; i < 32; i += 8)
        d[(size_t)(n0 + ty + i) * K + k0 + tx] = __float2half_rn(t[tx][ty + i]);
}

// ---------------- bias concat for fused QKV ----------------------------------
__global__ void bias_cat_kernel(const float* __restrict__ bq,
                                const float* __restrict__ bk,
                                const float* __restrict__ bv,
                                float* __restrict__ out)
{
    int i = blockIdx.x * blockDim.x + threadIdx.x;
    if (i >= LYR * 3 * DD) return;
    int l = i / (3 * DD), j = i % (3 * DD);
    float v = (j < DD) ? bq[l * DD + j]
            : (j < 2 * DD) ? bk[l * DD + j - DD]
            : bv[l * DD + j - 2 * DD];
    out[i] = v;
}

// ---------------- PE add ----------------
__global__ void add_pe_kernel(const float* __restrict__ embed,
                              const float* __restrict__ pe,
                              float* __restrict__ x)
{
    int i = blockIdx.x * blockDim.x + threadIdx.x;
    const int TOT4 = MM * DD / 4;
    if (i >= TOT4) return;
    int pe4 = i % (SS * DD / 4);
    float4 e = ((const float4*)embed)[i];
    float4 p = ((const float4*)pe)[pe4];
    float4 r; r.x = e.x + p.x; r.y = e.y + p.y; r.z = e.z + p.z; r.w = e.w + p.w;
    ((float4*)x)[i] = r;
}

// ---------------- LayerNorm (dual output: fp32 + fp16) -----------------------
__global__ void ln_kernel(const float* __restrict__ x,
                          const float* __restrict__ g,
                          const float* __restrict__ beta,
                          float* __restrict__ y,
                          __half* __restrict__ ytf)
{
    __shared__ float shm[32];
    __shared__ float s_mu, s_rstd;
    int row = blockIdx.x;
    int t   = threadIdx.x;
    const float4* xr = (const float4*)(x + (size_t)row * DD);
    float4 v = xr[t];
    float s = v.x + v.y + v.z + v.w;
    #pragma unroll
    for (int o = 16; o; o >>= 1) s += __shfl_xor_sync(0xffffffffu, s, o);
    if ((t & 31) == 0) shm[t >> 5] = s;
    __syncthreads();
    if (t < 32) {
        float tot = (t < 8) ? shm[t] : 0.f;
        #pragma unroll
        for (int o = 4; o; o >>= 1) tot += __shfl_xor_sync(0xffffffffu, tot, o);
        if (t == 0) s_mu = tot * (1.0f / DD);
    }
    __syncthreads();
    float mu = s_mu;
    float d0 = v.x - mu, d1 = v.y - mu, d2 = v.z - mu, d3 = v.w - mu;
    float s2 = d0*d0 + d1*d1 + d2*d2 + d3*d3;
    #pragma unroll
    for (int o = 16; o; o >>= 1) s2 += __shfl_xor_sync(0xffffffffu, s2, o);
    if ((t & 31) == 0) shm[t >> 5] = s2;
    __syncthreads();
    if (t < 32) {
        float tot = (t < 8) ? shm[t] : 0.f;
        #pragma unroll
        for (int o = 4; o; o >>= 1) tot += __shfl_xor_sync(0xffffffffu, tot, o);
        if (t == 0) s_rstd = rsqrtf(tot * (1.0f / DD) + LN_EPS);
    }
    __syncthreads();
    float rstd = s_rstd;
    float4 gg = ((const float4*)g)[t];
    float4 bb = ((const float4*)beta)[t];
    float4 out;
    out.x = d0 * rstd * gg.x + bb.x;
    out.y = d1 * rstd * gg.y + bb.y;
    out.z = d2 * rstd * gg.z + bb.z;
    out.w = d3 * rstd * gg.w + bb.w;
    ((float4*)(y + (size_t)row * DD))[t] = out;
    if (ytf) {
        __half2* yh = (__half2*)(ytf + (size_t)row * DD);
        yh[2*t    ] = __floats2half2_rn(out.x, out.y);
        yh[2*t + 1] = __floats2half2_rn(out.z, out.w);
    }
}

// ---------------- FP16 GEMM (mma.sync m16n8k16), 4-stage cp.async ------------
#define BM 128
#define BN 128
#define BKH 32
#define STAGES 4
#define STRH 40
#define T_STG (BM*STRH)
#define GEMM_SMEM_BYTES (STAGES * 2 * T_STG * 2)   // 81920

__global__ __launch_bounds__(256, 2)
void mma_gemm_kernel(const __half* __restrict__ A, const __half* __restrict__ Bt,
                     const float* __restrict__ bias, const float* __restrict__ res,
                     const int* __restrict__ mask, void* __restrict__ Cv,
                     int M, int N, int K, int epi)
{
    extern __shared__ __half smemh[];
    __half* Asm = smemh;
    __half* Bsm = smemh + STAGES * T_STG;
    const unsigned a_u = (unsigned)__cvta_generic_to_shared(Asm);
    const unsigned b_u = (unsigned)__cvta_generic_to_shared(Bsm);

    const int tid  = threadIdx.x;
    const int lane = tid & 31;
    const int wrp  = tid >> 5;
    const int wm   = wrp >> 2;
    const int wn   = wrp & 3;
    const int l15  = lane & 15;
    const int lhi  = lane >> 4;
    const int g    = lane >> 2;
    const int cc   = lane & 3;

    const int brow = blockIdx.y * BM;
    const int bcol = blockIdx.x * BN;

    const int s_r = tid >> 1, s_c = (tid & 1) * 16;
    const __half* Ag = A  + (size_t)(brow + s_r) * K + s_c;
    const __half* Bg = Bt + (size_t)(bcol + s_r) * K + s_c;

    const int NK = K / BKH;

    auto load_stage = [&](int s, int kt) {
        const __half* ag = Ag + kt * BKH;
        const __half* bg = Bg + kt * BKH;
        unsigned d = (unsigned)((s * T_STG + s_r * STRH + s_c) * 2);
        cp16(a_u + d, ag); cp16(a_u + d + 16, ag + 8);
        cp16(b_u + d, bg); cp16(b_u + d + 16, bg + 8);
    };

    float acc[4][4][4];
    #pragma unroll
    for (int i = 0; i < 4; i++)
        #pragma unroll
        for (int j = 0; j < 4; j++) {
            acc[i][j][0] = 0.f; acc[i][j][1] = 0.f;
            acc[i][j][2] = 0.f; acc[i][j][3] = 0.f;
        }

    load_stage(0, 0); CP_COMMIT();
    load_stage(1, 1); CP_COMMIT();
    load_stage(2, 2); CP_COMMIT();

    const unsigned a_frag_off = (unsigned)(((wm * 64 + l15) * STRH + lhi * 8) * 2);
    const unsigned b_frag_off = (unsigned)(((wn * 32 + l15) * STRH + lhi * 8) * 2);

    int cur = 0;
    for (int kt = 0; kt < NK; kt++) {
        CP_WAIT2();
        __syncthreads();

        if (kt + 3 < NK) load_stage((kt + 3) & 3, kt + 3);
        CP_COMMIT();

        const unsigned abase = a_u + (unsigned)(cur * T_STG * 2) + a_frag_off;
        const unsigned bbase = b_u + (unsigned)(cur * T_STG * 2) + b_frag_off;

        #pragma unroll
        for (int ks = 0; ks < 2; ks++) {
            unsigned a[4][4], b[2][4];
            #pragma unroll
            for (int mt = 0; mt < 4; mt++)
                ldsm4(a[mt], abase + (unsigned)(mt * 16 * STRH * 2 + ks * 32));
            #pragma unroll
            for (int bt = 0; bt < 2; bt++)
                ldsm4(b[bt], bbase + (unsigned)(bt * 16 * STRH * 2 + ks * 32));

            #pragma unroll
            for (int mt = 0; mt < 4; mt++) {
                {   unsigned bf[2] = { b[0][0], b[0][2] };
                    mma_f16(acc[mt][0], a[mt], bf); }
                {   unsigned bf[2] = { b[0][1], b[0][3] };
                    mma_f16(acc[mt][1], a[mt], bf); }
                {   unsigned bf[2] = { b[1][0], b[1][2] };
                    mma_f16(acc[mt][2], a[mt], bf); }
                {   unsigned bf[2] = { b[1][1], b[1][3] };
                    mma_f16(acc[mt][3], a[mt], bf); }
            }
        }
        cur = (cur + 1) & 3;
    }

    // ---- epilogue ----
    #pragma unroll
    for (int mt = 0; mt < 4; mt++) {
        int r0 = brow + wm * 64 + mt * 16 + g;
        int r1 = r0 + 8;
        float mk0 = 1.f, mk1 = 1.f;
        if (epi == 2) {
            mk0 = mask[r0] ? 1.f : 0.f;
            mk1 = mask[r1] ? 1.f : 0.f;
        }
        #pragma unroll
        for (int nt = 0; nt < 4; nt++) {
            int ncol = bcol + wn * 32 + nt * 8 + cc * 2;
            float2 bv = *(const float2*)(bias + ncol);
            float2 o0, o1;
            o0.x = acc[mt][nt][0] + bv.x; o0.y = acc[mt][nt][1] + bv.y;
            o1.x = acc[mt][nt][2] + bv.x; o1.y = acc[mt][nt][3] + bv.y;
            if (epi == 0) {
                __half* Ch = (__half*)Cv;
                *(__half2*)(Ch + (size_t)r0 * N + ncol) = __floats2half2_rn(o0.x, o0.y);
                *(__half2*)(Ch + (size_t)r1 * N + ncol) = __floats2half2_rn(o1.x, o1.y);
            } else if (epi == 1) {
                __half* Ch = (__half*)Cv;
                *(__half2*)(Ch + (size_t)r0 * N + ncol) =
                    __floats2half2_rn(fmaxf(o0.x, 0.f), fmaxf(o0.y, 0.f));
                *(__half2*)(Ch + (size_t)r1 * N + ncol) =
                    __floats2half2_rn(fmaxf(o1.x, 0.f), fmaxf(o1.y, 0.f));
            } else {
                float* Cf = (float*)Cv;
                float2 rv0 = *(const float2*)(res + (size_t)r0 * N + ncol);
                float2 rv1 = *(const float2*)(res + (size_t)r1 * N + ncol);
                o0.x = (o0.x + rv0.x) * mk0; o0.y = (o0.y + rv0.y) * mk0;
                o1.x = (o1.x + rv1.x) * mk1; o1.y = (o1.y + rv1.y) * mk1;
                *(float2*)(Cf + (size_t)r0 * N + ncol) = o0;
                *(float2*)(Cf + (size_t)r1 * N + ncol) = o1;
            }
        }
    }
}

// ---------------- FP16 flash attention (mma m16n8k16, ldsm.trans V) ----------
// grid (S/64, H, B), 128 threads = 4 warps. KT=32, double-buffered cp.async.
#define AQT 64
#define AKT 32
#define KSTR 72   // row stride (halfs) for Q/K/V smem tiles

__global__ __launch_bounds__(128)
void attn_f16_kernel(const __half* __restrict__ QKV, const int* __restrict__ npm,
                     __half* __restrict__ O)
{
    __shared__ __half Qs[AQT][KSTR];
    __shared__ __half Ks[2][AKT][KSTR];
    __shared__ __half Vs[2][AKT][KSTR];
    __shared__ int kmsi[2][AKT];

    const unsigned q_u = (unsigned)__cvta_generic_to_shared(Qs);
    const unsigned k_u = (unsigned)__cvta_generic_to_shared(Ks);
    const unsigned v_u = (unsigned)__cvta_generic_to_shared(Vs);
    const unsigned m_u = (unsigned)__cvta_generic_to_shared(kmsi);

    const int b = blockIdx.z, h = blockIdx.y, qt = blockIdx.x;
    const int tid  = threadIdx.x;
    const int lane = tid & 31;
    const int wq   = tid >> 5;
    const int g    = lane >> 2;
    const int cc   = lane & 3;
    const int l15  = lane & 15;
    const int lhi  = lane >> 4;
    const int wr   = wq * 16;

    const int RS = 3 * DD;
    const __half* Qbase = QKV + (size_t)(b * SS + qt * AQT) * RS + h * 64;
    const __half* Kb0   = QKV + (size_t)(b * SS) * RS + DD + h * 64;
    const __half* Vb0   = QKV + (size_t)(b * SS) * RS + 2 * DD + h * 64;

    // Q tile via cp.async
    #pragma unroll
    for (int i = tid; i < AQT * 8; i += 128) {
        int r = i >> 3, c = (i & 7) * 8;
        cp16(q_u + (unsigned)((r * KSTR + c) * 2), Qbase + (size_t)r * RS + c);
    }
    CP_COMMIT();

    auto load_kv = [&](int s, int kt) {
        const __half* kp = Kb0 + (size_t)(kt * AKT) * RS;
        const __half* vp = Vb0 + (size_t)(kt * AKT) * RS;
        #pragma unroll
        for (int i = tid; i < AKT * 8; i += 128) {
            int r = i >> 3, c = (i & 7) * 8;
            cp16(k_u + (unsigned)(((s * AKT + r) * KSTR + c) * 2), kp + (size_t)r * RS + c);
            cp16(v_u + (unsigned)(((s * AKT + r) * KSTR + c) * 2), vp + (size_t)r * RS + c);
        }
        if (tid < AKT) cp4(m_u + (unsigned)((s * AKT + tid) * 4),
                           npm + b * SS + kt * AKT + tid);
    };

    load_kv(0, 0); CP_COMMIT();

    float m0 = -1e30f, m1 = -1e30f, l0 = 0.f, l1 = 0.f;
    float o[8][4];
    #pragma unroll
    for (int nt = 0; nt < 8; nt++) {
        o[nt][0] = 0.f; o[nt][1] = 0.f; o[nt][2] = 0.f; o[nt][3] = 0.f;
    }

    const unsigned qf_off = (unsigned)(((wr + l15) * KSTR + lhi * 8) * 2);
    const int NKT = SS / AKT;

    for (int kt = 0; kt < NKT; kt++) {
        int st = kt & 1;
        if (kt + 1 < NKT) load_kv(st ^ 1, kt + 1);
        CP_COMMIT();
        CP_WAIT1();
        __syncthreads();

        // ---- S = Q @ K^T ----
        float s[4][4];
        #pragma unroll
        for (int nt = 0; nt < 4; nt++) {
            s[nt][0] = 0.f; s[nt][1] = 0.f; s[nt][2] = 0.f; s[nt][3] = 0.f;
        }
        #pragma unroll
        for (int ks = 0; ks < 4; ks++) {
            unsigned a[4];
            ldsm4(a, q_u + qf_off + (unsigned)(ks * 32));
            #pragma unroll
            for (int bt = 0; bt < 2; bt++) {
                unsigned bfr[4];
                ldsm4(bfr, k_u + (unsigned)((((st * AKT + bt * 16 + l15) * KSTR + lhi * 8) * 2 + ks * 32)));
                {   unsigned bf[2] = { bfr[0], bfr[2] };
                    mma_f16(s[bt*2    ], a, bf); }
                {   unsigned bf[2] = { bfr[1], bfr[3] };
                    mma_f16(s[bt*2 + 1], a, bf); }
            }
        }

        // ---- mask + scale ----
        #pragma unroll
        for (int nt = 0; nt < 4; nt++) {
            int k0i = kmsi[st][nt*8 + 2*cc];
            int k1i = kmsi[st][nt*8 + 2*cc + 1];
            s[nt][0] = k0i ? s[nt][0] * ATT_SCALE : -1e9f;
            s[nt][1] = k1i ? s[nt][1] * ATT_SCALE : -1e9f;
            s[nt][2] = k0i ? s[nt][2] * ATT_SCALE : -1e9f;
            s[nt][3] = k1i ? s[nt][3] * ATT_SCALE : -1e9f;
        }

        // ---- online softmax ----
        float tm0 = s[0][0], tm1 = s[0][2];
        #pragma unroll
        for (int nt = 0; nt < 4; nt++) {
            tm0 = fmaxf(tm0, fmaxf(s[nt][0], s[nt][1]));
            tm1 = fmaxf(tm1, fmaxf(s[nt][2], s[nt][3]));
        }
        tm0 = fmaxf(tm0, __shfl_xor_sync(0xffffffffu, tm0, 1));
        tm0 = fmaxf(tm0, __shfl_xor_sync(0xffffffffu, tm0, 2));
        tm1 = fmaxf(tm1, __shfl_xor_sync(0xffffffffu, tm1, 1));
        tm1 = fmaxf(tm1, __shfl_xor_sync(0xffffffffu, tm1, 2));
        float nm0 = fmaxf(m0, tm0), nm1 = fmaxf(m1, tm1);
        float f0 = __expf(m0 - nm0), f1 = __expf(m1 - nm1);

        float sum0 = 0.f, sum1 = 0.f;
        unsigned ap[2][4];
        #pragma unroll
        for (int nt = 0; nt < 4; nt++) {
            float p0 = __expf(s[nt][0] - nm0);
            float p1 = __expf(s[nt][1] - nm0);
            float p2 = __expf(s[nt][2] - nm1);
            float p3 = __expf(s[nt][3] - nm1);
            sum0 += p0 + p1;
            sum1 += p2 + p3;
            int ks = nt >> 1, hi = (nt & 1) * 2;
            ap[ks][hi    ] = packh2(p0, p1);
            ap[ks][hi + 1] = packh2(p2, p3);
        }
        sum0 += __shfl_xor_sync(0xffffffffu, sum0, 1);
        sum0 += __shfl_xor_sync(0xffffffffu, sum0, 2);
        sum1 += __shfl_xor_sync(0xffffffffu, sum1, 1);
        sum1 += __shfl_xor_sync(0xffffffffu, sum1, 2);
        l0 = l0 * f0 + sum0;
        l1 = l1 * f1 + sum1;
        m0 = nm0; m1 = nm1;

        #pragma unroll
        for (int nt = 0; nt < 8; nt++) {
            o[nt][0] *= f0; o[nt][1] *= f0;
            o[nt][2] *= f1; o[nt][3] *= f1;
        }

        // ---- O += P @ V via ldmatrix.trans on row-major V ----
        #pragma unroll
        for (int ks = 0; ks < 2; ks++) {
            #pragma unroll
            for (int dkc = 0; dkc < 4; dkc++) {
                unsigned bfr[4];
                ldsm4t(bfr, v_u + (unsigned)((((st * AKT + ks * 16 + l15) * KSTR
                                               + dkc * 16 + lhi * 8) * 2)));
                {   unsigned bf[2] = { bfr[0], bfr[1] };
                    mma_f16(o[dkc*2    ], ap[ks], bf); }
                {   unsigned bf[2] = { bfr[2], bfr[3] };
                    mma_f16(o[dkc*2 + 1], ap[ks], bf); }
            }
        }
        __syncthreads();
    }

    // ---- normalize + write fp16 ----
    float i0 = 1.f / l0, i1 = 1.f / l1;
    size_t r0 = (size_t)(b * SS + qt * AQT + wr + g) * DD + h * 64;
    size_t r1 = r0 + (size_t)8 * DD;
    #pragma unroll
    for (int nt = 0; nt < 8; nt++) {
        int ncol = nt * 8 + 2 * cc;
        *(__half2*)(O + r0 + ncol) = __floats2half2_rn(o[nt][0] * i0, o[nt][1] * i0);
        *(__half2*)(O + r1 + ncol) = __floats2half2_rn(o[nt][2] * i1, o[nt][3] * i1);
    }
}

// ---------------- host orchestration ----------------
extern "C" void kernel_launch(void* const* d_in, const int* in_sizes, int n_in,
                              void* d_out, int out_size)
{
    const float* embed = (const float*)d_in[0];
    const int*   npm   = (const int*)  d_in[1];
    const float* pe    = (const float*)d_in[2];
    const float* Wq    = (const float*)d_in[3];
    const float* bq    = (const float*)d_in[4];
    const float* Wk    = (const float*)d_in[5];
    const float* bk    = (const float*)d_in[6];
    const float* Wv    = (const float*)d_in[7];
    const float* bv    = (const float*)d_in[8];
    const float* Wo    = (const float*)d_in[9];
    const float* bo    = (const float*)d_in[10];
    const float* ln1g  = (const float*)d_in[11];
    const float* ln1b  = (const float*)d_in[12];
    const float* W1    = (const float*)d_in[13];
    const float* b1    = (const float*)d_in[14];
    const float* W2    = (const float*)d_in[15];
    const float* b2    = (const float*)d_in[16];
    const float* ln2g  = (const float*)d_in[17];
    const float* ln2b  = (const float*)d_in[18];
    const float* lnfg  = (const float*)d_in[19];
    const float* lnfb  = (const float*)d_in[20];

    float *x, *hh, *x1, *bqkv;
    __half *htf, *qkv, *ob, *ffb;
    __half *wqkvc, *woc, *w1c, *w2c;
    cudaGetSymbolAddress((void**)&x,    g_x);
    cudaGetSymbolAddress((void**)&hh,   g_h);
    cudaGetSymbolAddress((void**)&htf,  g_htf);
    cudaGetSymbolAddress((void**)&x1,   g_x1);
    cudaGetSymbolAddress((void**)&qkv,  g_qkv);
    cudaGetSymbolAddress((void**)&ob,   g_o);
    cudaGetSymbolAddress((void**)&ffb,  g_ff);
    cudaGetSymbolAddress((void**)&wqkvc, g_wqkvc);
    cudaGetSymbolAddress((void**)&woc,  g_woc);
    cudaGetSymbolAddress((void**)&w1c,  g_w1c);
    cudaGetSymbolAddress((void**)&w2c,  g_w2c);
    cudaGetSymbolAddress((void**)&bqkv, g_bqkv);

    cudaFuncSetAttribute(mma_gemm_kernel,
                         cudaFuncAttributeMaxDynamicSharedMemorySize,
                         GEMM_SMEM_BYTES);

    // weight prep
    {
        dim3 blk(32, 8);
        size_t qkvLS = (size_t)3 * DD * DD;
        h16conv_t_kernel<<<dim3(DD/32, DD/32, LYR), blk>>>(Wq, wqkvc, DD, DD, qkvLS, 0);
        h16conv_t_kernel<<<dim3(DD/32, DD/32, LYR), blk>>>(Wk, wqkvc, DD, DD, qkvLS, DD);
        h16conv_t_kernel<<<dim3(DD/32, DD/32, LYR), blk>>>(Wv, wqkvc, DD, DD, qkvLS, 2*DD);
        h16conv_t_kernel<<<dim3(DD/32, DD/32, LYR), blk>>>(Wo, woc, DD, DD, (size_t)DD*DD, 0);
        h16conv_t_kernel<<<dim3(FF/32, DD/32, LYR), blk>>>(W1, w1c, DD, FF, (size_t)DD*FF, 0);
        h16conv_t_kernel<<<dim3(DD/32, FF/32, LYR), blk>>>(W2, w2c, FF, DD, (size_t)FF*DD, 0);
        int nb = LYR * 3 * DD;
        bias_cat_kernel<<<(nb + 255) / 256, 256>>>(bq, bk, bv, bqkv);
    }

    {
        int tot4 = MM * DD / 4;
        add_pe_kernel<<<(tot4 + 255) / 256, 256>>>(embed, pe, x);
    }

    dim3 gQKV(3 * DD / BN, MM / BM);  // (24, 32)
    dim3 gD(DD / BN, MM / BM);        // (8, 32)
    dim3 gF(FF / BN, MM / BM);        // (32, 32)
    dim3 gAttn(SS / AQT, HH, BB);     // (16, 16, 4)

    for (int l = 0; l < LYR; l++) {
        const __half* wqkv_l = wqkvc + (size_t)l * 3 * DD * DD;
        const __half* wo = woc + (size_t)l * DD * DD;
        const __half* w1 = w1c + (size_t)l * DD * FF;
        const __half* w2 = w2c + (size_t)l * FF * DD;
        const float* lbqkv = bqkv + (size_t)l * 3 * DD;
        const float* lbo = bo + (size_t)l * DD;
        const float* lb1 = b1 + (size_t)l * FF;
        const float* lb2 = b2 + (size_t)l * DD;

        ln_kernel<<<MM, 256>>>(x, ln1g + (size_t)l * DD, ln1b + (size_t)l * DD, hh, htf);
        mma_gemm_kernel<<<gQKV, 256, GEMM_SMEM_BYTES>>>(htf, wqkv_l, lbqkv, nullptr, nullptr, qkv, MM, 3*DD, DD, 0);
        attn_f16_kernel<<<gAttn, 128>>>(qkv, npm, ob);
        mma_gemm_kernel<<<gD, 256, GEMM_SMEM_BYTES>>>(ob, wo, lbo, hh, npm, x1, MM, DD, DD, 2);
        ln_kernel<<<MM, 256>>>(x1, ln2g + (size_t)l * DD, ln2b + (size_t)l * DD, hh, htf);
        mma_gemm_kernel<<<gF, 256, GEMM_SMEM_BYTES>>>(htf, w1, lb1, nullptr, nullptr, ffb, MM, FF, DD, 1);
        mma_gemm_kernel<<<gD, 256, GEMM_SMEM_BYTES>>>(ffb, w2, lb2, hh, npm, x, MM, DD, FF, 2);
    }

    ln_kernel<<<MM, 256>>>(x, lnfg, lnfb, (float*)d_out, nullptr);
}